// round 1
// baseline (speedup 1.0000x reference)
#include <cuda_runtime.h>
#include <cuda_bf16.h>
#include <cstdint>

// Problem constants
#define B_  2
#define T_  2048
#define D_  2048
#define H_  16
#define G_  4
#define KH  128           // head dim
#define NREP (H_/G_)      // 4
#define EPS 1e-6f
static const float SCALE = 0.088388347648318447f; // 128^-0.5

// ---------------- scratch (device globals: no allocation allowed) ------------
__device__ float g_qraw[B_*T_*H_*2*KH];  // [B,T,H,2K]  (q in-place normed+roped in first K; gate in second K)
__device__ float g_kraw[B_*T_*G_*KH];    // [B,T,G,K]   (in-place normed+roped)
__device__ float g_vraw[B_*T_*G_*KH];    // [B,T,G,K]
__device__ float g_attn[B_*T_*H_*KH];    // [B,T,H,K]   attention out, gated in place

// ---------------- generic fp32 tiled GEMM: C[M,N] = A[M,Kd] @ B[Kd,N] --------
// 64x64 tile, BK=16, 256 threads, 4x4 micro-tile per thread.
__global__ __launch_bounds__(256)
void gemm_kernel(const float* __restrict__ A, const float* __restrict__ Bm,
                 float* __restrict__ C, int M, int N, int Kd) {
    __shared__ float As[16][64];
    __shared__ float Bs[16][64];
    const int tid = threadIdx.x;
    const int tx = tid & 15, ty = tid >> 4;
    const int m0 = blockIdx.y * 64;
    const int n0 = blockIdx.x * 64;

    const int arow = tid >> 2;          // 0..63
    const int acol = (tid & 3) << 2;    // 0,4,8,12
    const int brow = tid >> 4;          // 0..15
    const int bcol = (tid & 15) << 2;   // 0..60

    float acc[4][4] = {};

    for (int k0 = 0; k0 < Kd; k0 += 16) {
        float4 av = *(const float4*)&A[(size_t)(m0 + arow) * Kd + k0 + acol];
        As[acol + 0][arow] = av.x;
        As[acol + 1][arow] = av.y;
        As[acol + 2][arow] = av.z;
        As[acol + 3][arow] = av.w;
        *(float4*)&Bs[brow][bcol] =
            *(const float4*)&Bm[(size_t)(k0 + brow) * N + n0 + bcol];
        __syncthreads();
        #pragma unroll
        for (int kk = 0; kk < 16; kk++) {
            float4 a = *(const float4*)&As[kk][ty << 2];
            float4 b = *(const float4*)&Bs[kk][tx << 2];
            acc[0][0] += a.x*b.x; acc[0][1] += a.x*b.y; acc[0][2] += a.x*b.z; acc[0][3] += a.x*b.w;
            acc[1][0] += a.y*b.x; acc[1][1] += a.y*b.y; acc[1][2] += a.y*b.z; acc[1][3] += a.y*b.w;
            acc[2][0] += a.z*b.x; acc[2][1] += a.z*b.y; acc[2][2] += a.z*b.z; acc[2][3] += a.z*b.w;
            acc[3][0] += a.w*b.x; acc[3][1] += a.w*b.y; acc[3][2] += a.w*b.z; acc[3][3] += a.w*b.w;
        }
        __syncthreads();
    }
    #pragma unroll
    for (int i = 0; i < 4; i++) {
        float4 o;
        o.x = acc[i][0]; o.y = acc[i][1]; o.z = acc[i][2]; o.w = acc[i][3];
        *(float4*)&C[(size_t)(m0 + (ty << 2) + i) * N + n0 + (tx << 2)] = o;
    }
}

// ---------------- fused RMSNorm + RoPE (in place) ----------------------------
// one block per (bt, head) row of length K=128; threads = 128
__global__ __launch_bounds__(128)
void rope_norm_kernel(float* __restrict__ data, const float* __restrict__ cosp,
                      const float* __restrict__ sinp, const float* __restrict__ w,
                      int rowStride) {
    const int idx = blockIdx.x;           // bt*nH + h
    const int nH  = gridDim.x / (B_ * T_);
    const int bt  = idx / nH;
    const size_t base = (size_t)idx * rowStride;
    const int d = threadIdx.x;

    float x = data[base + d];
    float ss = x * x;
    #pragma unroll
    for (int o = 16; o; o >>= 1) ss += __shfl_xor_sync(0xffffffffu, ss, o);
    __shared__ float wsum[4];
    __shared__ float sn[128];
    if ((d & 31) == 0) wsum[d >> 5] = ss;
    __syncthreads();
    float tot = wsum[0] + wsum[1] + wsum[2] + wsum[3];
    float r = rsqrtf(tot * (1.0f / 128.0f) + EPS);
    sn[d] = x * r * w[d];
    __syncthreads();
    float c = cosp[(size_t)bt * KH + d];
    float s = sinp[(size_t)bt * KH + d];
    float out;
    if (d < 64) out = sn[d] * c - sn[d + 64] * s;
    else        out = sn[d] * c + sn[d - 64] * s;
    data[base + d] = out;
}

// ---------------- flash attention (fp32 SIMT, online softmax) ----------------
// block: 128 threads, 64 queries x 32-key tiles. grid: (T/64, B*H)
// smem layout (floats), padded rows to avoid bank conflicts
#define QS_OFF   0
#define KS_OFF   8448            // 64*132
#define VS_OFF   12672           // +32*132
#define SS_OFF   16896           // +32*132
#define RM_OFF   19008           // +64*33
#define RL_OFF   19072
#define AL_OFF   19136
#define QSEG_OFF 19200
#define KSEG_OFF 19264
#define ATTN_SMEM_FLOATS 19296
#define ATTN_SMEM_BYTES  (ATTN_SMEM_FLOATS * 4)

__global__ __launch_bounds__(128)
void attn_kernel(const float* __restrict__ qraw, const float* __restrict__ kraw,
                 const float* __restrict__ vraw, const int* __restrict__ seg,
                 float* __restrict__ attn) {
    extern __shared__ float sm[];
    float* Qs   = sm + QS_OFF;
    float* Ks   = sm + KS_OFF;
    float* Vs   = sm + VS_OFF;
    float* Ss   = sm + SS_OFF;
    float* rowm = sm + RM_OFF;
    float* rowl = sm + RL_OFF;
    float* alph = sm + AL_OFF;
    int*   qseg = (int*)(sm + QSEG_OFF);
    int*   kseg = (int*)(sm + KSEG_OFF);

    const int tid = threadIdx.x;
    const int tx = tid & 7;       // 0..7
    const int ty = tid >> 3;      // 0..15
    const int bh = blockIdx.y;
    const int b = bh / H_, h = bh % H_;
    const int g = h / NREP;
    const int q0 = blockIdx.x * 64;

    // load Q tile (64 x 128)
    for (int i = tid; i < 64 * 32; i += 128) {
        int r = i >> 5, c4 = (i & 31) << 2;
        *(float4*)&Qs[r * 132 + c4] =
            *(const float4*)&qraw[(size_t)((b * T_ + q0 + r) * H_ + h) * (2 * KH) + c4];
    }
    if (tid < 64) {
        rowm[tid] = -1e30f;
        rowl[tid] = 0.0f;
        qseg[tid] = seg[b * T_ + q0 + tid];
    }
    float O[4][16];
    #pragma unroll
    for (int i = 0; i < 4; i++)
        #pragma unroll
        for (int j = 0; j < 16; j++) O[i][j] = 0.0f;
    __syncthreads();

    const int nTiles = (q0 + 64) / 32;   // causal: keys <= q0+63
    for (int t = 0; t < nTiles; t++) {
        const int s0 = t * 32;
        // load K,V tiles (32 x 128 each)
        for (int i = tid; i < 32 * 32; i += 128) {
            int r = i >> 5, c4 = (i & 31) << 2;
            size_t gb = (size_t)((b * T_ + s0 + r) * G_ + g) * KH + c4;
            *(float4*)&Ks[r * 132 + c4] = *(const float4*)&kraw[gb];
            *(float4*)&Vs[r * 132 + c4] = *(const float4*)&vraw[gb];
        }
        if (tid < 32) kseg[tid] = seg[b * T_ + s0 + tid];
        __syncthreads();

        // S = Q K^T  (each thread: 4 m x 4 n)
        float sAcc[4][4] = {};
        #pragma unroll 8
        for (int d = 0; d < 128; d += 4) {
            float4 a0 = *(const float4*)&Qs[(ty     ) * 132 + d];
            float4 a1 = *(const float4*)&Qs[(ty + 16) * 132 + d];
            float4 a2 = *(const float4*)&Qs[(ty + 32) * 132 + d];
            float4 a3 = *(const float4*)&Qs[(ty + 48) * 132 + d];
            #pragma unroll
            for (int j = 0; j < 4; j++) {
                float4 bq = *(const float4*)&Ks[(tx + 8 * j) * 132 + d];
                sAcc[0][j] += a0.x*bq.x + a0.y*bq.y + a0.z*bq.z + a0.w*bq.w;
                sAcc[1][j] += a1.x*bq.x + a1.y*bq.y + a1.z*bq.z + a1.w*bq.w;
                sAcc[2][j] += a2.x*bq.x + a2.y*bq.y + a2.z*bq.z + a2.w*bq.w;
                sAcc[3][j] += a3.x*bq.x + a3.y*bq.y + a3.z*bq.z + a3.w*bq.w;
            }
        }
        // scale + mask -> Ss
        #pragma unroll
        for (int i = 0; i < 4; i++) {
            int m = ty + 16 * i, qp = q0 + m;
            #pragma unroll
            for (int j = 0; j < 4; j++) {
                int n = tx + 8 * j, kp = s0 + n;
                float val = sAcc[i][j] * SCALE;
                if (kp > qp || kseg[n] != qseg[m]) val = -1e30f;
                Ss[m * 33 + n] = val;
            }
        }
        __syncthreads();

        // online softmax row update (one thread per row)
        if (tid < 64) {
            const int r = tid;
            float mo = rowm[r];
            float mx = mo;
            #pragma unroll 8
            for (int n = 0; n < 32; n++) mx = fmaxf(mx, Ss[r * 33 + n]);
            float a = __expf(mo - mx);
            float sum = 0.0f;
            #pragma unroll 8
            for (int n = 0; n < 32; n++) {
                float p = __expf(Ss[r * 33 + n] - mx);
                Ss[r * 33 + n] = p;
                sum += p;
            }
            rowm[r] = mx;
            rowl[r] = rowl[r] * a + sum;
            alph[r] = a;
        }
        __syncthreads();

        // rescale O, then O += P @ V
        #pragma unroll
        for (int i = 0; i < 4; i++) {
            float a = alph[ty + 16 * i];
            #pragma unroll
            for (int j = 0; j < 16; j++) O[i][j] *= a;
        }
        #pragma unroll 4
        for (int n = 0; n < 32; n++) {
            float p0 = Ss[(ty     ) * 33 + n];
            float p1 = Ss[(ty + 16) * 33 + n];
            float p2 = Ss[(ty + 32) * 33 + n];
            float p3 = Ss[(ty + 48) * 33 + n];
            #pragma unroll
            for (int jj = 0; jj < 4; jj++) {
                float4 v = *(const float4*)&Vs[n * 132 + (tx << 2) + 32 * jj];
                O[0][jj*4+0] += p0*v.x; O[0][jj*4+1] += p0*v.y; O[0][jj*4+2] += p0*v.z; O[0][jj*4+3] += p0*v.w;
                O[1][jj*4+0] += p1*v.x; O[1][jj*4+1] += p1*v.y; O[1][jj*4+2] += p1*v.z; O[1][jj*4+3] += p1*v.w;
                O[2][jj*4+0] += p2*v.x; O[2][jj*4+1] += p2*v.y; O[2][jj*4+2] += p2*v.z; O[2][jj*4+3] += p2*v.w;
                O[3][jj*4+0] += p3*v.x; O[3][jj*4+1] += p3*v.y; O[3][jj*4+2] += p3*v.z; O[3][jj*4+3] += p3*v.w;
            }
        }
        __syncthreads();
    }

    // write normalized output [B,T,H,K]
    #pragma unroll
    for (int i = 0; i < 4; i++) {
        int m = ty + 16 * i;
        float inv = 1.0f / rowl[m];
        size_t rb = (size_t)((b * T_ + q0 + m) * H_ + h) * KH;
        #pragma unroll
        for (int jj = 0; jj < 4; jj++) {
            float4 o;
            o.x = O[i][jj*4+0] * inv; o.y = O[i][jj*4+1] * inv;
            o.z = O[i][jj*4+2] * inv; o.w = O[i][jj*4+3] * inv;
            *(float4*)&attn[rb + (tx << 2) + 32 * jj] = o;
        }
    }
}

// ---------------- sigmoid gate (in place on attn) ----------------------------
__global__ __launch_bounds__(256)
void gate_kernel(const float* __restrict__ qraw, float* __restrict__ attn) {
    size_t i = (size_t)blockIdx.x * 256 + threadIdx.x;   // over B*T*H*K
    int d = (int)(i & 127);
    size_t rest = i >> 7;
    int h = (int)(rest & 15);
    size_t bt = rest >> 4;
    float gv = qraw[(bt * H_ + h) * (2 * KH) + KH + d];
    attn[i] *= 1.0f / (1.0f + __expf(-gv));
}

// ---------------- launch -----------------------------------------------------
extern "C" void kernel_launch(void* const* d_in, const int* in_sizes, int n_in,
                              void* d_out, int out_size) {
    const float* hidden = (const float*)d_in[0];
    const float* cosp   = (const float*)d_in[1];
    const float* sinp   = (const float*)d_in[2];
    const int*   seg    = (const int*)d_in[3];
    // d_in[4] = position_ids (arange; causal handled by index math)
    const float* Wq = (const float*)d_in[5];
    const float* Wk = (const float*)d_in[6];
    const float* Wv = (const float*)d_in[7];
    const float* Wo = (const float*)d_in[8];
    const float* qw = (const float*)d_in[9];
    const float* kw = (const float*)d_in[10];
    float* out = (float*)d_out;

    float *qraw, *kraw, *vraw, *attn;
    cudaGetSymbolAddress((void**)&qraw, g_qraw);
    cudaGetSymbolAddress((void**)&kraw, g_kraw);
    cudaGetSymbolAddress((void**)&vraw, g_vraw);
    cudaGetSymbolAddress((void**)&attn, g_attn);

    cudaFuncSetAttribute(attn_kernel, cudaFuncAttributeMaxDynamicSharedMemorySize,
                         ATTN_SMEM_BYTES);

    const int M = B_ * T_;   // 4096
    // projections
    gemm_kernel<<<dim3((H_*2*KH)/64, M/64), 256>>>(hidden, Wq, qraw, M, H_*2*KH, D_);
    gemm_kernel<<<dim3((G_*KH)/64,  M/64), 256>>>(hidden, Wk, kraw, M, G_*KH,  D_);
    gemm_kernel<<<dim3((G_*KH)/64,  M/64), 256>>>(hidden, Wv, vraw, M, G_*KH,  D_);
    // rmsnorm + rope
    rope_norm_kernel<<<B_*T_*H_, 128>>>(qraw, cosp, sinp, qw, 2*KH);
    rope_norm_kernel<<<B_*T_*G_, 128>>>(kraw, cosp, sinp, kw, KH);
    // attention
    attn_kernel<<<dim3(T_/64, B_*H_), 128, ATTN_SMEM_BYTES>>>(qraw, kraw, vraw, seg, attn);
    // gate
    gate_kernel<<<(B_*T_*H_*KH)/256, 256>>>(qraw, attn);
    // output projection
    gemm_kernel<<<dim3(D_/64, M/64), 256>>>(attn, Wo, out, M, D_, H_*KH);
}

// round 3
// speedup vs baseline: 1.7238x; 1.7238x over previous
#include <cuda_runtime.h>
#include <cuda_bf16.h>
#include <cstdint>

// Problem constants
#define B_  2
#define T_  2048
#define D_  2048
#define H_  16
#define G_  4
#define KH  128           // head dim
#define NREP (H_/G_)      // 4
#define EPS 1e-6f
static const float SCALE = 0.088388347648318447f; // 128^-0.5

// ---------------- scratch (device globals) -----------------------------------
__device__ float g_qraw[B_*T_*H_*2*KH];  // [B,T,H,2K]
__device__ float g_kraw[B_*T_*G_*KH];    // [B,T,G,K]
__device__ float g_vraw[B_*T_*G_*KH];    // [B,T,G,K]
__device__ float g_attn[B_*T_*H_*KH];    // [B,T,H,K]

// ============================ mma helpers ====================================
__device__ __forceinline__ uint32_t smem_u32(const void* p) {
    return (uint32_t)__cvta_generic_to_shared((void*)p);
}
__device__ __forceinline__ void ldsm_x4(uint32_t* r, uint32_t addr) {
    asm volatile("ldmatrix.sync.aligned.m8n8.x4.shared.b16 {%0,%1,%2,%3}, [%4];"
        : "=r"(r[0]), "=r"(r[1]), "=r"(r[2]), "=r"(r[3]) : "r"(addr));
}
__device__ __forceinline__ void ldsm_x4_t(uint32_t* r, uint32_t addr) {
    asm volatile("ldmatrix.sync.aligned.m8n8.x4.trans.shared.b16 {%0,%1,%2,%3}, [%4];"
        : "=r"(r[0]), "=r"(r[1]), "=r"(r[2]), "=r"(r[3]) : "r"(addr));
}
__device__ __forceinline__ void mma16816(float* d, const uint32_t* a, const uint32_t* b) {
    asm volatile("mma.sync.aligned.m16n8k16.row.col.f32.bf16.bf16.f32 "
        "{%0,%1,%2,%3}, {%4,%5,%6,%7}, {%8,%9}, {%0,%1,%2,%3};"
        : "+f"(d[0]), "+f"(d[1]), "+f"(d[2]), "+f"(d[3])
        : "r"(a[0]), "r"(a[1]), "r"(a[2]), "r"(a[3]), "r"(b[0]), "r"(b[1]));
}

// pack 2 fp32 -> bf16x2 hi word + residual bf16x2 lo word
__device__ __forceinline__ uint32_t pack2(float a, float b, uint32_t& lo) {
    __nv_bfloat16 ha = __float2bfloat16_rn(a);
    __nv_bfloat16 hb = __float2bfloat16_rn(b);
    float la = a - __bfloat162float(ha);
    float lb = b - __bfloat162float(hb);
    __nv_bfloat162 hp; hp.x = ha; hp.y = hb;
    __nv_bfloat162 lp = __floats2bfloat162_rn(la, lb);
    lo = *reinterpret_cast<uint32_t*>(&lp);
    return *reinterpret_cast<uint32_t*>(&hp);
}
__device__ __forceinline__ void cvt_store8(char* hb, char* lb, uint32_t off,
                                           float4 v0, float4 v1) {
    uint4 Hv, Lv;
    Hv.x = pack2(v0.x, v0.y, Lv.x);
    Hv.y = pack2(v0.z, v0.w, Lv.y);
    Hv.z = pack2(v1.x, v1.y, Lv.z);
    Hv.w = pack2(v1.z, v1.w, Lv.w);
    *(uint4*)(hb + off) = Hv;
    *(uint4*)(lb + off) = Lv;
}

// ================= HMMA GEMM: C[M,N] = A[M,Kd] @ B[Kd,N] =====================
// CTA 128x128, BK=32, 256 threads, warp tile 64x32, bf16 hi/lo 3-term split.
#define A_STRIDE 80      // bytes per A m-row (32 bf16 + 8 pad)
#define B_STRIDE 272     // bytes per B k-row (128 bf16 + 8 pad)
#define AH_OFF  0
#define AL_OFFB 10240
#define BH_OFF  20480
#define BL_OFF  29184
#define GEMM_SMEM 37888

__global__ __launch_bounds__(256, 2)
void gemm_tc_kernel(const float* __restrict__ A, const float* __restrict__ Bm,
                    float* __restrict__ C, int N, int Kd) {
    __shared__ char smc[GEMM_SMEM];
    uint32_t smb = smem_u32(smc);
    const int tid = threadIdx.x;
    const int wid = tid >> 5, lane = tid & 31;
    const int m0 = blockIdx.y * 128, n0 = blockIdx.x * 128;
    const int wm = (wid & 1) * 64, wn = (wid >> 1) * 32;

    // loader indices
    const int arow = tid >> 1;            // 0..127 (m row)
    const int akb  = (tid & 1) * 16;      // k base
    const int bkr  = tid >> 3;            // 0..31  (k row)
    const int bnb  = (tid & 7) * 16;      // n base

    // ldmatrix per-lane source addresses
    const int a_r = lane & 15, a_c = (lane >> 4) << 3;
    const uint32_t aoffH = smb + AH_OFF + (uint32_t)(wm + a_r) * A_STRIDE + a_c * 2;
    const uint32_t aoffL = aoffH + (AL_OFFB - AH_OFF);
    const int bg  = lane >> 3;
    const int b_k = ((bg & 1) << 3) + (lane & 7);
    const int b_n = (bg & 2) ? 8 : 0;
    const uint32_t boffH = smb + BH_OFF + (uint32_t)b_k * B_STRIDE + (uint32_t)(wn + b_n) * 2;
    const uint32_t boffL = boffH + (BL_OFF - BH_OFF);

    float acc[4][4][4];
    #pragma unroll
    for (int i = 0; i < 4; i++)
        #pragma unroll
        for (int j = 0; j < 4; j++)
            #pragma unroll
            for (int e = 0; e < 4; e++) acc[i][j][e] = 0.0f;

    const int NC = Kd >> 5;
    const float* aptr = A + (size_t)(m0 + arow) * Kd + akb;
    const float* bptr = Bm + (size_t)bkr * N + n0 + bnb;
    char* AhS = smc + AH_OFF;  char* AlS = smc + AL_OFFB;
    char* BhS = smc + BH_OFF;  char* BlS = smc + BL_OFF;
    const uint32_t a_soff = (uint32_t)arow * A_STRIDE;
    const uint32_t b_soff = (uint32_t)bkr * B_STRIDE;

    for (int c = 0; c < NC; c++) {
        // ---- load fp32, convert to hi/lo bf16, store to smem ----
        {
            float4 v0 = *(const float4*)(aptr);
            float4 v1 = *(const float4*)(aptr + 4);
            cvt_store8(AhS, AlS, a_soff + akb * 2, v0, v1);
            v0 = *(const float4*)(aptr + 8);
            v1 = *(const float4*)(aptr + 12);
            cvt_store8(AhS, AlS, a_soff + (akb + 8) * 2, v0, v1);
            aptr += 32;
        }
        {
            float4 v0 = *(const float4*)(bptr);
            float4 v1 = *(const float4*)(bptr + 4);
            cvt_store8(BhS, BlS, b_soff + bnb * 2, v0, v1);
            v0 = *(const float4*)(bptr + 8);
            v1 = *(const float4*)(bptr + 12);
            cvt_store8(BhS, BlS, b_soff + (bnb + 8) * 2, v0, v1);
            bptr += (size_t)32 * N;
        }
        __syncthreads();

        // ---- compute: 2 k-halves x 3 split terms ----
        #pragma unroll
        for (int kk = 0; kk < 2; kk++) {
            const uint32_t akoff = (uint32_t)kk * 32;           // 16 bf16
            const uint32_t bkoff = (uint32_t)kk * (16 * B_STRIDE);
            uint32_t ah[4][4], bh[2][4];
            #pragma unroll
            for (int mi = 0; mi < 4; mi++)
                ldsm_x4(ah[mi], aoffH + mi * (16 * A_STRIDE) + akoff);
            #pragma unroll
            for (int bj = 0; bj < 2; bj++)
                ldsm_x4_t(bh[bj], boffH + bkoff + bj * 32);
            // Ah * Bh
            #pragma unroll
            for (int mi = 0; mi < 4; mi++)
                #pragma unroll
                for (int nj = 0; nj < 4; nj++)
                    mma16816(acc[mi][nj], ah[mi], &bh[nj >> 1][(nj & 1) * 2]);
            // Ah * Bl
            {
                uint32_t bl[2][4];
                #pragma unroll
                for (int bj = 0; bj < 2; bj++)
                    ldsm_x4_t(bl[bj], boffL + bkoff + bj * 32);
                #pragma unroll
                for (int mi = 0; mi < 4; mi++)
                    #pragma unroll
                    for (int nj = 0; nj < 4; nj++)
                        mma16816(acc[mi][nj], ah[mi], &bl[nj >> 1][(nj & 1) * 2]);
            }
            // Al * Bh
            {
                uint32_t al[4][4];
                #pragma unroll
                for (int mi = 0; mi < 4; mi++)
                    ldsm_x4(al[mi], aoffL + mi * (16 * A_STRIDE) + akoff);
                #pragma unroll
                for (int mi = 0; mi < 4; mi++)
                    #pragma unroll
                    for (int nj = 0; nj < 4; nj++)
                        mma16816(acc[mi][nj], al[mi], &bh[nj >> 1][(nj & 1) * 2]);
            }
        }
        __syncthreads();
    }

    // ---- epilogue ----
    const int r0 = m0 + wm + (lane >> 2);
    const int c0 = n0 + wn + (lane & 3) * 2;
    #pragma unroll
    for (int mi = 0; mi < 4; mi++) {
        #pragma unroll
        for (int nj = 0; nj < 4; nj++) {
            float2 lo2; lo2.x = acc[mi][nj][0]; lo2.y = acc[mi][nj][1];
            float2 hi2; hi2.x = acc[mi][nj][2]; hi2.y = acc[mi][nj][3];
            *(float2*)&C[(size_t)(r0 + mi * 16) * N + c0 + nj * 8] = lo2;
            *(float2*)&C[(size_t)(r0 + mi * 16 + 8) * N + c0 + nj * 8] = hi2;
        }
    }
}

// ---------------- fused RMSNorm + RoPE (in place) ----------------------------
__global__ __launch_bounds__(128)
void rope_norm_kernel(float* __restrict__ data, const float* __restrict__ cosp,
                      const float* __restrict__ sinp, const float* __restrict__ w,
                      int rowStride) {
    const int idx = blockIdx.x;
    const int nH  = gridDim.x / (B_ * T_);
    const int bt  = idx / nH;
    const size_t base = (size_t)idx * rowStride;
    const int d = threadIdx.x;

    float x = data[base + d];
    float ss = x * x;
    #pragma unroll
    for (int o = 16; o; o >>= 1) ss += __shfl_xor_sync(0xffffffffu, ss, o);
    __shared__ float wsum[4];
    __shared__ float sn[128];
    if ((d & 31) == 0) wsum[d >> 5] = ss;
    __syncthreads();
    float tot = wsum[0] + wsum[1] + wsum[2] + wsum[3];
    float r = rsqrtf(tot * (1.0f / 128.0f) + EPS);
    sn[d] = x * r * w[d];
    __syncthreads();
    float c = cosp[(size_t)bt * KH + d];
    float s = sinp[(size_t)bt * KH + d];
    float out;
    if (d < 64) out = sn[d] * c - sn[d + 64] * s;
    else        out = sn[d] * c + sn[d - 64] * s;
    data[base + d] = out;
}

// ---------------- flash attention (fp32 SIMT, online softmax) ----------------
#define QS_OFF   0
#define KS_OFF   8448
#define VS_OFF   12672
#define SS_OFF   16896
#define RM_OFF   19008
#define RL_OFF   19072
#define AL_OFF   19136
#define QSEG_OFF 19200
#define KSEG_OFF 19264
#define ATTN_SMEM_FLOATS 19296
#define ATTN_SMEM_BYTES  (ATTN_SMEM_FLOATS * 4)

__global__ __launch_bounds__(128)
void attn_kernel(const float* __restrict__ qraw, const float* __restrict__ kraw,
                 const float* __restrict__ vraw, const int* __restrict__ seg,
                 float* __restrict__ attn) {
    extern __shared__ float sm[];
    float* Qs   = sm + QS_OFF;
    float* Ks   = sm + KS_OFF;
    float* Vs   = sm + VS_OFF;
    float* Ss   = sm + SS_OFF;
    float* rowm = sm + RM_OFF;
    float* rowl = sm + RL_OFF;
    float* alph = sm + AL_OFF;
    int*   qseg = (int*)(sm + QSEG_OFF);
    int*   kseg = (int*)(sm + KSEG_OFF);

    const int tid = threadIdx.x;
    const int tx = tid & 7;
    const int ty = tid >> 3;
    const int bh = blockIdx.y;
    const int b = bh / H_, h = bh % H_;
    const int g = h / NREP;
    const int q0 = blockIdx.x * 64;

    for (int i = tid; i < 64 * 32; i += 128) {
        int r = i >> 5, c4 = (i & 31) << 2;
        *(float4*)&Qs[r * 132 + c4] =
            *(const float4*)&qraw[(size_t)((b * T_ + q0 + r) * H_ + h) * (2 * KH) + c4];
    }
    if (tid < 64) {
        rowm[tid] = -1e30f;
        rowl[tid] = 0.0f;
        qseg[tid] = seg[b * T_ + q0 + tid];
    }
    float O[4][16];
    #pragma unroll
    for (int i = 0; i < 4; i++)
        #pragma unroll
        for (int j = 0; j < 16; j++) O[i][j] = 0.0f;
    __syncthreads();

    const int nTiles = (q0 + 64) / 32;
    for (int t = 0; t < nTiles; t++) {
        const int s0 = t * 32;
        for (int i = tid; i < 32 * 32; i += 128) {
            int r = i >> 5, c4 = (i & 31) << 2;
            size_t gb = (size_t)((b * T_ + s0 + r) * G_ + g) * KH + c4;
            *(float4*)&Ks[r * 132 + c4] = *(const float4*)&kraw[gb];
            *(float4*)&Vs[r * 132 + c4] = *(const float4*)&vraw[gb];
        }
        if (tid < 32) kseg[tid] = seg[b * T_ + s0 + tid];
        __syncthreads();

        float sAcc[4][4] = {};
        #pragma unroll 8
        for (int d = 0; d < 128; d += 4) {
            float4 a0 = *(const float4*)&Qs[(ty     ) * 132 + d];
            float4 a1 = *(const float4*)&Qs[(ty + 16) * 132 + d];
            float4 a2 = *(const float4*)&Qs[(ty + 32) * 132 + d];
            float4 a3 = *(const float4*)&Qs[(ty + 48) * 132 + d];
            #pragma unroll
            for (int j = 0; j < 4; j++) {
                float4 bq = *(const float4*)&Ks[(tx + 8 * j) * 132 + d];
                sAcc[0][j] += a0.x*bq.x + a0.y*bq.y + a0.z*bq.z + a0.w*bq.w;
                sAcc[1][j] += a1.x*bq.x + a1.y*bq.y + a1.z*bq.z + a1.w*bq.w;
                sAcc[2][j] += a2.x*bq.x + a2.y*bq.y + a2.z*bq.z + a2.w*bq.w;
                sAcc[3][j] += a3.x*bq.x + a3.y*bq.y + a3.z*bq.z + a3.w*bq.w;
            }
        }
        #pragma unroll
        for (int i = 0; i < 4; i++) {
            int m = ty + 16 * i, qp = q0 + m;
            #pragma unroll
            for (int j = 0; j < 4; j++) {
                int n = tx + 8 * j, kp = s0 + n;
                float val = sAcc[i][j] * SCALE;
                if (kp > qp || kseg[n] != qseg[m]) val = -1e30f;
                Ss[m * 33 + n] = val;
            }
        }
        __syncthreads();

        if (tid < 64) {
            const int r = tid;
            float mo = rowm[r];
            float mx = mo;
            #pragma unroll 8
            for (int n = 0; n < 32; n++) mx = fmaxf(mx, Ss[r * 33 + n]);
            float a = __expf(mo - mx);
            float sum = 0.0f;
            #pragma unroll 8
            for (int n = 0; n < 32; n++) {
                float p = __expf(Ss[r * 33 + n] - mx);
                Ss[r * 33 + n] = p;
                sum += p;
            }
            rowm[r] = mx;
            rowl[r] = rowl[r] * a + sum;
            alph[r] = a;
        }
        __syncthreads();

        #pragma unroll
        for (int i = 0; i < 4; i++) {
            float a = alph[ty + 16 * i];
            #pragma unroll
            for (int j = 0; j < 16; j++) O[i][j] *= a;
        }
        #pragma unroll 4
        for (int n = 0; n < 32; n++) {
            float p0 = Ss[(ty     ) * 33 + n];
            float p1 = Ss[(ty + 16) * 33 + n];
            float p2 = Ss[(ty + 32) * 33 + n];
            float p3 = Ss[(ty + 48) * 33 + n];
            #pragma unroll
            for (int jj = 0; jj < 4; jj++) {
                float4 v = *(const float4*)&Vs[n * 132 + (tx << 2) + 32 * jj];
                O[0][jj*4+0] += p0*v.x; O[0][jj*4+1] += p0*v.y; O[0][jj*4+2] += p0*v.z; O[0][jj*4+3] += p0*v.w;
                O[1][jj*4+0] += p1*v.x; O[1][jj*4+1] += p1*v.y; O[1][jj*4+2] += p1*v.z; O[1][jj*4+3] += p1*v.w;
                O[2][jj*4+0] += p2*v.x; O[2][jj*4+1] += p2*v.y; O[2][jj*4+2] += p2*v.z; O[2][jj*4+3] += p2*v.w;
                O[3][jj*4+0] += p3*v.x; O[3][jj*4+1] += p3*v.y; O[3][jj*4+2] += p3*v.z; O[3][jj*4+3] += p3*v.w;
            }
        }
        __syncthreads();
    }

    #pragma unroll
    for (int i = 0; i < 4; i++) {
        int m = ty + 16 * i;
        float inv = 1.0f / rowl[m];
        size_t rb = (size_t)((b * T_ + q0 + m) * H_ + h) * KH;
        #pragma unroll
        for (int jj = 0; jj < 4; jj++) {
            float4 o;
            o.x = O[i][jj*4+0] * inv; o.y = O[i][jj*4+1] * inv;
            o.z = O[i][jj*4+2] * inv; o.w = O[i][jj*4+3] * inv;
            *(float4*)&attn[rb + (tx << 2) + 32 * jj] = o;
        }
    }
}

// ---------------- sigmoid gate (in place on attn) ----------------------------
__global__ __launch_bounds__(256)
void gate_kernel(const float* __restrict__ qraw, float* __restrict__ attn) {
    size_t i = (size_t)blockIdx.x * 256 + threadIdx.x;
    int d = (int)(i & 127);
    size_t rest = i >> 7;
    int h = (int)(rest & 15);
    size_t bt = rest >> 4;
    float gv = qraw[(bt * H_ + h) * (2 * KH) + KH + d];
    attn[i] *= 1.0f / (1.0f + __expf(-gv));
}

// ---------------- launch -----------------------------------------------------
extern "C" void kernel_launch(void* const* d_in, const int* in_sizes, int n_in,
                              void* d_out, int out_size) {
    const float* hidden = (const float*)d_in[0];
    const float* cosp   = (const float*)d_in[1];
    const float* sinp   = (const float*)d_in[2];
    const int*   seg    = (const int*)d_in[3];
    const float* Wq = (const float*)d_in[5];
    const float* Wk = (const float*)d_in[6];
    const float* Wv = (const float*)d_in[7];
    const float* Wo = (const float*)d_in[8];
    const float* qw = (const float*)d_in[9];
    const float* kw = (const float*)d_in[10];
    float* out = (float*)d_out;

    float *qraw, *kraw, *vraw, *attn;
    cudaGetSymbolAddress((void**)&qraw, g_qraw);
    cudaGetSymbolAddress((void**)&kraw, g_kraw);
    cudaGetSymbolAddress((void**)&vraw, g_vraw);
    cudaGetSymbolAddress((void**)&attn, g_attn);

    cudaFuncSetAttribute(attn_kernel, cudaFuncAttributeMaxDynamicSharedMemorySize,
                         ATTN_SMEM_BYTES);

    const int M = B_ * T_;       // 4096
    const int NQ = H_ * 2 * KH;  // 4096
    const int NKV = G_ * KH;     // 512

    // projections (tensor core, bf16 hi/lo split; B used directly as [K,N])
    gemm_tc_kernel<<<dim3(NQ / 128, M / 128), 256>>>(hidden, Wq, qraw, NQ, D_);
    gemm_tc_kernel<<<dim3(NKV / 128, M / 128), 256>>>(hidden, Wk, kraw, NKV, D_);
    gemm_tc_kernel<<<dim3(NKV / 128, M / 128), 256>>>(hidden, Wv, vraw, NKV, D_);

    // rmsnorm + rope
    rope_norm_kernel<<<B_*T_*H_, 128>>>(qraw, cosp, sinp, qw, 2 * KH);
    rope_norm_kernel<<<B_*T_*G_, 128>>>(kraw, cosp, sinp, kw, KH);

    // attention
    attn_kernel<<<dim3(T_/64, B_*H_), 128, ATTN_SMEM_BYTES>>>(qraw, kraw, vraw, seg, attn);

    // gate
    gate_kernel<<<(B_*T_*H_*KH)/256, 256>>>(qraw, attn);

    // output projection
    gemm_tc_kernel<<<dim3(D_ / 128, M / 128), 256>>>(attn, Wo, out, D_, H_ * KH);
}

// round 5
// speedup vs baseline: 3.0306x; 1.7581x over previous
#include <cuda_runtime.h>
#include <cuda_bf16.h>
#include <cstdint>

// Problem constants
#define B_  2
#define T_  2048
#define D_  2048
#define H_  16
#define G_  4
#define KH  128
#define EPS 1e-6f
static const float SCALE = 0.088388347648318447f; // 128^-0.5

// ---------------- scratch (device globals) -----------------------------------
__device__ float g_qraw[B_*T_*H_*2*KH];       // [bt][h*256+..] fp32 (gate kept here)
__device__ float g_kraw[B_*T_*G_*KH];
__device__ float g_vraw[B_*T_*G_*KH];
// bf16 hi/lo splits
__device__ __nv_bfloat16 g_hid_h[B_*T_*D_],  g_hid_l[B_*T_*D_];
__device__ __nv_bfloat16 g_wq_h[D_*H_*2*KH], g_wq_l[D_*H_*2*KH];
__device__ __nv_bfloat16 g_wk_h[D_*G_*KH],   g_wk_l[D_*G_*KH];
__device__ __nv_bfloat16 g_wv_h[D_*G_*KH],   g_wv_l[D_*G_*KH];
__device__ __nv_bfloat16 g_wo_h[H_*KH*D_],   g_wo_l[H_*KH*D_];
__device__ __nv_bfloat16 g_qb_h[B_*H_*T_*KH], g_qb_l[B_*H_*T_*KH];  // [b,h,t,d]
__device__ __nv_bfloat16 g_kb_h[B_*G_*T_*KH], g_kb_l[B_*G_*T_*KH];  // [b,g,t,d]
__device__ __nv_bfloat16 g_vb_h[B_*G_*T_*KH], g_vb_l[B_*G_*T_*KH];
__device__ __nv_bfloat16 g_ao_h[B_*T_*H_*KH], g_ao_l[B_*T_*H_*KH]; // gated attn, [bt][h*128+d]

// ============================ helpers ========================================
__device__ __forceinline__ uint32_t smem_u32(const void* p) {
    return (uint32_t)__cvta_generic_to_shared((void*)p);
}
__device__ __forceinline__ void ldsm_x4(uint32_t* r, uint32_t addr) {
    asm volatile("ldmatrix.sync.aligned.m8n8.x4.shared.b16 {%0,%1,%2,%3}, [%4];"
        : "=r"(r[0]), "=r"(r[1]), "=r"(r[2]), "=r"(r[3]) : "r"(addr));
}
__device__ __forceinline__ void ldsm_x4_t(uint32_t* r, uint32_t addr) {
    asm volatile("ldmatrix.sync.aligned.m8n8.x4.trans.shared.b16 {%0,%1,%2,%3}, [%4];"
        : "=r"(r[0]), "=r"(r[1]), "=r"(r[2]), "=r"(r[3]) : "r"(addr));
}
__device__ __forceinline__ void mma2(float* d, const uint32_t* a, uint32_t b0, uint32_t b1) {
    asm volatile("mma.sync.aligned.m16n8k16.row.col.f32.bf16.bf16.f32 "
        "{%0,%1,%2,%3}, {%4,%5,%6,%7}, {%8,%9}, {%0,%1,%2,%3};"
        : "+f"(d[0]), "+f"(d[1]), "+f"(d[2]), "+f"(d[3])
        : "r"(a[0]), "r"(a[1]), "r"(a[2]), "r"(a[3]), "r"(b0), "r"(b1));
}
__device__ __forceinline__ void cpa16(uint32_t s, const void* g) {
    asm volatile("cp.async.cg.shared.global [%0], [%1], 16;" :: "r"(s), "l"(g));
}
__device__ __forceinline__ void cpa_commit() { asm volatile("cp.async.commit_group;"); }
template<int N> __device__ __forceinline__ void cpa_wait() {
    asm volatile("cp.async.wait_group %0;" :: "n"(N));
}
__device__ __forceinline__ float ex2f(float x) {
    float y; asm("ex2.approx.ftz.f32 %0, %1;" : "=f"(y) : "f"(x)); return y;
}
__device__ __forceinline__ uint32_t pack2(float a, float b, uint32_t& lo) {
    __nv_bfloat16 ha = __float2bfloat16_rn(a);
    __nv_bfloat16 hb = __float2bfloat16_rn(b);
    __nv_bfloat162 hp; hp.x = ha; hp.y = hb;
    __nv_bfloat162 lp = __floats2bfloat162_rn(a - __bfloat162float(ha),
                                              b - __bfloat162float(hb));
    lo = *reinterpret_cast<uint32_t*>(&lp);
    return *reinterpret_cast<uint32_t*>(&hp);
}

// ---------------- split fp32 -> bf16 hi/lo -----------------------------------
__global__ __launch_bounds__(256)
void split4_kernel(const float* __restrict__ in, __nv_bfloat16* __restrict__ hi,
                   __nv_bfloat16* __restrict__ lo) {
    size_t i = ((size_t)blockIdx.x * 256 + threadIdx.x) * 4;
    float4 v = *(const float4*)(in + i);
    uint32_t l0, l1;
    uint32_t h0 = pack2(v.x, v.y, l0);
    uint32_t h1 = pack2(v.z, v.w, l1);
    *(uint32_t*)(hi + i) = h0; *(uint32_t*)(hi + i + 2) = h1;
    *(uint32_t*)(lo + i) = l0; *(uint32_t*)(lo + i + 2) = l1;
}

// ================= GEMM: C[M,N] = A @ B, 3-term bf16 split ===================
// CTA 128x256, BK=32, 256 thr, 8 warps x (64x64), 2-stage cp.async.
#define GA_ST 80
#define GB_ST 528
#define G_AH 0
#define G_AL 10240
#define G_BH 20480
#define G_BL 37376
#define G_STAGE 54272
#define G_SMEM 108544

__global__ __launch_bounds__(256, 1)
void gemm_bf3_kernel(const __nv_bfloat16* __restrict__ Ah, const __nv_bfloat16* __restrict__ Al,
                     const __nv_bfloat16* __restrict__ Bh, const __nv_bfloat16* __restrict__ Bl,
                     const __nv_bfloat16* __restrict__ B2h, const __nv_bfloat16* __restrict__ B2l,
                     float* __restrict__ C, float* __restrict__ C2,
                     int N, int Kd, int dual) {
    extern __shared__ char sg[];
    uint32_t smb = smem_u32(sg);
    const int tid = threadIdx.x, wid = tid >> 5, lane = tid & 31;
    const int m0 = blockIdx.y * 128;
    int n0 = blockIdx.x * 256;
    const __nv_bfloat16 *bh = Bh, *bl = Bl;
    float* c = C;
    int bst = N;
    if (dual) {
        bst = 512;
        if (n0 >= 512) { bh = B2h; bl = B2l; c = C2; n0 -= 512; }
    }
    const int wm = (wid & 1) * 64, wn = (wid >> 1) * 64;

    float acc[4][8][4];
    #pragma unroll
    for (int i = 0; i < 4; i++)
        #pragma unroll
        for (int j = 0; j < 8; j++)
            #pragma unroll
            for (int e = 0; e < 4; e++) acc[i][j][e] = 0.0f;

    const int NC = Kd >> 5;

    #define G_ISSUE(ch) do { \
        int _s = (ch) & 1; int _k0 = (ch) << 5; \
        uint32_t _st = smb + _s * G_STAGE; \
        _Pragma("unroll") \
        for (int _j = 0; _j < 2; _j++) { \
            int _i = tid + 256 * _j; int _r = _i >> 2, _cc = _i & 3; \
            size_t _go = (size_t)(m0 + _r) * Kd + _k0 + _cc * 8; \
            cpa16(_st + G_AH + _r * GA_ST + _cc * 16, Ah + _go); \
            cpa16(_st + G_AL + _r * GA_ST + _cc * 16, Al + _go); \
        } \
        _Pragma("unroll") \
        for (int _j = 0; _j < 4; _j++) { \
            int _i = tid + 256 * _j; int _r = _i >> 5, _cc = _i & 31; \
            size_t _go = (size_t)(_k0 + _r) * bst + n0 + _cc * 8; \
            cpa16(_st + G_BH + _r * GB_ST + _cc * 16, bh + _go); \
            cpa16(_st + G_BL + _r * GB_ST + _cc * 16, bl + _go); \
        } \
        cpa_commit(); \
    } while (0)

    G_ISSUE(0);

    const int a_r = lane & 15;
    const int a_cb = (lane >> 4) * 16;
    const int b_k = (((lane >> 3) & 1) << 3) + (lane & 7);
    const int b_cb = ((lane >> 3) & 2) ? 16 : 0;

    for (int ch = 0; ch < NC; ch++) {
        if (ch + 1 < NC) { G_ISSUE(ch + 1); cpa_wait<1>(); }
        else cpa_wait<0>();
        __syncthreads();
        uint32_t st = smb + (ch & 1) * G_STAGE;
        uint32_t aHb = st + G_AH + (wm + a_r) * GA_ST + a_cb;
        uint32_t aLb = st + G_AL + (wm + a_r) * GA_ST + a_cb;
        uint32_t bHb = st + G_BH + b_k * GB_ST + wn * 2 + b_cb;
        uint32_t bLb = st + G_BL + b_k * GB_ST + wn * 2 + b_cb;

        #pragma unroll
        for (int kc = 0; kc < 2; kc++) {
            uint32_t ah[4][4], al[4][4];
            #pragma unroll
            for (int mi = 0; mi < 4; mi++) {
                ldsm_x4(ah[mi], aHb + mi * (16 * GA_ST) + kc * 32);
                ldsm_x4(al[mi], aLb + mi * (16 * GA_ST) + kc * 32);
            }
            #pragma unroll
            for (int bj = 0; bj < 4; bj++) {
                uint32_t bhf[4], blf[4];
                ldsm_x4_t(bhf, bHb + kc * (16 * GB_ST) + bj * 32);
                ldsm_x4_t(blf, bLb + kc * (16 * GB_ST) + bj * 32);
                #pragma unroll
                for (int mi = 0; mi < 4; mi++) {
                    mma2(acc[mi][2*bj],   ah[mi], bhf[0], bhf[1]);
                    mma2(acc[mi][2*bj+1], ah[mi], bhf[2], bhf[3]);
                    mma2(acc[mi][2*bj],   ah[mi], blf[0], blf[1]);
                    mma2(acc[mi][2*bj+1], ah[mi], blf[2], blf[3]);
                    mma2(acc[mi][2*bj],   al[mi], bhf[0], bhf[1]);
                    mma2(acc[mi][2*bj+1], al[mi], bhf[2], bhf[3]);
                }
            }
        }
        __syncthreads();
    }

    const int r0 = m0 + wm + (lane >> 2);
    const int c0 = n0 + wn + (lane & 3) * 2;
    #pragma unroll
    for (int mi = 0; mi < 4; mi++) {
        #pragma unroll
        for (int nj = 0; nj < 8; nj++) {
            float2 lo2; lo2.x = acc[mi][nj][0]; lo2.y = acc[mi][nj][1];
            float2 hi2; hi2.x = acc[mi][nj][2]; hi2.y = acc[mi][nj][3];
            *(float2*)&c[(size_t)(r0 + mi * 16) * bst + c0 + nj * 8] = lo2;
            *(float2*)&c[(size_t)(r0 + mi * 16 + 8) * bst + c0 + nj * 8] = hi2;
        }
    }
}

// ---------------- RMSNorm + RoPE -> bf16 hi/lo (Q) ---------------------------
__global__ __launch_bounds__(128)
void rope_norm_q_kernel(const float* __restrict__ qraw, const float* __restrict__ cosp,
                        const float* __restrict__ sinp, const float* __restrict__ w,
                        __nv_bfloat16* __restrict__ outh, __nv_bfloat16* __restrict__ outl) {
    const int idx = blockIdx.x;           // bt*H + h
    const int bt = idx >> 4, h = idx & 15;
    const int b = bt >> 11, t = bt & 2047;
    const int d = threadIdx.x;
    float x = qraw[(size_t)idx * 256 + d];
    float ss = x * x;
    #pragma unroll
    for (int o = 16; o; o >>= 1) ss += __shfl_xor_sync(0xffffffffu, ss, o);
    __shared__ float wsum[4];
    __shared__ float sn[128];
    if ((d & 31) == 0) wsum[d >> 5] = ss;
    __syncthreads();
    float tot = wsum[0] + wsum[1] + wsum[2] + wsum[3];
    float r = rsqrtf(tot * (1.0f / 128.0f) + EPS);
    sn[d] = x * r * w[d];
    __syncthreads();
    float c = cosp[(size_t)bt * KH + d];
    float s = sinp[(size_t)bt * KH + d];
    float out = (d < 64) ? sn[d] * c - sn[d + 64] * s : sn[d] * c + sn[d - 64] * s;
    size_t o = ((size_t)(b * H_ + h) * T_ + t) * KH + d;
    __nv_bfloat16 hv = __float2bfloat16_rn(out);
    outh[o] = hv;
    outl[o] = __float2bfloat16_rn(out - __bfloat162float(hv));
}

__global__ __launch_bounds__(128)
void rope_norm_k_kernel(const float* __restrict__ kraw, const float* __restrict__ cosp,
                        const float* __restrict__ sinp, const float* __restrict__ w,
                        __nv_bfloat16* __restrict__ outh, __nv_bfloat16* __restrict__ outl) {
    const int idx = blockIdx.x;           // bt*G + g
    const int bt = idx >> 2, g = idx & 3;
    const int b = bt >> 11, t = bt & 2047;
    const int d = threadIdx.x;
    float x = kraw[(size_t)idx * 128 + d];
    float ss = x * x;
    #pragma unroll
    for (int o = 16; o; o >>= 1) ss += __shfl_xor_sync(0xffffffffu, ss, o);
    __shared__ float wsum[4];
    __shared__ float sn[128];
    if ((d & 31) == 0) wsum[d >> 5] = ss;
    __syncthreads();
    float tot = wsum[0] + wsum[1] + wsum[2] + wsum[3];
    float r = rsqrtf(tot * (1.0f / 128.0f) + EPS);
    sn[d] = x * r * w[d];
    __syncthreads();
    float c = cosp[(size_t)bt * KH + d];
    float s = sinp[(size_t)bt * KH + d];
    float out = (d < 64) ? sn[d] * c - sn[d + 64] * s : sn[d] * c + sn[d - 64] * s;
    size_t o = ((size_t)(b * G_ + g) * T_ + t) * KH + d;
    __nv_bfloat16 hv = __float2bfloat16_rn(out);
    outh[o] = hv;
    outl[o] = __float2bfloat16_rn(out - __bfloat162float(hv));
}

// ---------------- V split with layout remap ----------------------------------
__global__ __launch_bounds__(256)
void vsplit_kernel(const float* __restrict__ vraw, __nv_bfloat16* __restrict__ vh,
                   __nv_bfloat16* __restrict__ vl) {
    size_t i = (size_t)blockIdx.x * 256 + threadIdx.x;   // pair index
    int d = (int)((i & 63) << 1);
    int g = (int)((i >> 6) & 3);
    size_t bt = i >> 8;
    int b = (int)(bt >> 11), t = (int)(bt & 2047);
    float2 v = *(const float2*)&vraw[(bt * G_ + g) * 128 + d];
    uint32_t lo; uint32_t hi = pack2(v.x, v.y, lo);
    size_t o = ((size_t)(b * G_ + g) * T_ + t) * KH + d;
    *(uint32_t*)&vh[o] = hi;
    *(uint32_t*)&vl[o] = lo;
}

// ================= tensor-core flash attention ===============================
// CTA: 128 q-rows, key tiles of 64, 256 threads (8 warps x 16 rows).
#define AT_ST 272
#define AT_KV 69632             // after Qhi/Qlo (2*128*272)
#define AT_KVSTG 69632          // per stage: Khi,Klo,Vhi,Vlo each 64*272
#define AT_SEG 208896
#define AT_SMEM 209408

__global__ __launch_bounds__(256, 1)
void attn_tc_kernel(const __nv_bfloat16* __restrict__ qh, const __nv_bfloat16* __restrict__ ql,
                    const __nv_bfloat16* __restrict__ kh, const __nv_bfloat16* __restrict__ kl,
                    const __nv_bfloat16* __restrict__ vh, const __nv_bfloat16* __restrict__ vl,
                    const float* __restrict__ qraw, const int* __restrict__ seg,
                    __nv_bfloat16* __restrict__ oh, __nv_bfloat16* __restrict__ ol) {
    extern __shared__ char sa[];
    uint32_t smb = smem_u32(sa);
    const int tid = threadIdx.x, wid = tid >> 5, lane = tid & 31;
    const int qt = (int)(gridDim.x - 1 - blockIdx.x);   // heavy tiles first
    const int q0 = qt * 128;
    const int bh_ = blockIdx.y;
    const int b = bh_ >> 4, h = bh_ & 15;
    const int g = h >> 2;
    const int wm = wid * 16;

    const __nv_bfloat16* qhb = qh + ((size_t)(b * H_ + h) * T_ + q0) * KH;
    const __nv_bfloat16* qlb = ql + ((size_t)(b * H_ + h) * T_ + q0) * KH;
    const __nv_bfloat16* khb = kh + (size_t)(b * G_ + g) * T_ * KH;
    const __nv_bfloat16* klb = kl + (size_t)(b * G_ + g) * T_ * KH;
    const __nv_bfloat16* vhb = vh + (size_t)(b * G_ + g) * T_ * KH;
    const __nv_bfloat16* vlb = vl + (size_t)(b * G_ + g) * T_ * KH;

    // Q prologue loads
    #pragma unroll
    for (int j = 0; j < 8; j++) {
        int i = tid + 256 * j; int r = i >> 4, cc = i & 15;
        cpa16(smb + r * AT_ST + cc * 16, qhb + (size_t)r * KH + cc * 8);
        cpa16(smb + 34816 + r * AT_ST + cc * 16, qlb + (size_t)r * KH + cc * 8);
    }

    const int nT = (q0 + 128) / 64;

    #define AT_ISSUE(t) do { \
        int _s = (t) & 1; int _s0 = (t) * 64; \
        uint32_t _bs = smb + AT_KV + _s * AT_KVSTG; \
        _Pragma("unroll") \
        for (int _j = 0; _j < 4; _j++) { \
            int _i = tid + 256 * _j; int _r = _i >> 4, _cc = _i & 15; \
            size_t _go = (size_t)(_s0 + _r) * KH + _cc * 8; \
            cpa16(_bs + _r * AT_ST + _cc * 16, khb + _go); \
            cpa16(_bs + 17408 + _r * AT_ST + _cc * 16, klb + _go); \
            cpa16(_bs + 34816 + _r * AT_ST + _cc * 16, vhb + _go); \
            cpa16(_bs + 52224 + _r * AT_ST + _cc * 16, vlb + _go); \
        } \
        if (tid < 16) cpa16(smb + AT_SEG + _s * 256 + tid * 16, seg + (size_t)b * T_ + _s0 + tid * 4); \
        cpa_commit(); \
    } while (0)

    AT_ISSUE(0);

    const int qp0 = q0 + wm + (lane >> 2), qp1 = qp0 + 8;
    const int qs0 = seg[(size_t)b * T_ + qp0];
    const int qs1 = seg[(size_t)b * T_ + qp1];

    float rm0 = -1e30f, rm1 = -1e30f, rl0 = 0.0f, rl1 = 0.0f;
    float oacc[16][4];
    #pragma unroll
    for (int i = 0; i < 16; i++)
        #pragma unroll
        for (int e = 0; e < 4; e++) oacc[i][e] = 0.0f;

    const uint32_t aQh = smb + (wm + (lane & 15)) * AT_ST + (lane >> 4) * 16;
    const uint32_t aQl = aQh + 34816;
    const int vb_k = (((lane >> 3) & 1) << 3) + (lane & 7);
    const int vb_cb = ((lane >> 3) & 2) ? 16 : 0;
    const float SC = SCALE * 1.4426950408889634f;
    const float NEGINF = -__int_as_float(0x7f800000);

    for (int t = 0; t < nT; t++) {
        if (t + 1 < nT) { AT_ISSUE(t + 1); cpa_wait<1>(); }
        else cpa_wait<0>();
        __syncthreads();
        const int s0 = t * 64;
        uint32_t kst = smb + AT_KV + (t & 1) * AT_KVSTG;
        const int* kseg = (const int*)(sa + AT_SEG + (t & 1) * 256);

        // ---- S = Q K^T (3-term) ----
        float sacc[8][4];
        #pragma unroll
        for (int i = 0; i < 8; i++)
            #pragma unroll
            for (int e = 0; e < 4; e++) sacc[i][e] = 0.0f;

        #pragma unroll
        for (int kc = 0; kc < 8; kc++) {
            uint32_t ahf[4], alf[4];
            ldsm_x4(ahf, aQh + kc * 32);
            ldsm_x4(alf, aQl + kc * 32);
            #pragma unroll
            for (int ng = 0; ng < 4; ng++) {
                uint32_t kbh[4], kbl[4];
                uint32_t ka = kst + (ng * 16 + (lane & 15)) * AT_ST + (lane >> 4) * 16 + kc * 32;
                ldsm_x4(kbh, ka);
                ldsm_x4(kbl, ka + 17408);
                mma2(sacc[2*ng],   ahf, kbh[0], kbh[2]);
                mma2(sacc[2*ng+1], ahf, kbh[1], kbh[3]);
                mma2(sacc[2*ng],   ahf, kbl[0], kbl[2]);
                mma2(sacc[2*ng+1], ahf, kbl[1], kbl[3]);
                mma2(sacc[2*ng],   alf, kbh[0], kbh[2]);
                mma2(sacc[2*ng+1], alf, kbh[1], kbh[3]);
            }
        }

        // ---- scale + mask ----
        const int lc = (lane & 3) * 2;
        #pragma unroll
        for (int gi = 0; gi < 8; gi++) {
            int c0c = s0 + gi * 8 + lc, c1c = c0c + 1;
            int ks0 = kseg[gi * 8 + lc], ks1 = kseg[gi * 8 + lc + 1];
            float v;
            v = sacc[gi][0] * SC; sacc[gi][0] = (c0c <= qp0 && ks0 == qs0) ? v : NEGINF;
            v = sacc[gi][1] * SC; sacc[gi][1] = (c1c <= qp0 && ks1 == qs0) ? v : NEGINF;
            v = sacc[gi][2] * SC; sacc[gi][2] = (c0c <= qp1 && ks0 == qs1) ? v : NEGINF;
            v = sacc[gi][3] * SC; sacc[gi][3] = (c1c <= qp1 && ks1 == qs1) ? v : NEGINF;
        }

        // ---- online softmax ----
        float mx0 = NEGINF, mx1 = NEGINF;
        #pragma unroll
        for (int gi = 0; gi < 8; gi++) {
            mx0 = fmaxf(mx0, fmaxf(sacc[gi][0], sacc[gi][1]));
            mx1 = fmaxf(mx1, fmaxf(sacc[gi][2], sacc[gi][3]));
        }
        mx0 = fmaxf(mx0, __shfl_xor_sync(0xffffffffu, mx0, 1));
        mx0 = fmaxf(mx0, __shfl_xor_sync(0xffffffffu, mx0, 2));
        mx1 = fmaxf(mx1, __shfl_xor_sync(0xffffffffu, mx1, 1));
        mx1 = fmaxf(mx1, __shfl_xor_sync(0xffffffffu, mx1, 2));
        float nm0 = fmaxf(rm0, mx0), nm1 = fmaxf(rm1, mx1);
        float al0 = ex2f(rm0 - nm0), al1 = ex2f(rm1 - nm1);
        rm0 = nm0; rm1 = nm1;
        float sum0 = 0.0f, sum1 = 0.0f;
        #pragma unroll
        for (int gi = 0; gi < 8; gi++) {
            float p;
            p = ex2f(sacc[gi][0] - nm0); sum0 += p; sacc[gi][0] = p;
            p = ex2f(sacc[gi][1] - nm0); sum0 += p; sacc[gi][1] = p;
            p = ex2f(sacc[gi][2] - nm1); sum1 += p; sacc[gi][2] = p;
            p = ex2f(sacc[gi][3] - nm1); sum1 += p; sacc[gi][3] = p;
        }
        rl0 = rl0 * al0 + sum0;
        rl1 = rl1 * al1 + sum1;
        #pragma unroll
        for (int og = 0; og < 16; og++) {
            oacc[og][0] *= al0; oacc[og][1] *= al0;
            oacc[og][2] *= al1; oacc[og][3] *= al1;
        }

        // ---- O += P V (3-term: Ph*Vh + Pl*Vh + Ph*Vl) ----
        #pragma unroll
        for (int kc2 = 0; kc2 < 4; kc2++) {
            uint32_t pa[4], pl[4];
            pa[0] = pack2(sacc[2*kc2][0],   sacc[2*kc2][1],   pl[0]);
            pa[1] = pack2(sacc[2*kc2][2],   sacc[2*kc2][3],   pl[1]);
            pa[2] = pack2(sacc[2*kc2+1][0], sacc[2*kc2+1][1], pl[2]);
            pa[3] = pack2(sacc[2*kc2+1][2], sacc[2*kc2+1][3], pl[3]);
            uint32_t vbase = kst + 34816 + (kc2 * 16 + vb_k) * AT_ST + vb_cb;
            #pragma unroll
            for (int nd = 0; nd < 8; nd++) {
                uint32_t vbh[4], vbl[4];
                ldsm_x4_t(vbh, vbase + nd * 32);
                ldsm_x4_t(vbl, vbase + 17408 + nd * 32);
                mma2(oacc[2*nd],   pa, vbh[0], vbh[1]);
                mma2(oacc[2*nd+1], pa, vbh[2], vbh[3]);
                mma2(oacc[2*nd],   pl, vbh[0], vbh[1]);
                mma2(oacc[2*nd+1], pl, vbh[2], vbh[3]);
                mma2(oacc[2*nd],   pa, vbl[0], vbl[1]);
                mma2(oacc[2*nd+1], pa, vbl[2], vbl[3]);
            }
        }
        __syncthreads();
    }

    // ---- epilogue: normalize, gate, split to bf16 hi/lo ----
    rl0 += __shfl_xor_sync(0xffffffffu, rl0, 1);
    rl0 += __shfl_xor_sync(0xffffffffu, rl0, 2);
    rl1 += __shfl_xor_sync(0xffffffffu, rl1, 1);
    rl1 += __shfl_xor_sync(0xffffffffu, rl1, 2);
    float inv0 = 1.0f / rl0, inv1 = 1.0f / rl1;
    const float L2E = 1.4426950408889634f;
    #pragma unroll
    for (int og = 0; og < 16; og++) {
        int d = og * 8 + (lane & 3) * 2;
        // row 0
        {
            float2 gt = *(const float2*)&qraw[((size_t)(b * T_ + qp0) * H_ + h) * 256 + 128 + d];
            float s0v = 1.0f / (1.0f + ex2f(-gt.x * L2E));
            float s1v = 1.0f / (1.0f + ex2f(-gt.y * L2E));
            float x0 = oacc[og][0] * inv0 * s0v;
            float x1 = oacc[og][1] * inv0 * s1v;
            uint32_t lo; uint32_t hi = pack2(x0, x1, lo);
            size_t o = (size_t)(b * T_ + qp0) * (H_ * KH) + h * KH + d;
            *(uint32_t*)&oh[o] = hi; *(uint32_t*)&ol[o] = lo;
        }
        // row 1
        {
            float2 gt = *(const float2*)&qraw[((size_t)(b * T_ + qp1) * H_ + h) * 256 + 128 + d];
            float s0v = 1.0f / (1.0f + ex2f(-gt.x * L2E));
            float s1v = 1.0f / (1.0f + ex2f(-gt.y * L2E));
            float x0 = oacc[og][2] * inv1 * s0v;
            float x1 = oacc[og][3] * inv1 * s1v;
            uint32_t lo; uint32_t hi = pack2(x0, x1, lo);
            size_t o = (size_t)(b * T_ + qp1) * (H_ * KH) + h * KH + d;
            *(uint32_t*)&oh[o] = hi; *(uint32_t*)&ol[o] = lo;
        }
    }
}

// ---------------- launch -----------------------------------------------------
extern "C" void kernel_launch(void* const* d_in, const int* in_sizes, int n_in,
                              void* d_out, int out_size) {
    const float* hidden = (const float*)d_in[0];
    const float* cosp   = (const float*)d_in[1];
    const float* sinp   = (const float*)d_in[2];
    const int*   seg    = (const int*)d_in[3];
    const float* Wq = (const float*)d_in[5];
    const float* Wk = (const float*)d_in[6];
    const float* Wv = (const float*)d_in[7];
    const float* Wo = (const float*)d_in[8];
    const float* qw = (const float*)d_in[9];
    const float* kw = (const float*)d_in[10];
    float* out = (float*)d_out;

    float *qraw, *kraw, *vraw;
    __nv_bfloat16 *hidh, *hidl, *wqh, *wql, *wkh, *wkl, *wvh, *wvl, *woh, *wol;
    __nv_bfloat16 *qbh, *qbl, *kbh, *kbl, *vbh, *vbl, *aoh, *aol;
    cudaGetSymbolAddress((void**)&qraw, g_qraw);
    cudaGetSymbolAddress((void**)&kraw, g_kraw);
    cudaGetSymbolAddress((void**)&vraw, g_vraw);
    cudaGetSymbolAddress((void**)&hidh, g_hid_h); cudaGetSymbolAddress((void**)&hidl, g_hid_l);
    cudaGetSymbolAddress((void**)&wqh, g_wq_h);   cudaGetSymbolAddress((void**)&wql, g_wq_l);
    cudaGetSymbolAddress((void**)&wkh, g_wk_h);   cudaGetSymbolAddress((void**)&wkl, g_wk_l);
    cudaGetSymbolAddress((void**)&wvh, g_wv_h);   cudaGetSymbolAddress((void**)&wvl, g_wv_l);
    cudaGetSymbolAddress((void**)&woh, g_wo_h);   cudaGetSymbolAddress((void**)&wol, g_wo_l);
    cudaGetSymbolAddress((void**)&qbh, g_qb_h);   cudaGetSymbolAddress((void**)&qbl, g_qb_l);
    cudaGetSymbolAddress((void**)&kbh, g_kb_h);   cudaGetSymbolAddress((void**)&kbl, g_kb_l);
    cudaGetSymbolAddress((void**)&vbh, g_vb_h);   cudaGetSymbolAddress((void**)&vbl, g_vb_l);
    cudaGetSymbolAddress((void**)&aoh, g_ao_h);   cudaGetSymbolAddress((void**)&aol, g_ao_l);

    cudaFuncSetAttribute(gemm_bf3_kernel, cudaFuncAttributeMaxDynamicSharedMemorySize, G_SMEM);
    cudaFuncSetAttribute(attn_tc_kernel,  cudaFuncAttributeMaxDynamicSharedMemorySize, AT_SMEM);

    // 1. split operands to bf16 hi/lo
    split4_kernel<<<(B_*T_*D_) / 1024, 256>>>(hidden, hidh, hidl);
    split4_kernel<<<(D_*H_*2*KH) / 1024, 256>>>(Wq, wqh, wql);
    split4_kernel<<<(D_*G_*KH) / 1024, 256>>>(Wk, wkh, wkl);
    split4_kernel<<<(D_*G_*KH) / 1024, 256>>>(Wv, wvh, wvl);
    split4_kernel<<<(H_*KH*D_) / 1024, 256>>>(Wo, woh, wol);

    // 2. projections
    gemm_bf3_kernel<<<dim3(16, 32), 256, G_SMEM>>>(hidh, hidl, wqh, wql, nullptr, nullptr,
                                                   qraw, nullptr, 4096, 2048, 0);
    gemm_bf3_kernel<<<dim3(4, 32), 256, G_SMEM>>>(hidh, hidl, wkh, wkl, wvh, wvl,
                                                  kraw, vraw, 1024, 2048, 1);

    // 3. rmsnorm + rope -> bf16, V split
    rope_norm_q_kernel<<<B_*T_*H_, 128>>>(qraw, cosp, sinp, qw, qbh, qbl);
    rope_norm_k_kernel<<<B_*T_*G_, 128>>>(kraw, cosp, sinp, kw, kbh, kbl);
    vsplit_kernel<<<(B_*T_*G_*KH/2) / 256, 256>>>(vraw, vbh, vbl);

    // 4. attention (gate fused)
    attn_tc_kernel<<<dim3(T_/128, B_*H_), 256, AT_SMEM>>>(qbh, qbl, kbh, kbl, vbh, vbl,
                                                          qraw, seg, aoh, aol);

    // 5. output projection
    gemm_bf3_kernel<<<dim3(8, 32), 256, G_SMEM>>>(aoh, aol, woh, wol, nullptr, nullptr,
                                                  out, nullptr, 2048, 2048, 0);
}

// round 6
// speedup vs baseline: 3.0345x; 1.0013x over previous
#include <cuda_runtime.h>
#include <cuda_bf16.h>
#include <cstdint>

// Problem constants
#define B_  2
#define T_  2048
#define D_  2048
#define H_  16
#define G_  4
#define KH  128
#define EPS 1e-6f
static const float SCALE = 0.088388347648318447f; // 128^-0.5

// ---------------- scratch (device globals) -----------------------------------
__device__ float g_qraw[B_*T_*H_*2*KH];       // [bt][h*256+..] fp32 (gate kept here)
__device__ float g_kraw[B_*T_*G_*KH];
__device__ float g_vraw[B_*T_*G_*KH];
// bf16 hi/lo splits
__device__ __nv_bfloat16 g_hid_h[B_*T_*D_],  g_hid_l[B_*T_*D_];
__device__ __nv_bfloat16 g_wq_h[D_*H_*2*KH], g_wq_l[D_*H_*2*KH];
__device__ __nv_bfloat16 g_wk_h[D_*G_*KH],   g_wk_l[D_*G_*KH];
__device__ __nv_bfloat16 g_wv_h[D_*G_*KH],   g_wv_l[D_*G_*KH];
__device__ __nv_bfloat16 g_wo_h[H_*KH*D_],   g_wo_l[H_*KH*D_];
__device__ __nv_bfloat16 g_qb_h[B_*H_*T_*KH], g_qb_l[B_*H_*T_*KH];  // [b,h,t,d]
__device__ __nv_bfloat16 g_kb_h[B_*G_*T_*KH], g_kb_l[B_*G_*T_*KH];  // [b,g,t,d]
__device__ __nv_bfloat16 g_vb_h[B_*G_*T_*KH], g_vb_l[B_*G_*T_*KH];
__device__ __nv_bfloat16 g_ao_h[B_*T_*H_*KH], g_ao_l[B_*T_*H_*KH]; // gated attn, [bt][h*128+d]

// ============================ helpers ========================================
__device__ __forceinline__ uint32_t smem_u32(const void* p) {
    return (uint32_t)__cvta_generic_to_shared((void*)p);
}
__device__ __forceinline__ void ldsm_x4(uint32_t* r, uint32_t addr) {
    asm volatile("ldmatrix.sync.aligned.m8n8.x4.shared.b16 {%0,%1,%2,%3}, [%4];"
        : "=r"(r[0]), "=r"(r[1]), "=r"(r[2]), "=r"(r[3]) : "r"(addr));
}
__device__ __forceinline__ void ldsm_x4_t(uint32_t* r, uint32_t addr) {
    asm volatile("ldmatrix.sync.aligned.m8n8.x4.trans.shared.b16 {%0,%1,%2,%3}, [%4];"
        : "=r"(r[0]), "=r"(r[1]), "=r"(r[2]), "=r"(r[3]) : "r"(addr));
}
__device__ __forceinline__ void mma2(float* d, const uint32_t* a, uint32_t b0, uint32_t b1) {
    asm volatile("mma.sync.aligned.m16n8k16.row.col.f32.bf16.bf16.f32 "
        "{%0,%1,%2,%3}, {%4,%5,%6,%7}, {%8,%9}, {%0,%1,%2,%3};"
        : "+f"(d[0]), "+f"(d[1]), "+f"(d[2]), "+f"(d[3])
        : "r"(a[0]), "r"(a[1]), "r"(a[2]), "r"(a[3]), "r"(b0), "r"(b1));
}
__device__ __forceinline__ void cpa16(uint32_t s, const void* g) {
    asm volatile("cp.async.cg.shared.global [%0], [%1], 16;" :: "r"(s), "l"(g));
}
__device__ __forceinline__ void cpa_commit() { asm volatile("cp.async.commit_group;"); }
template<int N> __device__ __forceinline__ void cpa_wait() {
    asm volatile("cp.async.wait_group %0;" :: "n"(N));
}
__device__ __forceinline__ float ex2f(float x) {
    float y; asm("ex2.approx.ftz.f32 %0, %1;" : "=f"(y) : "f"(x)); return y;
}
__device__ __forceinline__ uint32_t pack2(float a, float b, uint32_t& lo) {
    __nv_bfloat16 ha = __float2bfloat16_rn(a);
    __nv_bfloat16 hb = __float2bfloat16_rn(b);
    __nv_bfloat162 hp; hp.x = ha; hp.y = hb;
    __nv_bfloat162 lp = __floats2bfloat162_rn(a - __bfloat162float(ha),
                                              b - __bfloat162float(hb));
    lo = *reinterpret_cast<uint32_t*>(&lp);
    return *reinterpret_cast<uint32_t*>(&hp);
}

// ---------------- split fp32 -> bf16 hi/lo -----------------------------------
__global__ __launch_bounds__(256)
void split4_kernel(const float* __restrict__ in, __nv_bfloat16* __restrict__ hi,
                   __nv_bfloat16* __restrict__ lo) {
    size_t i = ((size_t)blockIdx.x * 256 + threadIdx.x) * 4;
    float4 v = *(const float4*)(in + i);
    uint32_t l0, l1;
    uint32_t h0 = pack2(v.x, v.y, l0);
    uint32_t h1 = pack2(v.z, v.w, l1);
    *(uint32_t*)(hi + i) = h0; *(uint32_t*)(hi + i + 2) = h1;
    *(uint32_t*)(lo + i) = l0; *(uint32_t*)(lo + i + 2) = l1;
}

// ================= GEMM: C[M,N] = A @ B, 3-term bf16 split ===================
// CTA 128x256, BK=32, 256 thr, 8 warps x (64x64), 2-stage cp.async.
#define GA_ST 80
#define GB_ST 528
#define G_AH 0
#define G_AL 10240
#define G_BH 20480
#define G_BL 37376
#define G_STAGE 54272
#define G_SMEM 108544

__global__ __launch_bounds__(256, 1)
void gemm_bf3_kernel(const __nv_bfloat16* __restrict__ Ah, const __nv_bfloat16* __restrict__ Al,
                     const __nv_bfloat16* __restrict__ Bh, const __nv_bfloat16* __restrict__ Bl,
                     const __nv_bfloat16* __restrict__ B2h, const __nv_bfloat16* __restrict__ B2l,
                     float* __restrict__ C, float* __restrict__ C2,
                     int N, int Kd, int dual) {
    extern __shared__ char sg[];
    uint32_t smb = smem_u32(sg);
    const int tid = threadIdx.x, wid = tid >> 5, lane = tid & 31;
    const int m0 = blockIdx.y * 128;
    int n0 = blockIdx.x * 256;
    const __nv_bfloat16 *bh = Bh, *bl = Bl;
    float* c = C;
    int bst = N;
    if (dual) {
        bst = 512;
        if (n0 >= 512) { bh = B2h; bl = B2l; c = C2; n0 -= 512; }
    }
    const int wm = (wid & 1) * 64, wn = (wid >> 1) * 64;

    float acc[4][8][4];
    #pragma unroll
    for (int i = 0; i < 4; i++)
        #pragma unroll
        for (int j = 0; j < 8; j++)
            #pragma unroll
            for (int e = 0; e < 4; e++) acc[i][j][e] = 0.0f;

    const int NC = Kd >> 5;

    #define G_ISSUE(ch) do { \
        int _s = (ch) & 1; int _k0 = (ch) << 5; \
        uint32_t _st = smb + _s * G_STAGE; \
        _Pragma("unroll") \
        for (int _j = 0; _j < 2; _j++) { \
            int _i = tid + 256 * _j; int _r = _i >> 2, _cc = _i & 3; \
            size_t _go = (size_t)(m0 + _r) * Kd + _k0 + _cc * 8; \
            cpa16(_st + G_AH + _r * GA_ST + _cc * 16, Ah + _go); \
            cpa16(_st + G_AL + _r * GA_ST + _cc * 16, Al + _go); \
        } \
        _Pragma("unroll") \
        for (int _j = 0; _j < 4; _j++) { \
            int _i = tid + 256 * _j; int _r = _i >> 5, _cc = _i & 31; \
            size_t _go = (size_t)(_k0 + _r) * bst + n0 + _cc * 8; \
            cpa16(_st + G_BH + _r * GB_ST + _cc * 16, bh + _go); \
            cpa16(_st + G_BL + _r * GB_ST + _cc * 16, bl + _go); \
        } \
        cpa_commit(); \
    } while (0)

    G_ISSUE(0);

    const int a_r = lane & 15;
    const int a_cb = (lane >> 4) * 16;
    const int b_k = (((lane >> 3) & 1) << 3) + (lane & 7);
    const int b_cb = ((lane >> 3) & 2) ? 16 : 0;

    for (int ch = 0; ch < NC; ch++) {
        if (ch + 1 < NC) { G_ISSUE(ch + 1); cpa_wait<1>(); }
        else cpa_wait<0>();
        __syncthreads();
        uint32_t st = smb + (ch & 1) * G_STAGE;
        uint32_t aHb = st + G_AH + (wm + a_r) * GA_ST + a_cb;
        uint32_t aLb = st + G_AL + (wm + a_r) * GA_ST + a_cb;
        uint32_t bHb = st + G_BH + b_k * GB_ST + wn * 2 + b_cb;
        uint32_t bLb = st + G_BL + b_k * GB_ST + wn * 2 + b_cb;

        #pragma unroll
        for (int kc = 0; kc < 2; kc++) {
            uint32_t ah[4][4], al[4][4];
            #pragma unroll
            for (int mi = 0; mi < 4; mi++) {
                ldsm_x4(ah[mi], aHb + mi * (16 * GA_ST) + kc * 32);
                ldsm_x4(al[mi], aLb + mi * (16 * GA_ST) + kc * 32);
            }
            #pragma unroll
            for (int bj = 0; bj < 4; bj++) {
                uint32_t bhf[4], blf[4];
                ldsm_x4_t(bhf, bHb + kc * (16 * GB_ST) + bj * 32);
                ldsm_x4_t(blf, bLb + kc * (16 * GB_ST) + bj * 32);
                #pragma unroll
                for (int mi = 0; mi < 4; mi++) {
                    mma2(acc[mi][2*bj],   ah[mi], bhf[0], bhf[1]);
                    mma2(acc[mi][2*bj+1], ah[mi], bhf[2], bhf[3]);
                    mma2(acc[mi][2*bj],   ah[mi], blf[0], blf[1]);
                    mma2(acc[mi][2*bj+1], ah[mi], blf[2], blf[3]);
                    mma2(acc[mi][2*bj],   al[mi], bhf[0], bhf[1]);
                    mma2(acc[mi][2*bj+1], al[mi], bhf[2], bhf[3]);
                }
            }
        }
        __syncthreads();
    }

    const int r0 = m0 + wm + (lane >> 2);
    const int c0 = n0 + wn + (lane & 3) * 2;
    #pragma unroll
    for (int mi = 0; mi < 4; mi++) {
        #pragma unroll
        for (int nj = 0; nj < 8; nj++) {
            float2 lo2; lo2.x = acc[mi][nj][0]; lo2.y = acc[mi][nj][1];
            float2 hi2; hi2.x = acc[mi][nj][2]; hi2.y = acc[mi][nj][3];
            *(float2*)&c[(size_t)(r0 + mi * 16) * bst + c0 + nj * 8] = lo2;
            *(float2*)&c[(size_t)(r0 + mi * 16 + 8) * bst + c0 + nj * 8] = hi2;
        }
    }
}

// ---------------- RMSNorm + RoPE -> bf16 hi/lo (Q) ---------------------------
__global__ __launch_bounds__(128)
void rope_norm_q_kernel(const float* __restrict__ qraw, const float* __restrict__ cosp,
                        const float* __restrict__ sinp, const float* __restrict__ w,
                        __nv_bfloat16* __restrict__ outh, __nv_bfloat16* __restrict__ outl) {
    const int idx = blockIdx.x;           // bt*H + h
    const int bt = idx >> 4, h = idx & 15;
    const int b = bt >> 11, t = bt & 2047;
    const int d = threadIdx.x;
    float x = qraw[(size_t)idx * 256 + d];
    float ss = x * x;
    #pragma unroll
    for (int o = 16; o; o >>= 1) ss += __shfl_xor_sync(0xffffffffu, ss, o);
    __shared__ float wsum[4];
    __shared__ float sn[128];
    if ((d & 31) == 0) wsum[d >> 5] = ss;
    __syncthreads();
    float tot = wsum[0] + wsum[1] + wsum[2] + wsum[3];
    float r = rsqrtf(tot * (1.0f / 128.0f) + EPS);
    sn[d] = x * r * w[d];
    __syncthreads();
    float c = cosp[(size_t)bt * KH + d];
    float s = sinp[(size_t)bt * KH + d];
    float out = (d < 64) ? sn[d] * c - sn[d + 64] * s : sn[d] * c + sn[d - 64] * s;
    size_t o = ((size_t)(b * H_ + h) * T_ + t) * KH + d;
    __nv_bfloat16 hv = __float2bfloat16_rn(out);
    outh[o] = hv;
    outl[o] = __float2bfloat16_rn(out - __bfloat162float(hv));
}

__global__ __launch_bounds__(128)
void rope_norm_k_kernel(const float* __restrict__ kraw, const float* __restrict__ cosp,
                        const float* __restrict__ sinp, const float* __restrict__ w,
                        __nv_bfloat16* __restrict__ outh, __nv_bfloat16* __restrict__ outl) {
    const int idx = blockIdx.x;           // bt*G + g
    const int bt = idx >> 2, g = idx & 3;
    const int b = bt >> 11, t = bt & 2047;
    const int d = threadIdx.x;
    float x = kraw[(size_t)idx * 128 + d];
    float ss = x * x;
    #pragma unroll
    for (int o = 16; o; o >>= 1) ss += __shfl_xor_sync(0xffffffffu, ss, o);
    __shared__ float wsum[4];
    __shared__ float sn[128];
    if ((d & 31) == 0) wsum[d >> 5] = ss;
    __syncthreads();
    float tot = wsum[0] + wsum[1] + wsum[2] + wsum[3];
    float r = rsqrtf(tot * (1.0f / 128.0f) + EPS);
    sn[d] = x * r * w[d];
    __syncthreads();
    float c = cosp[(size_t)bt * KH + d];
    float s = sinp[(size_t)bt * KH + d];
    float out = (d < 64) ? sn[d] * c - sn[d + 64] * s : sn[d] * c + sn[d - 64] * s;
    size_t o = ((size_t)(b * G_ + g) * T_ + t) * KH + d;
    __nv_bfloat16 hv = __float2bfloat16_rn(out);
    outh[o] = hv;
    outl[o] = __float2bfloat16_rn(out - __bfloat162float(hv));
}

// ---------------- V split with layout remap ----------------------------------
__global__ __launch_bounds__(256)
void vsplit_kernel(const float* __restrict__ vraw, __nv_bfloat16* __restrict__ vh,
                   __nv_bfloat16* __restrict__ vl) {
    size_t i = (size_t)blockIdx.x * 256 + threadIdx.x;   // pair index
    int d = (int)((i & 63) << 1);
    int g = (int)((i >> 6) & 3);
    size_t bt = i >> 8;
    int b = (int)(bt >> 11), t = (int)(bt & 2047);
    float2 v = *(const float2*)&vraw[(bt * G_ + g) * 128 + d];
    uint32_t lo; uint32_t hi = pack2(v.x, v.y, lo);
    size_t o = ((size_t)(b * G_ + g) * T_ + t) * KH + d;
    *(uint32_t*)&vh[o] = hi;
    *(uint32_t*)&vl[o] = lo;
}

// ================= tensor-core flash attention ===============================
// CTA: 128 q-rows, key tiles of 64, 256 threads (8 warps x 16 rows).
#define AT_ST 272
#define AT_KV 69632             // after Qhi/Qlo (2*128*272)
#define AT_KVSTG 69632          // per stage: Khi,Klo,Vhi,Vlo each 64*272
#define AT_SEG 208896
#define AT_SMEM 209408

__global__ __launch_bounds__(256, 1)
void attn_tc_kernel(const __nv_bfloat16* __restrict__ qh, const __nv_bfloat16* __restrict__ ql,
                    const __nv_bfloat16* __restrict__ kh, const __nv_bfloat16* __restrict__ kl,
                    const __nv_bfloat16* __restrict__ vh, const __nv_bfloat16* __restrict__ vl,
                    const float* __restrict__ qraw, const int* __restrict__ seg,
                    __nv_bfloat16* __restrict__ oh, __nv_bfloat16* __restrict__ ol) {
    extern __shared__ char sa[];
    uint32_t smb = smem_u32(sa);
    const int tid = threadIdx.x, wid = tid >> 5, lane = tid & 31;
    const int qt = (int)(gridDim.x - 1 - blockIdx.x);   // heavy tiles first
    const int q0 = qt * 128;
    const int bh_ = blockIdx.y;
    const int b = bh_ >> 4, h = bh_ & 15;
    const int g = h >> 2;
    const int wm = wid * 16;

    const __nv_bfloat16* qhb = qh + ((size_t)(b * H_ + h) * T_ + q0) * KH;
    const __nv_bfloat16* qlb = ql + ((size_t)(b * H_ + h) * T_ + q0) * KH;
    const __nv_bfloat16* khb = kh + (size_t)(b * G_ + g) * T_ * KH;
    const __nv_bfloat16* klb = kl + (size_t)(b * G_ + g) * T_ * KH;
    const __nv_bfloat16* vhb = vh + (size_t)(b * G_ + g) * T_ * KH;
    const __nv_bfloat16* vlb = vl + (size_t)(b * G_ + g) * T_ * KH;

    // Q prologue loads
    #pragma unroll
    for (int j = 0; j < 8; j++) {
        int i = tid + 256 * j; int r = i >> 4, cc = i & 15;
        cpa16(smb + r * AT_ST + cc * 16, qhb + (size_t)r * KH + cc * 8);
        cpa16(smb + 34816 + r * AT_ST + cc * 16, qlb + (size_t)r * KH + cc * 8);
    }

    const int nT = (q0 + 128) / 64;

    #define AT_ISSUE(t) do { \
        int _s = (t) & 1; int _s0 = (t) * 64; \
        uint32_t _bs = smb + AT_KV + _s * AT_KVSTG; \
        _Pragma("unroll") \
        for (int _j = 0; _j < 4; _j++) { \
            int _i = tid + 256 * _j; int _r = _i >> 4, _cc = _i & 15; \
            size_t _go = (size_t)(_s0 + _r) * KH + _cc * 8; \
            cpa16(_bs + _r * AT_ST + _cc * 16, khb + _go); \
            cpa16(_bs + 17408 + _r * AT_ST + _cc * 16, klb + _go); \
            cpa16(_bs + 34816 + _r * AT_ST + _cc * 16, vhb + _go); \
            cpa16(_bs + 52224 + _r * AT_ST + _cc * 16, vlb + _go); \
        } \
        if (tid < 16) cpa16(smb + AT_SEG + _s * 256 + tid * 16, seg + (size_t)b * T_ + _s0 + tid * 4); \
        cpa_commit(); \
    } while (0)

    AT_ISSUE(0);

    const int qp0 = q0 + wm + (lane >> 2), qp1 = qp0 + 8;
    const int qs0 = seg[(size_t)b * T_ + qp0];
    const int qs1 = seg[(size_t)b * T_ + qp1];

    float rm0 = -1e30f, rm1 = -1e30f, rl0 = 0.0f, rl1 = 0.0f;
    float oacc[16][4];
    #pragma unroll
    for (int i = 0; i < 16; i++)
        #pragma unroll
        for (int e = 0; e < 4; e++) oacc[i][e] = 0.0f;

    const uint32_t aQh = smb + (wm + (lane & 15)) * AT_ST + (lane >> 4) * 16;
    const uint32_t aQl = aQh + 34816;
    const int vb_k = (((lane >> 3) & 1) << 3) + (lane & 7);
    const int vb_cb = ((lane >> 3) & 2) ? 16 : 0;
    const float SC = SCALE * 1.4426950408889634f;
    const float NEGINF = -__int_as_float(0x7f800000);

    for (int t = 0; t < nT; t++) {
        if (t + 1 < nT) { AT_ISSUE(t + 1); cpa_wait<1>(); }
        else cpa_wait<0>();
        __syncthreads();
        const int s0 = t * 64;
        uint32_t kst = smb + AT_KV + (t & 1) * AT_KVSTG;
        const int* kseg = (const int*)(sa + AT_SEG + (t & 1) * 256);

        // ---- S = Q K^T (3-term) ----
        float sacc[8][4];
        #pragma unroll
        for (int i = 0; i < 8; i++)
            #pragma unroll
            for (int e = 0; e < 4; e++) sacc[i][e] = 0.0f;

        #pragma unroll
        for (int kc = 0; kc < 8; kc++) {
            uint32_t ahf[4], alf[4];
            ldsm_x4(ahf, aQh + kc * 32);
            ldsm_x4(alf, aQl + kc * 32);
            #pragma unroll
            for (int ng = 0; ng < 4; ng++) {
                uint32_t kbh[4], kbl[4];
                uint32_t ka = kst + (ng * 16 + (lane & 15)) * AT_ST + (lane >> 4) * 16 + kc * 32;
                ldsm_x4(kbh, ka);
                ldsm_x4(kbl, ka + 17408);
                mma2(sacc[2*ng],   ahf, kbh[0], kbh[2]);
                mma2(sacc[2*ng+1], ahf, kbh[1], kbh[3]);
                mma2(sacc[2*ng],   ahf, kbl[0], kbl[2]);
                mma2(sacc[2*ng+1], ahf, kbl[1], kbl[3]);
                mma2(sacc[2*ng],   alf, kbh[0], kbh[2]);
                mma2(sacc[2*ng+1], alf, kbh[1], kbh[3]);
            }
        }

        // ---- scale + mask ----
        const int lc = (lane & 3) * 2;
        #pragma unroll
        for (int gi = 0; gi < 8; gi++) {
            int c0c = s0 + gi * 8 + lc, c1c = c0c + 1;
            int ks0 = kseg[gi * 8 + lc], ks1 = kseg[gi * 8 + lc + 1];
            float v;
            v = sacc[gi][0] * SC; sacc[gi][0] = (c0c <= qp0 && ks0 == qs0) ? v : NEGINF;
            v = sacc[gi][1] * SC; sacc[gi][1] = (c1c <= qp0 && ks1 == qs0) ? v : NEGINF;
            v = sacc[gi][2] * SC; sacc[gi][2] = (c0c <= qp1 && ks0 == qs1) ? v : NEGINF;
            v = sacc[gi][3] * SC; sacc[gi][3] = (c1c <= qp1 && ks1 == qs1) ? v : NEGINF;
        }

        // ---- online softmax ----
        float mx0 = NEGINF, mx1 = NEGINF;
        #pragma unroll
        for (int gi = 0; gi < 8; gi++) {
            mx0 = fmaxf(mx0, fmaxf(sacc[gi][0], sacc[gi][1]));
            mx1 = fmaxf(mx1, fmaxf(sacc[gi][2], sacc[gi][3]));
        }
        mx0 = fmaxf(mx0, __shfl_xor_sync(0xffffffffu, mx0, 1));
        mx0 = fmaxf(mx0, __shfl_xor_sync(0xffffffffu, mx0, 2));
        mx1 = fmaxf(mx1, __shfl_xor_sync(0xffffffffu, mx1, 1));
        mx1 = fmaxf(mx1, __shfl_xor_sync(0xffffffffu, mx1, 2));
        float nm0 = fmaxf(rm0, mx0), nm1 = fmaxf(rm1, mx1);
        float al0 = ex2f(rm0 - nm0), al1 = ex2f(rm1 - nm1);
        rm0 = nm0; rm1 = nm1;
        float sum0 = 0.0f, sum1 = 0.0f;
        #pragma unroll
        for (int gi = 0; gi < 8; gi++) {
            float p;
            p = ex2f(sacc[gi][0] - nm0); sum0 += p; sacc[gi][0] = p;
            p = ex2f(sacc[gi][1] - nm0); sum0 += p; sacc[gi][1] = p;
            p = ex2f(sacc[gi][2] - nm1); sum1 += p; sacc[gi][2] = p;
            p = ex2f(sacc[gi][3] - nm1); sum1 += p; sacc[gi][3] = p;
        }
        rl0 = rl0 * al0 + sum0;
        rl1 = rl1 * al1 + sum1;
        #pragma unroll
        for (int og = 0; og < 16; og++) {
            oacc[og][0] *= al0; oacc[og][1] *= al0;
            oacc[og][2] *= al1; oacc[og][3] *= al1;
        }

        // ---- O += P V (3-term: Ph*Vh + Pl*Vh + Ph*Vl) ----
        #pragma unroll
        for (int kc2 = 0; kc2 < 4; kc2++) {
            uint32_t pa[4], pl[4];
            pa[0] = pack2(sacc[2*kc2][0],   sacc[2*kc2][1],   pl[0]);
            pa[1] = pack2(sacc[2*kc2][2],   sacc[2*kc2][3],   pl[1]);
            pa[2] = pack2(sacc[2*kc2+1][0], sacc[2*kc2+1][1], pl[2]);
            pa[3] = pack2(sacc[2*kc2+1][2], sacc[2*kc2+1][3], pl[3]);
            uint32_t vbase = kst + 34816 + (kc2 * 16 + vb_k) * AT_ST + vb_cb;
            #pragma unroll
            for (int nd = 0; nd < 8; nd++) {
                uint32_t vbh[4], vbl[4];
                ldsm_x4_t(vbh, vbase + nd * 32);
                ldsm_x4_t(vbl, vbase + 17408 + nd * 32);
                mma2(oacc[2*nd],   pa, vbh[0], vbh[1]);
                mma2(oacc[2*nd+1], pa, vbh[2], vbh[3]);
                mma2(oacc[2*nd],   pl, vbh[0], vbh[1]);
                mma2(oacc[2*nd+1], pl, vbh[2], vbh[3]);
                mma2(oacc[2*nd],   pa, vbl[0], vbl[1]);
                mma2(oacc[2*nd+1], pa, vbl[2], vbl[3]);
            }
        }
        __syncthreads();
    }

    // ---- epilogue: normalize, gate, split to bf16 hi/lo ----
    rl0 += __shfl_xor_sync(0xffffffffu, rl0, 1);
    rl0 += __shfl_xor_sync(0xffffffffu, rl0, 2);
    rl1 += __shfl_xor_sync(0xffffffffu, rl1, 1);
    rl1 += __shfl_xor_sync(0xffffffffu, rl1, 2);
    float inv0 = 1.0f / rl0, inv1 = 1.0f / rl1;
    const float L2E = 1.4426950408889634f;
    #pragma unroll
    for (int og = 0; og < 16; og++) {
        int d = og * 8 + (lane & 3) * 2;
        // row 0
        {
            float2 gt = *(const float2*)&qraw[((size_t)(b * T_ + qp0) * H_ + h) * 256 + 128 + d];
            float s0v = 1.0f / (1.0f + ex2f(-gt.x * L2E));
            float s1v = 1.0f / (1.0f + ex2f(-gt.y * L2E));
            float x0 = oacc[og][0] * inv0 * s0v;
            float x1 = oacc[og][1] * inv0 * s1v;
            uint32_t lo; uint32_t hi = pack2(x0, x1, lo);
            size_t o = (size_t)(b * T_ + qp0) * (H_ * KH) + h * KH + d;
            *(uint32_t*)&oh[o] = hi; *(uint32_t*)&ol[o] = lo;
        }
        // row 1
        {
            float2 gt = *(const float2*)&qraw[((size_t)(b * T_ + qp1) * H_ + h) * 256 + 128 + d];
            float s0v = 1.0f / (1.0f + ex2f(-gt.x * L2E));
            float s1v = 1.0f / (1.0f + ex2f(-gt.y * L2E));
            float x0 = oacc[og][2] * inv1 * s0v;
            float x1 = oacc[og][3] * inv1 * s1v;
            uint32_t lo; uint32_t hi = pack2(x0, x1, lo);
            size_t o = (size_t)(b * T_ + qp1) * (H_ * KH) + h * KH + d;
            *(uint32_t*)&oh[o] = hi; *(uint32_t*)&ol[o] = lo;
        }
    }
}

// ---------------- launch -----------------------------------------------------
extern "C" void kernel_launch(void* const* d_in, const int* in_sizes, int n_in,
                              void* d_out, int out_size) {
    const float* hidden = (const float*)d_in[0];
    const float* cosp   = (const float*)d_in[1];
    const float* sinp   = (const float*)d_in[2];
    const int*   seg    = (const int*)d_in[3];
    const float* Wq = (const float*)d_in[5];
    const float* Wk = (const float*)d_in[6];
    const float* Wv = (const float*)d_in[7];
    const float* Wo = (const float*)d_in[8];
    const float* qw = (const float*)d_in[9];
    const float* kw = (const float*)d_in[10];
    float* out = (float*)d_out;

    float *qraw, *kraw, *vraw;
    __nv_bfloat16 *hidh, *hidl, *wqh, *wql, *wkh, *wkl, *wvh, *wvl, *woh, *wol;
    __nv_bfloat16 *qbh, *qbl, *kbh, *kbl, *vbh, *vbl, *aoh, *aol;
    cudaGetSymbolAddress((void**)&qraw, g_qraw);
    cudaGetSymbolAddress((void**)&kraw, g_kraw);
    cudaGetSymbolAddress((void**)&vraw, g_vraw);
    cudaGetSymbolAddress((void**)&hidh, g_hid_h); cudaGetSymbolAddress((void**)&hidl, g_hid_l);
    cudaGetSymbolAddress((void**)&wqh, g_wq_h);   cudaGetSymbolAddress((void**)&wql, g_wq_l);
    cudaGetSymbolAddress((void**)&wkh, g_wk_h);   cudaGetSymbolAddress((void**)&wkl, g_wk_l);
    cudaGetSymbolAddress((void**)&wvh, g_wv_h);   cudaGetSymbolAddress((void**)&wvl, g_wv_l);
    cudaGetSymbolAddress((void**)&woh, g_wo_h);   cudaGetSymbolAddress((void**)&wol, g_wo_l);
    cudaGetSymbolAddress((void**)&qbh, g_qb_h);   cudaGetSymbolAddress((void**)&qbl, g_qb_l);
    cudaGetSymbolAddress((void**)&kbh, g_kb_h);   cudaGetSymbolAddress((void**)&kbl, g_kb_l);
    cudaGetSymbolAddress((void**)&vbh, g_vb_h);   cudaGetSymbolAddress((void**)&vbl, g_vb_l);
    cudaGetSymbolAddress((void**)&aoh, g_ao_h);   cudaGetSymbolAddress((void**)&aol, g_ao_l);

    cudaFuncSetAttribute(gemm_bf3_kernel, cudaFuncAttributeMaxDynamicSharedMemorySize, G_SMEM);
    cudaFuncSetAttribute(attn_tc_kernel,  cudaFuncAttributeMaxDynamicSharedMemorySize, AT_SMEM);

    // 1. split operands to bf16 hi/lo
    split4_kernel<<<(B_*T_*D_) / 1024, 256>>>(hidden, hidh, hidl);
    split4_kernel<<<(D_*H_*2*KH) / 1024, 256>>>(Wq, wqh, wql);
    split4_kernel<<<(D_*G_*KH) / 1024, 256>>>(Wk, wkh, wkl);
    split4_kernel<<<(D_*G_*KH) / 1024, 256>>>(Wv, wvh, wvl);
    split4_kernel<<<(H_*KH*D_) / 1024, 256>>>(Wo, woh, wol);

    // 2. projections
    gemm_bf3_kernel<<<dim3(16, 32), 256, G_SMEM>>>(hidh, hidl, wqh, wql, nullptr, nullptr,
                                                   qraw, nullptr, 4096, 2048, 0);
    gemm_bf3_kernel<<<dim3(4, 32), 256, G_SMEM>>>(hidh, hidl, wkh, wkl, wvh, wvl,
                                                  kraw, vraw, 1024, 2048, 1);

    // 3. rmsnorm + rope -> bf16, V split
    rope_norm_q_kernel<<<B_*T_*H_, 128>>>(qraw, cosp, sinp, qw, qbh, qbl);
    rope_norm_k_kernel<<<B_*T_*G_, 128>>>(kraw, cosp, sinp, kw, kbh, kbl);
    vsplit_kernel<<<(B_*T_*G_*KH/2) / 256, 256>>>(vraw, vbh, vbl);

    // 4. attention (gate fused)
    attn_tc_kernel<<<dim3(T_/128, B_*H_), 256, AT_SMEM>>>(qbh, qbl, kbh, kbl, vbh, vbl,
                                                          qraw, seg, aoh, aol);

    // 5. output projection
    gemm_bf3_kernel<<<dim3(8, 32), 256, G_SMEM>>>(aoh, aol, woh, wol, nullptr, nullptr,
                                                  out, nullptr, 2048, 2048, 0);
}

// round 8
// speedup vs baseline: 3.1223x; 1.0290x over previous
#include <cuda_runtime.h>
#include <cuda_bf16.h>
#include <cstdint>

// Problem constants
#define B_  2
#define T_  2048
#define D_  2048
#define H_  16
#define G_  4
#define KH  128
#define EPS 1e-6f
static const float SCALE = 0.088388347648318447f; // 128^-0.5

// ---------------- scratch (device globals) -----------------------------------
__device__ float g_qraw[B_*T_*H_*2*KH];       // [bt][h*256+..] fp32 (gate kept here)
__device__ float g_kraw[B_*T_*G_*KH];
// bf16 hi/lo splits
__device__ __nv_bfloat16 g_hid_h[B_*T_*D_],  g_hid_l[B_*T_*D_];
__device__ __nv_bfloat16 g_wq_h[D_*H_*2*KH], g_wq_l[D_*H_*2*KH];
__device__ __nv_bfloat16 g_wk_h[D_*G_*KH],   g_wk_l[D_*G_*KH];
__device__ __nv_bfloat16 g_wv_h[D_*G_*KH],   g_wv_l[D_*G_*KH];
__device__ __nv_bfloat16 g_wo_h[H_*KH*D_],   g_wo_l[H_*KH*D_];
__device__ __nv_bfloat16 g_qb_h[B_*H_*T_*KH], g_qb_l[B_*H_*T_*KH];  // [b,h,t,d]
__device__ __nv_bfloat16 g_kb_h[B_*G_*T_*KH], g_kb_l[B_*G_*T_*KH];  // [b,g,t,d]
__device__ __nv_bfloat16 g_vb_h[B_*G_*T_*KH], g_vb_l[B_*G_*T_*KH];
__device__ __nv_bfloat16 g_ao_h[B_*T_*H_*KH], g_ao_l[B_*T_*H_*KH]; // gated attn

// ============================ helpers ========================================
__device__ __forceinline__ uint32_t smem_u32(const void* p) {
    return (uint32_t)__cvta_generic_to_shared((void*)p);
}
__device__ __forceinline__ void ldsm_x4(uint32_t* r, uint32_t addr) {
    asm volatile("ldmatrix.sync.aligned.m8n8.x4.shared.b16 {%0,%1,%2,%3}, [%4];"
        : "=r"(r[0]), "=r"(r[1]), "=r"(r[2]), "=r"(r[3]) : "r"(addr));
}
__device__ __forceinline__ void ldsm_x4_t(uint32_t* r, uint32_t addr) {
    asm volatile("ldmatrix.sync.aligned.m8n8.x4.trans.shared.b16 {%0,%1,%2,%3}, [%4];"
        : "=r"(r[0]), "=r"(r[1]), "=r"(r[2]), "=r"(r[3]) : "r"(addr));
}
__device__ __forceinline__ void mma2(float* d, const uint32_t* a, uint32_t b0, uint32_t b1) {
    asm volatile("mma.sync.aligned.m16n8k16.row.col.f32.bf16.bf16.f32 "
        "{%0,%1,%2,%3}, {%4,%5,%6,%7}, {%8,%9}, {%0,%1,%2,%3};"
        : "+f"(d[0]), "+f"(d[1]), "+f"(d[2]), "+f"(d[3])
        : "r"(a[0]), "r"(a[1]), "r"(a[2]), "r"(a[3]), "r"(b0), "r"(b1));
}
__device__ __forceinline__ void cpa16(uint32_t s, const void* g) {
    asm volatile("cp.async.cg.shared.global [%0], [%1], 16;" :: "r"(s), "l"(g));
}
__device__ __forceinline__ void cpa_commit() { asm volatile("cp.async.commit_group;"); }
template<int N> __device__ __forceinline__ void cpa_wait() {
    asm volatile("cp.async.wait_group %0;" :: "n"(N));
}
__device__ __forceinline__ float ex2f(float x) {
    float y; asm("ex2.approx.ftz.f32 %0, %1;" : "=f"(y) : "f"(x)); return y;
}
__device__ __forceinline__ uint32_t pack2(float a, float b, uint32_t& lo) {
    __nv_bfloat16 ha = __float2bfloat16_rn(a);
    __nv_bfloat16 hb = __float2bfloat16_rn(b);
    __nv_bfloat162 hp; hp.x = ha; hp.y = hb;
    __nv_bfloat162 lp = __floats2bfloat162_rn(a - __bfloat162float(ha),
                                              b - __bfloat162float(hb));
    lo = *reinterpret_cast<uint32_t*>(&lp);
    return *reinterpret_cast<uint32_t*>(&hp);
}

// ---------------- split fp32 -> bf16 hi/lo -----------------------------------
__global__ __launch_bounds__(256)
void split4_kernel(const float* __restrict__ in, __nv_bfloat16* __restrict__ hi,
                   __nv_bfloat16* __restrict__ lo) {
    size_t i = ((size_t)blockIdx.x * 256 + threadIdx.x) * 4;
    float4 v = *(const float4*)(in + i);
    uint32_t l0, l1;
    uint32_t h0 = pack2(v.x, v.y, l0);
    uint32_t h1 = pack2(v.z, v.w, l1);
    *(uint32_t*)(hi + i) = h0; *(uint32_t*)(hi + i + 2) = h1;
    *(uint32_t*)(lo + i) = l0; *(uint32_t*)(lo + i + 2) = l1;
}

// ================= GEMM: C[M,N] = A @ B, 3-term bf16 split ===================
// CTA 128x256, BK=64, 256 thr, 8 warps x (64x64), 2-stage cp.async.
// qkv mode: n-tiles 0-15 -> Wq (fp32 out), 16-17 -> Wk (fp32), 18-19 -> Wv
// (bf16 hi/lo out with [b,g,t,d] remap).
#define GA_ST 144
#define GB_ST 528
#define G_AH 0
#define G_AL 18432
#define G_BH 36864
#define G_BL 70656
#define G_STAGE 104448
#define G_SMEM 208896

__global__ __launch_bounds__(256, 1)
void gemm_bf3_kernel(const __nv_bfloat16* __restrict__ Ah, const __nv_bfloat16* __restrict__ Al,
                     const __nv_bfloat16* __restrict__ Bh0, const __nv_bfloat16* __restrict__ Bl0,
                     const __nv_bfloat16* __restrict__ Bkh, const __nv_bfloat16* __restrict__ Bkl,
                     const __nv_bfloat16* __restrict__ Bvh, const __nv_bfloat16* __restrict__ Bvl,
                     float* __restrict__ Cq, float* __restrict__ Ck,
                     __nv_bfloat16* __restrict__ Voh, __nv_bfloat16* __restrict__ Vol,
                     int N0, int Kd, int qkv) {
    extern __shared__ char sg[];
    uint32_t smb = smem_u32(sg);
    const int tid = threadIdx.x, wid = tid >> 5, lane = tid & 31;
    const int m0 = blockIdx.y * 128;
    const int x = blockIdx.x;

    const __nv_bfloat16 *bh, *bl;
    float* c = nullptr;
    int bst, n0, isV = 0;
    if (!qkv) { bh = Bh0; bl = Bl0; bst = N0; n0 = x * 256; c = Cq; }
    else if (x < 16) { bh = Bh0; bl = Bl0; bst = 4096; n0 = x * 256; c = Cq; }
    else if (x < 18) { bh = Bkh; bl = Bkl; bst = 512; n0 = (x - 16) * 256; c = Ck; }
    else            { bh = Bvh; bl = Bvl; bst = 512; n0 = (x - 18) * 256; isV = 1; }

    const int wm = (wid & 1) * 64, wn = (wid >> 1) * 64;

    float acc[4][8][4];
    #pragma unroll
    for (int i = 0; i < 4; i++)
        #pragma unroll
        for (int j = 0; j < 8; j++)
            #pragma unroll
            for (int e = 0; e < 4; e++) acc[i][j][e] = 0.0f;

    const int NC = Kd >> 6;

    #define G_ISSUE(ch) do { \
        int _s = (ch) & 1; int _k0 = (ch) << 6; \
        uint32_t _st = smb + _s * G_STAGE; \
        _Pragma("unroll") \
        for (int _j = 0; _j < 4; _j++) { \
            int _i = tid + 256 * _j; int _r = _i >> 3, _cc = _i & 7; \
            size_t _go = (size_t)(m0 + _r) * Kd + _k0 + _cc * 8; \
            cpa16(_st + G_AH + _r * GA_ST + _cc * 16, Ah + _go); \
            cpa16(_st + G_AL + _r * GA_ST + _cc * 16, Al + _go); \
        } \
        _Pragma("unroll") \
        for (int _j = 0; _j < 8; _j++) { \
            int _i = tid + 256 * _j; int _r = _i >> 5, _cc = _i & 31; \
            size_t _go = (size_t)(_k0 + _r) * bst + n0 + _cc * 8; \
            cpa16(_st + G_BH + _r * GB_ST + _cc * 16, bh + _go); \
            cpa16(_st + G_BL + _r * GB_ST + _cc * 16, bl + _go); \
        } \
        cpa_commit(); \
    } while (0)

    G_ISSUE(0);

    const int a_r = lane & 15;
    const int a_cb = (lane >> 4) * 16;
    const int b_k = (((lane >> 3) & 1) << 3) + (lane & 7);
    const int b_cb = ((lane >> 3) & 2) ? 16 : 0;

    for (int ch = 0; ch < NC; ch++) {
        if (ch + 1 < NC) { G_ISSUE(ch + 1); cpa_wait<1>(); }
        else cpa_wait<0>();
        __syncthreads();
        uint32_t st = smb + (ch & 1) * G_STAGE;
        uint32_t aHb = st + G_AH + (wm + a_r) * GA_ST + a_cb;
        uint32_t aLb = st + G_AL + (wm + a_r) * GA_ST + a_cb;
        uint32_t bHb = st + G_BH + b_k * GB_ST + wn * 2 + b_cb;
        uint32_t bLb = st + G_BL + b_k * GB_ST + wn * 2 + b_cb;

        #pragma unroll
        for (int kc = 0; kc < 4; kc++) {
            uint32_t ah[4][4], al[4][4];
            #pragma unroll
            for (int mi = 0; mi < 4; mi++) {
                ldsm_x4(ah[mi], aHb + mi * (16 * GA_ST) + kc * 32);
                ldsm_x4(al[mi], aLb + mi * (16 * GA_ST) + kc * 32);
            }
            #pragma unroll
            for (int bj = 0; bj < 4; bj++) {
                uint32_t bhf[4], blf[4];
                ldsm_x4_t(bhf, bHb + kc * (16 * GB_ST) + bj * 32);
                ldsm_x4_t(blf, bLb + kc * (16 * GB_ST) + bj * 32);
                #pragma unroll
                for (int mi = 0; mi < 4; mi++) {
                    mma2(acc[mi][2*bj],   ah[mi], bhf[0], bhf[1]);
                    mma2(acc[mi][2*bj+1], ah[mi], bhf[2], bhf[3]);
                    mma2(acc[mi][2*bj],   ah[mi], blf[0], blf[1]);
                    mma2(acc[mi][2*bj+1], ah[mi], blf[2], blf[3]);
                    mma2(acc[mi][2*bj],   al[mi], bhf[0], bhf[1]);
                    mma2(acc[mi][2*bj+1], al[mi], bhf[2], bhf[3]);
                }
            }
        }
        __syncthreads();
    }

    const int r0 = m0 + wm + (lane >> 2);
    const int c0 = n0 + wn + (lane & 3) * 2;
    if (!isV) {
        #pragma unroll
        for (int mi = 0; mi < 4; mi++) {
            #pragma unroll
            for (int nj = 0; nj < 8; nj++) {
                float2 lo2; lo2.x = acc[mi][nj][0]; lo2.y = acc[mi][nj][1];
                float2 hi2; hi2.x = acc[mi][nj][2]; hi2.y = acc[mi][nj][3];
                *(float2*)&c[(size_t)(r0 + mi * 16) * bst + c0 + nj * 8] = lo2;
                *(float2*)&c[(size_t)(r0 + mi * 16 + 8) * bst + c0 + nj * 8] = hi2;
            }
        }
    } else {
        // V: fused bf16 hi/lo split + [b,g,t,d] remap
        #pragma unroll
        for (int mi = 0; mi < 4; mi++) {
            #pragma unroll
            for (int nj = 0; nj < 8; nj++) {
                int cg = c0 + nj * 8;
                int g = cg >> 7, d = cg & 127;
                #pragma unroll
                for (int half = 0; half < 2; half++) {
                    int r = r0 + mi * 16 + half * 8;
                    int b = r >> 11, t = r & 2047;
                    uint32_t lo;
                    uint32_t hi = pack2(acc[mi][nj][half*2], acc[mi][nj][half*2+1], lo);
                    size_t o = ((size_t)(b * G_ + g) * T_ + t) * KH + d;
                    *(uint32_t*)&Voh[o] = hi;
                    *(uint32_t*)&Vol[o] = lo;
                }
            }
        }
    }
}

// ---------------- RMSNorm + RoPE -> bf16 hi/lo (Q) ---------------------------
__global__ __launch_bounds__(128)
void rope_norm_q_kernel(const float* __restrict__ qraw, const float* __restrict__ cosp,
                        const float* __restrict__ sinp, const float* __restrict__ w,
                        __nv_bfloat16* __restrict__ outh, __nv_bfloat16* __restrict__ outl) {
    const int idx = blockIdx.x;           // bt*H + h
    const int bt = idx >> 4, h = idx & 15;
    const int b = bt >> 11, t = bt & 2047;
    const int d = threadIdx.x;
    float x = qraw[(size_t)idx * 256 + d];
    float ss = x * x;
    #pragma unroll
    for (int o = 16; o; o >>= 1) ss += __shfl_xor_sync(0xffffffffu, ss, o);
    __shared__ float wsum[4];
    __shared__ float sn[128];
    if ((d & 31) == 0) wsum[d >> 5] = ss;
    __syncthreads();
    float tot = wsum[0] + wsum[1] + wsum[2] + wsum[3];
    float r = rsqrtf(tot * (1.0f / 128.0f) + EPS);
    sn[d] = x * r * w[d];
    __syncthreads();
    float c = cosp[(size_t)bt * KH + d];
    float s = sinp[(size_t)bt * KH + d];
    float out = (d < 64) ? sn[d] * c - sn[d + 64] * s : sn[d] * c + sn[d - 64] * s;
    size_t o = ((size_t)(b * H_ + h) * T_ + t) * KH + d;
    __nv_bfloat16 hv = __float2bfloat16_rn(out);
    outh[o] = hv;
    outl[o] = __float2bfloat16_rn(out - __bfloat162float(hv));
}

__global__ __launch_bounds__(128)
void rope_norm_k_kernel(const float* __restrict__ kraw, const float* __restrict__ cosp,
                        const float* __restrict__ sinp, const float* __restrict__ w,
                        __nv_bfloat16* __restrict__ outh, __nv_bfloat16* __restrict__ outl) {
    const int idx = blockIdx.x;           // bt*G + g
    const int bt = idx >> 2, g = idx & 3;
    const int b = bt >> 11, t = bt & 2047;
    const int d = threadIdx.x;
    float x = kraw[(size_t)idx * 128 + d];
    float ss = x * x;
    #pragma unroll
    for (int o = 16; o; o >>= 1) ss += __shfl_xor_sync(0xffffffffu, ss, o);
    __shared__ float wsum[4];
    __shared__ float sn[128];
    if ((d & 31) == 0) wsum[d >> 5] = ss;
    __syncthreads();
    float tot = wsum[0] + wsum[1] + wsum[2] + wsum[3];
    float r = rsqrtf(tot * (1.0f / 128.0f) + EPS);
    sn[d] = x * r * w[d];
    __syncthreads();
    float c = cosp[(size_t)bt * KH + d];
    float s = sinp[(size_t)bt * KH + d];
    float out = (d < 64) ? sn[d] * c - sn[d + 64] * s : sn[d] * c + sn[d - 64] * s;
    size_t o = ((size_t)(b * G_ + g) * T_ + t) * KH + d;
    __nv_bfloat16 hv = __float2bfloat16_rn(out);
    outh[o] = hv;
    outl[o] = __float2bfloat16_rn(out - __bfloat162float(hv));
}

// ================= tensor-core flash attention ===============================
// CTA: 128 q-rows, key tiles of 64, 256 threads (8 warps x 16 rows).
#define AT_ST 272
#define AT_KV 69632             // after Qhi/Qlo (2*128*272)
#define AT_KVSTG 69632          // per stage: Khi,Klo,Vhi,Vlo each 64*272
#define AT_SEG 208896
#define AT_SMEM 209408

__global__ __launch_bounds__(256, 1)
void attn_tc_kernel(const __nv_bfloat16* __restrict__ qh, const __nv_bfloat16* __restrict__ ql,
                    const __nv_bfloat16* __restrict__ kh, const __nv_bfloat16* __restrict__ kl,
                    const __nv_bfloat16* __restrict__ vh, const __nv_bfloat16* __restrict__ vl,
                    const float* __restrict__ qraw, const int* __restrict__ seg,
                    __nv_bfloat16* __restrict__ oh, __nv_bfloat16* __restrict__ ol) {
    extern __shared__ char sa[];
    uint32_t smb = smem_u32(sa);
    const int tid = threadIdx.x, wid = tid >> 5, lane = tid & 31;
    const int qt = (int)(gridDim.x - 1 - blockIdx.x);   // heavy tiles first
    const int q0 = qt * 128;
    const int bh_ = blockIdx.y;
    const int b = bh_ >> 4, h = bh_ & 15;
    const int g = h >> 2;
    const int wm = wid * 16;

    const __nv_bfloat16* qhb = qh + ((size_t)(b * H_ + h) * T_ + q0) * KH;
    const __nv_bfloat16* qlb = ql + ((size_t)(b * H_ + h) * T_ + q0) * KH;
    const __nv_bfloat16* khb = kh + (size_t)(b * G_ + g) * T_ * KH;
    const __nv_bfloat16* klb = kl + (size_t)(b * G_ + g) * T_ * KH;
    const __nv_bfloat16* vhb = vh + (size_t)(b * G_ + g) * T_ * KH;
    const __nv_bfloat16* vlb = vl + (size_t)(b * G_ + g) * T_ * KH;

    // Q prologue loads
    #pragma unroll
    for (int j = 0; j < 8; j++) {
        int i = tid + 256 * j; int r = i >> 4, cc = i & 15;
        cpa16(smb + r * AT_ST + cc * 16, qhb + (size_t)r * KH + cc * 8);
        cpa16(smb + 34816 + r * AT_ST + cc * 16, qlb + (size_t)r * KH + cc * 8);
    }

    const int nT = (q0 + 128) / 64;

    #define AT_ISSUE(t) do { \
        int _s = (t) & 1; int _s0 = (t) * 64; \
        uint32_t _bs = smb + AT_KV + _s * AT_KVSTG; \
        _Pragma("unroll") \
        for (int _j = 0; _j < 4; _j++) { \
            int _i = tid + 256 * _j; int _r = _i >> 4, _cc = _i & 15; \
            size_t _go = (size_t)(_s0 + _r) * KH + _cc * 8; \
            cpa16(_bs + _r * AT_ST + _cc * 16, khb + _go); \
            cpa16(_bs + 17408 + _r * AT_ST + _cc * 16, klb + _go); \
            cpa16(_bs + 34816 + _r * AT_ST + _cc * 16, vhb + _go); \
            cpa16(_bs + 52224 + _r * AT_ST + _cc * 16, vlb + _go); \
        } \
        if (tid < 16) cpa16(smb + AT_SEG + _s * 256 + tid * 16, seg + (size_t)b * T_ + _s0 + tid * 4); \
        cpa_commit(); \
    } while (0)

    AT_ISSUE(0);

    const int qp0 = q0 + wm + (lane >> 2), qp1 = qp0 + 8;
    const int qs0 = seg[(size_t)b * T_ + qp0];
    const int qs1 = seg[(size_t)b * T_ + qp1];

    float rm0 = -1e30f, rm1 = -1e30f, rl0 = 0.0f, rl1 = 0.0f;
    float oacc[16][4];
    #pragma unroll
    for (int i = 0; i < 16; i++)
        #pragma unroll
        for (int e = 0; e < 4; e++) oacc[i][e] = 0.0f;

    const uint32_t aQh = smb + (wm + (lane & 15)) * AT_ST + (lane >> 4) * 16;
    const uint32_t aQl = aQh + 34816;
    const int vb_k = (((lane >> 3) & 1) << 3) + (lane & 7);
    const int vb_cb = ((lane >> 3) & 2) ? 16 : 0;
    const float SC = SCALE * 1.4426950408889634f;
    const float NEGINF = -__int_as_float(0x7f800000);

    for (int t = 0; t < nT; t++) {
        if (t + 1 < nT) { AT_ISSUE(t + 1); cpa_wait<1>(); }
        else cpa_wait<0>();
        __syncthreads();
        const int s0 = t * 64;
        uint32_t kst = smb + AT_KV + (t & 1) * AT_KVSTG;
        const int* kseg = (const int*)(sa + AT_SEG + (t & 1) * 256);

        // ---- S = Q K^T (3-term) ----
        float sacc[8][4];
        #pragma unroll
        for (int i = 0; i < 8; i++)
            #pragma unroll
            for (int e = 0; e < 4; e++) sacc[i][e] = 0.0f;

        #pragma unroll
        for (int kc = 0; kc < 8; kc++) {
            uint32_t ahf[4], alf[4];
            ldsm_x4(ahf, aQh + kc * 32);
            ldsm_x4(alf, aQl + kc * 32);
            #pragma unroll
            for (int ng = 0; ng < 4; ng++) {
                uint32_t kbh[4], kbl[4];
                uint32_t ka = kst + (ng * 16 + (lane & 15)) * AT_ST + (lane >> 4) * 16 + kc * 32;
                ldsm_x4(kbh, ka);
                ldsm_x4(kbl, ka + 17408);
                mma2(sacc[2*ng],   ahf, kbh[0], kbh[2]);
                mma2(sacc[2*ng+1], ahf, kbh[1], kbh[3]);
                mma2(sacc[2*ng],   ahf, kbl[0], kbl[2]);
                mma2(sacc[2*ng+1], ahf, kbl[1], kbl[3]);
                mma2(sacc[2*ng],   alf, kbh[0], kbh[2]);
                mma2(sacc[2*ng+1], alf, kbh[1], kbh[3]);
            }
        }

        // ---- scale + mask ----
        const int lc = (lane & 3) * 2;
        #pragma unroll
        for (int gi = 0; gi < 8; gi++) {
            int c0c = s0 + gi * 8 + lc, c1c = c0c + 1;
            int ks0 = kseg[gi * 8 + lc], ks1 = kseg[gi * 8 + lc + 1];
            float v;
            v = sacc[gi][0] * SC; sacc[gi][0] = (c0c <= qp0 && ks0 == qs0) ? v : NEGINF;
            v = sacc[gi][1] * SC; sacc[gi][1] = (c1c <= qp0 && ks1 == qs0) ? v : NEGINF;
            v = sacc[gi][2] * SC; sacc[gi][2] = (c0c <= qp1 && ks0 == qs1) ? v : NEGINF;
            v = sacc[gi][3] * SC; sacc[gi][3] = (c1c <= qp1 && ks1 == qs1) ? v : NEGINF;
        }

        // ---- online softmax ----
        float mx0 = NEGINF, mx1 = NEGINF;
        #pragma unroll
        for (int gi = 0; gi < 8; gi++) {
            mx0 = fmaxf(mx0, fmaxf(sacc[gi][0], sacc[gi][1]));
            mx1 = fmaxf(mx1, fmaxf(sacc[gi][2], sacc[gi][3]));
        }
        mx0 = fmaxf(mx0, __shfl_xor_sync(0xffffffffu, mx0, 1));
        mx0 = fmaxf(mx0, __shfl_xor_sync(0xffffffffu, mx0, 2));
        mx1 = fmaxf(mx1, __shfl_xor_sync(0xffffffffu, mx1, 1));
        mx1 = fmaxf(mx1, __shfl_xor_sync(0xffffffffu, mx1, 2));
        float nm0 = fmaxf(rm0, mx0), nm1 = fmaxf(rm1, mx1);
        float al0 = ex2f(rm0 - nm0), al1 = ex2f(rm1 - nm1);
        rm0 = nm0; rm1 = nm1;
        float sum0 = 0.0f, sum1 = 0.0f;
        #pragma unroll
        for (int gi = 0; gi < 8; gi++) {
            float p;
            p = ex2f(sacc[gi][0] - nm0); sum0 += p; sacc[gi][0] = p;
            p = ex2f(sacc[gi][1] - nm0); sum0 += p; sacc[gi][1] = p;
            p = ex2f(sacc[gi][2] - nm1); sum1 += p; sacc[gi][2] = p;
            p = ex2f(sacc[gi][3] - nm1); sum1 += p; sacc[gi][3] = p;
        }
        rl0 = rl0 * al0 + sum0;
        rl1 = rl1 * al1 + sum1;
        #pragma unroll
        for (int og = 0; og < 16; og++) {
            oacc[og][0] *= al0; oacc[og][1] *= al0;
            oacc[og][2] *= al1; oacc[og][3] *= al1;
        }

        // ---- O += P V (3-term: Ph*Vh + Pl*Vh + Ph*Vl) ----
        #pragma unroll
        for (int kc2 = 0; kc2 < 4; kc2++) {
            uint32_t pa[4], pl[4];
            pa[0] = pack2(sacc[2*kc2][0],   sacc[2*kc2][1],   pl[0]);
            pa[1] = pack2(sacc[2*kc2][2],   sacc[2*kc2][3],   pl[1]);
            pa[2] = pack2(sacc[2*kc2+1][0], sacc[2*kc2+1][1], pl[2]);
            pa[3] = pack2(sacc[2*kc2+1][2], sacc[2*kc2+1][3], pl[3]);
            uint32_t vbase = kst + 34816 + (kc2 * 16 + vb_k) * AT_ST + vb_cb;
            #pragma unroll
            for (int nd = 0; nd < 8; nd++) {
                uint32_t vbh[4], vbl[4];
                ldsm_x4_t(vbh, vbase + nd * 32);
                ldsm_x4_t(vbl, vbase + 17408 + nd * 32);
                mma2(oacc[2*nd],   pa, vbh[0], vbh[1]);
                mma2(oacc[2*nd+1], pa, vbh[2], vbh[3]);
                mma2(oacc[2*nd],   pl, vbh[0], vbh[1]);
                mma2(oacc[2*nd+1], pl, vbh[2], vbh[3]);
                mma2(oacc[2*nd],   pa, vbl[0], vbl[1]);
                mma2(oacc[2*nd+1], pa, vbl[2], vbl[3]);
            }
        }
        __syncthreads();
    }

    // ---- epilogue: normalize, gate, split to bf16 hi/lo ----
    rl0 += __shfl_xor_sync(0xffffffffu, rl0, 1);
    rl0 += __shfl_xor_sync(0xffffffffu, rl0, 2);
    rl1 += __shfl_xor_sync(0xffffffffu, rl1, 1);
    rl1 += __shfl_xor_sync(0xffffffffu, rl1, 2);
    float inv0 = 1.0f / rl0, inv1 = 1.0f / rl1;
    const float L2E = 1.4426950408889634f;
    #pragma unroll
    for (int og = 0; og < 16; og++) {
        int d = og * 8 + (lane & 3) * 2;
        // row 0
        {
            float2 gt = *(const float2*)&qraw[((size_t)(b * T_ + qp0) * H_ + h) * 256 + 128 + d];
            float s0v = 1.0f / (1.0f + ex2f(-gt.x * L2E));
            float s1v = 1.0f / (1.0f + ex2f(-gt.y * L2E));
            float x0 = oacc[og][0] * inv0 * s0v;
            float x1 = oacc[og][1] * inv0 * s1v;
            uint32_t lo; uint32_t hi = pack2(x0, x1, lo);
            size_t o = (size_t)(b * T_ + qp0) * (H_ * KH) + h * KH + d;
            *(uint32_t*)&oh[o] = hi; *(uint32_t*)&ol[o] = lo;
        }
        // row 1
        {
            float2 gt = *(const float2*)&qraw[((size_t)(b * T_ + qp1) * H_ + h) * 256 + 128 + d];
            float s0v = 1.0f / (1.0f + ex2f(-gt.x * L2E));
            float s1v = 1.0f / (1.0f + ex2f(-gt.y * L2E));
            float x0 = oacc[og][2] * inv1 * s0v;
            float x1 = oacc[og][3] * inv1 * s1v;
            uint32_t lo; uint32_t hi = pack2(x0, x1, lo);
            size_t o = (size_t)(b * T_ + qp1) * (H_ * KH) + h * KH + d;
            *(uint32_t*)&oh[o] = hi; *(uint32_t*)&ol[o] = lo;
        }
    }
}

// ---------------- launch -----------------------------------------------------
extern "C" void kernel_launch(void* const* d_in, const int* in_sizes, int n_in,
                              void* d_out, int out_size) {
    const float* hidden = (const float*)d_in[0];
    const float* cosp   = (const float*)d_in[1];
    const float* sinp   = (const float*)d_in[2];
    const int*   seg    = (const int*)d_in[3];
    const float* Wq = (const float*)d_in[5];
    const float* Wk = (const float*)d_in[6];
    const float* Wv = (const float*)d_in[7];
    const float* Wo = (const float*)d_in[8];
    const float* qw = (const float*)d_in[9];
    const float* kw = (const float*)d_in[10];
    float* out = (float*)d_out;

    float *qraw, *kraw;
    __nv_bfloat16 *hidh, *hidl, *wqh, *wql, *wkh, *wkl, *wvh, *wvl, *woh, *wol;
    __nv_bfloat16 *qbh, *qbl, *kbh, *kbl, *vbh, *vbl, *aoh, *aol;
    cudaGetSymbolAddress((void**)&qraw, g_qraw);
    cudaGetSymbolAddress((void**)&kraw, g_kraw);
    cudaGetSymbolAddress((void**)&hidh, g_hid_h); cudaGetSymbolAddress((void**)&hidl, g_hid_l);
    cudaGetSymbolAddress((void**)&wqh, g_wq_h);   cudaGetSymbolAddress((void**)&wql, g_wq_l);
    cudaGetSymbolAddress((void**)&wkh, g_wk_h);   cudaGetSymbolAddress((void**)&wkl, g_wk_l);
    cudaGetSymbolAddress((void**)&wvh, g_wv_h);   cudaGetSymbolAddress((void**)&wvl, g_wv_l);
    cudaGetSymbolAddress((void**)&woh, g_wo_h);   cudaGetSymbolAddress((void**)&wol, g_wo_l);
    cudaGetSymbolAddress((void**)&qbh, g_qb_h);   cudaGetSymbolAddress((void**)&qbl, g_qb_l);
    cudaGetSymbolAddress((void**)&kbh, g_kb_h);   cudaGetSymbolAddress((void**)&kbl, g_kb_l);
    cudaGetSymbolAddress((void**)&vbh, g_vb_h);   cudaGetSymbolAddress((void**)&vbl, g_vb_l);
    cudaGetSymbolAddress((void**)&aoh, g_ao_h);   cudaGetSymbolAddress((void**)&aol, g_ao_l);

    cudaFuncSetAttribute(gemm_bf3_kernel, cudaFuncAttributeMaxDynamicSharedMemorySize, G_SMEM);
    cudaFuncSetAttribute(attn_tc_kernel,  cudaFuncAttributeMaxDynamicSharedMemorySize, AT_SMEM);

    // 1. split operands to bf16 hi/lo
    split4_kernel<<<(B_*T_*D_) / 1024, 256>>>(hidden, hidh, hidl);
    split4_kernel<<<(D_*H_*2*KH) / 1024, 256>>>(Wq, wqh, wql);
    split4_kernel<<<(D_*G_*KH) / 1024, 256>>>(Wk, wkh, wkl);
    split4_kernel<<<(D_*G_*KH) / 1024, 256>>>(Wv, wvh, wvl);
    split4_kernel<<<(H_*KH*D_) / 1024, 256>>>(Wo, woh, wol);

    // 2. merged Q/K/V projection (V written directly as bf16 hi/lo [b,g,t,d])
    gemm_bf3_kernel<<<dim3(20, 32), 256, G_SMEM>>>(hidh, hidl, wqh, wql, wkh, wkl,
                                                   wvh, wvl, qraw, kraw, vbh, vbl,
                                                   0, 2048, 1);

    // 3. rmsnorm + rope -> bf16 hi/lo
    rope_norm_q_kernel<<<B_*T_*H_, 128>>>(qraw, cosp, sinp, qw, qbh, qbl);
    rope_norm_k_kernel<<<B_*T_*G_, 128>>>(kraw, cosp, sinp, kw, kbh, kbl);

    // 4. attention (gate fused)
    attn_tc_kernel<<<dim3(T_/128, B_*H_), 256, AT_SMEM>>>(qbh, qbl, kbh, kbl, vbh, vbl,
                                                          qraw, seg, aoh, aol);

    // 5. output projection
    gemm_bf3_kernel<<<dim3(8, 32), 256, G_SMEM>>>(aoh, aol, woh, wol, nullptr, nullptr,
                                                  nullptr, nullptr, out, nullptr,
                                                  nullptr, nullptr, 2048, 2048, 0);
}

// round 9
// speedup vs baseline: 3.1705x; 1.0154x over previous
#include <cuda_runtime.h>
#include <cuda_bf16.h>
#include <cstdint>

// Problem constants
#define B_  2
#define T_  2048
#define D_  2048
#define H_  16
#define G_  4
#define KH  128
#define EPS 1e-6f
static const float SCALE = 0.088388347648318447f; // 128^-0.5

// ---------------- scratch (device globals) -----------------------------------
__device__ float g_qraw[B_*T_*H_*2*KH];       // [bt][h*256+..] fp32 (gate kept here)
__device__ float g_kraw[B_*T_*G_*KH];
// bf16 hi/lo splits
__device__ __nv_bfloat16 g_hid_h[B_*T_*D_],  g_hid_l[B_*T_*D_];
__device__ __nv_bfloat16 g_wq_h[D_*H_*2*KH], g_wq_l[D_*H_*2*KH];
__device__ __nv_bfloat16 g_wk_h[D_*G_*KH],   g_wk_l[D_*G_*KH];
__device__ __nv_bfloat16 g_wv_h[D_*G_*KH],   g_wv_l[D_*G_*KH];
__device__ __nv_bfloat16 g_wo_h[H_*KH*D_],   g_wo_l[H_*KH*D_];
__device__ __nv_bfloat16 g_qb_h[B_*H_*T_*KH], g_qb_l[B_*H_*T_*KH];  // [b,h,t,d]
__device__ __nv_bfloat16 g_kb_h[B_*G_*T_*KH], g_kb_l[B_*G_*T_*KH];  // [b,g,t,d]
__device__ __nv_bfloat16 g_vb_h[B_*G_*T_*KH], g_vb_l[B_*G_*T_*KH];
__device__ __nv_bfloat16 g_ao_h[B_*T_*H_*KH], g_ao_l[B_*T_*H_*KH]; // gated attn

// ============================ helpers ========================================
__device__ __forceinline__ uint32_t smem_u32(const void* p) {
    return (uint32_t)__cvta_generic_to_shared((void*)p);
}
__device__ __forceinline__ void ldsm_x4(uint32_t* r, uint32_t addr) {
    asm volatile("ldmatrix.sync.aligned.m8n8.x4.shared.b16 {%0,%1,%2,%3}, [%4];"
        : "=r"(r[0]), "=r"(r[1]), "=r"(r[2]), "=r"(r[3]) : "r"(addr));
}
__device__ __forceinline__ void ldsm_x4_t(uint32_t* r, uint32_t addr) {
    asm volatile("ldmatrix.sync.aligned.m8n8.x4.trans.shared.b16 {%0,%1,%2,%3}, [%4];"
        : "=r"(r[0]), "=r"(r[1]), "=r"(r[2]), "=r"(r[3]) : "r"(addr));
}
__device__ __forceinline__ void mma2(float* d, const uint32_t* a, uint32_t b0, uint32_t b1) {
    asm volatile("mma.sync.aligned.m16n8k16.row.col.f32.bf16.bf16.f32 "
        "{%0,%1,%2,%3}, {%4,%5,%6,%7}, {%8,%9}, {%0,%1,%2,%3};"
        : "+f"(d[0]), "+f"(d[1]), "+f"(d[2]), "+f"(d[3])
        : "r"(a[0]), "r"(a[1]), "r"(a[2]), "r"(a[3]), "r"(b0), "r"(b1));
}
__device__ __forceinline__ void cpa16(uint32_t s, const void* g) {
    asm volatile("cp.async.cg.shared.global [%0], [%1], 16;" :: "r"(s), "l"(g));
}
__device__ __forceinline__ void cpa_commit() { asm volatile("cp.async.commit_group;"); }
template<int N> __device__ __forceinline__ void cpa_wait() {
    asm volatile("cp.async.wait_group %0;" :: "n"(N));
}
__device__ __forceinline__ float ex2f(float x) {
    float y; asm("ex2.approx.ftz.f32 %0, %1;" : "=f"(y) : "f"(x)); return y;
}
__device__ __forceinline__ uint32_t pack2(float a, float b, uint32_t& lo) {
    __nv_bfloat16 ha = __float2bfloat16_rn(a);
    __nv_bfloat16 hb = __float2bfloat16_rn(b);
    __nv_bfloat162 hp; hp.x = ha; hp.y = hb;
    __nv_bfloat162 lp = __floats2bfloat162_rn(a - __bfloat162float(ha),
                                              b - __bfloat162float(hb));
    lo = *reinterpret_cast<uint32_t*>(&lp);
    return *reinterpret_cast<uint32_t*>(&hp);
}

// ---------------- split fp32 -> bf16 hi/lo -----------------------------------
__global__ __launch_bounds__(256)
void split4_kernel(const float* __restrict__ in, __nv_bfloat16* __restrict__ hi,
                   __nv_bfloat16* __restrict__ lo) {
    size_t i = ((size_t)blockIdx.x * 256 + threadIdx.x) * 4;
    float4 v = *(const float4*)(in + i);
    uint32_t l0, l1;
    uint32_t h0 = pack2(v.x, v.y, l0);
    uint32_t h1 = pack2(v.z, v.w, l1);
    *(uint32_t*)(hi + i) = h0; *(uint32_t*)(hi + i + 2) = h1;
    *(uint32_t*)(lo + i) = l0; *(uint32_t*)(lo + i + 2) = l1;
}

// ================= GEMM: C[M,N] = A @ B, 3-term bf16 split ===================
// CTA 128x256, BK=64, 256 thr, 8 warps x (64x64), 2-stage cp.async.
// qkv mode: n-tiles 0-15 -> Wq (fp32 out), 16-17 -> Wk (fp32), 18-19 -> Wv
// (bf16 hi/lo out with [b,g,t,d] remap).
#define GA_ST 144
#define GB_ST 528
#define G_AH 0
#define G_AL 18432
#define G_BH 36864
#define G_BL 70656
#define G_STAGE 104448
#define G_SMEM 208896

__global__ __launch_bounds__(256, 1)
void gemm_bf3_kernel(const __nv_bfloat16* __restrict__ Ah, const __nv_bfloat16* __restrict__ Al,
                     const __nv_bfloat16* __restrict__ Bh0, const __nv_bfloat16* __restrict__ Bl0,
                     const __nv_bfloat16* __restrict__ Bkh, const __nv_bfloat16* __restrict__ Bkl,
                     const __nv_bfloat16* __restrict__ Bvh, const __nv_bfloat16* __restrict__ Bvl,
                     float* __restrict__ Cq, float* __restrict__ Ck,
                     __nv_bfloat16* __restrict__ Voh, __nv_bfloat16* __restrict__ Vol,
                     int N0, int Kd, int qkv) {
    extern __shared__ char sg[];
    uint32_t smb = smem_u32(sg);
    const int tid = threadIdx.x, wid = tid >> 5, lane = tid & 31;
    const int m0 = blockIdx.y * 128;
    const int x = blockIdx.x;

    const __nv_bfloat16 *bh, *bl;
    float* c = nullptr;
    int bst, n0, isV = 0;
    if (!qkv) { bh = Bh0; bl = Bl0; bst = N0; n0 = x * 256; c = Cq; }
    else if (x < 16) { bh = Bh0; bl = Bl0; bst = 4096; n0 = x * 256; c = Cq; }
    else if (x < 18) { bh = Bkh; bl = Bkl; bst = 512; n0 = (x - 16) * 256; c = Ck; }
    else            { bh = Bvh; bl = Bvl; bst = 512; n0 = (x - 18) * 256; isV = 1; }

    const int wm = (wid & 1) * 64, wn = (wid >> 1) * 64;

    float acc[4][8][4];
    #pragma unroll
    for (int i = 0; i < 4; i++)
        #pragma unroll
        for (int j = 0; j < 8; j++)
            #pragma unroll
            for (int e = 0; e < 4; e++) acc[i][j][e] = 0.0f;

    const int NC = Kd >> 6;

    #define G_ISSUE(ch) do { \
        int _s = (ch) & 1; int _k0 = (ch) << 6; \
        uint32_t _st = smb + _s * G_STAGE; \
        _Pragma("unroll") \
        for (int _j = 0; _j < 4; _j++) { \
            int _i = tid + 256 * _j; int _r = _i >> 3, _cc = _i & 7; \
            size_t _go = (size_t)(m0 + _r) * Kd + _k0 + _cc * 8; \
            cpa16(_st + G_AH + _r * GA_ST + _cc * 16, Ah + _go); \
            cpa16(_st + G_AL + _r * GA_ST + _cc * 16, Al + _go); \
        } \
        _Pragma("unroll") \
        for (int _j = 0; _j < 8; _j++) { \
            int _i = tid + 256 * _j; int _r = _i >> 5, _cc = _i & 31; \
            size_t _go = (size_t)(_k0 + _r) * bst + n0 + _cc * 8; \
            cpa16(_st + G_BH + _r * GB_ST + _cc * 16, bh + _go); \
            cpa16(_st + G_BL + _r * GB_ST + _cc * 16, bl + _go); \
        } \
        cpa_commit(); \
    } while (0)

    G_ISSUE(0);

    const int a_r = lane & 15;
    const int a_cb = (lane >> 4) * 16;
    const int b_k = (((lane >> 3) & 1) << 3) + (lane & 7);
    const int b_cb = ((lane >> 3) & 2) ? 16 : 0;

    for (int ch = 0; ch < NC; ch++) {
        if (ch + 1 < NC) { G_ISSUE(ch + 1); cpa_wait<1>(); }
        else cpa_wait<0>();
        __syncthreads();
        uint32_t st = smb + (ch & 1) * G_STAGE;
        uint32_t aHb = st + G_AH + (wm + a_r) * GA_ST + a_cb;
        uint32_t aLb = st + G_AL + (wm + a_r) * GA_ST + a_cb;
        uint32_t bHb = st + G_BH + b_k * GB_ST + wn * 2 + b_cb;
        uint32_t bLb = st + G_BL + b_k * GB_ST + wn * 2 + b_cb;

        #pragma unroll
        for (int kc = 0; kc < 4; kc++) {
            uint32_t ah[4][4], al[4][4];
            #pragma unroll
            for (int mi = 0; mi < 4; mi++) {
                ldsm_x4(ah[mi], aHb + mi * (16 * GA_ST) + kc * 32);
                ldsm_x4(al[mi], aLb + mi * (16 * GA_ST) + kc * 32);
            }
            #pragma unroll
            for (int bj = 0; bj < 4; bj++) {
                uint32_t bhf[4], blf[4];
                ldsm_x4_t(bhf, bHb + kc * (16 * GB_ST) + bj * 32);
                ldsm_x4_t(blf, bLb + kc * (16 * GB_ST) + bj * 32);
                #pragma unroll
                for (int mi = 0; mi < 4; mi++) {
                    mma2(acc[mi][2*bj],   ah[mi], bhf[0], bhf[1]);
                    mma2(acc[mi][2*bj+1], ah[mi], bhf[2], bhf[3]);
                    mma2(acc[mi][2*bj],   ah[mi], blf[0], blf[1]);
                    mma2(acc[mi][2*bj+1], ah[mi], blf[2], blf[3]);
                    mma2(acc[mi][2*bj],   al[mi], bhf[0], bhf[1]);
                    mma2(acc[mi][2*bj+1], al[mi], bhf[2], bhf[3]);
                }
            }
        }
        __syncthreads();
    }

    const int r0 = m0 + wm + (lane >> 2);
    const int c0 = n0 + wn + (lane & 3) * 2;
    if (!isV) {
        #pragma unroll
        for (int mi = 0; mi < 4; mi++) {
            #pragma unroll
            for (int nj = 0; nj < 8; nj++) {
                float2 lo2; lo2.x = acc[mi][nj][0]; lo2.y = acc[mi][nj][1];
                float2 hi2; hi2.x = acc[mi][nj][2]; hi2.y = acc[mi][nj][3];
                *(float2*)&c[(size_t)(r0 + mi * 16) * bst + c0 + nj * 8] = lo2;
                *(float2*)&c[(size_t)(r0 + mi * 16 + 8) * bst + c0 + nj * 8] = hi2;
            }
        }
    } else {
        // V: fused bf16 hi/lo split + [b,g,t,d] remap
        #pragma unroll
        for (int mi = 0; mi < 4; mi++) {
            #pragma unroll
            for (int nj = 0; nj < 8; nj++) {
                int cg = c0 + nj * 8;
                int g = cg >> 7, d = cg & 127;
                #pragma unroll
                for (int half = 0; half < 2; half++) {
                    int r = r0 + mi * 16 + half * 8;
                    int b = r >> 11, t = r & 2047;
                    uint32_t lo;
                    uint32_t hi = pack2(acc[mi][nj][half*2], acc[mi][nj][half*2+1], lo);
                    size_t o = ((size_t)(b * G_ + g) * T_ + t) * KH + d;
                    *(uint32_t*)&Voh[o] = hi;
                    *(uint32_t*)&Vol[o] = lo;
                }
            }
        }
    }
}

// ---------------- RMSNorm + RoPE -> bf16 hi/lo (Q) ---------------------------
__global__ __launch_bounds__(128)
void rope_norm_q_kernel(const float* __restrict__ qraw, const float* __restrict__ cosp,
                        const float* __restrict__ sinp, const float* __restrict__ w,
                        __nv_bfloat16* __restrict__ outh, __nv_bfloat16* __restrict__ outl) {
    const int idx = blockIdx.x;           // bt*H + h
    const int bt = idx >> 4, h = idx & 15;
    const int b = bt >> 11, t = bt & 2047;
    const int d = threadIdx.x;
    float x = qraw[(size_t)idx * 256 + d];
    float ss = x * x;
    #pragma unroll
    for (int o = 16; o; o >>= 1) ss += __shfl_xor_sync(0xffffffffu, ss, o);
    __shared__ float wsum[4];
    __shared__ float sn[128];
    if ((d & 31) == 0) wsum[d >> 5] = ss;
    __syncthreads();
    float tot = wsum[0] + wsum[1] + wsum[2] + wsum[3];
    float r = rsqrtf(tot * (1.0f / 128.0f) + EPS);
    sn[d] = x * r * w[d];
    __syncthreads();
    float c = cosp[(size_t)bt * KH + d];
    float s = sinp[(size_t)bt * KH + d];
    float out = (d < 64) ? sn[d] * c - sn[d + 64] * s : sn[d] * c + sn[d - 64] * s;
    size_t o = ((size_t)(b * H_ + h) * T_ + t) * KH + d;
    __nv_bfloat16 hv = __float2bfloat16_rn(out);
    outh[o] = hv;
    outl[o] = __float2bfloat16_rn(out - __bfloat162float(hv));
}

__global__ __launch_bounds__(128)
void rope_norm_k_kernel(const float* __restrict__ kraw, const float* __restrict__ cosp,
                        const float* __restrict__ sinp, const float* __restrict__ w,
                        __nv_bfloat16* __restrict__ outh, __nv_bfloat16* __restrict__ outl) {
    const int idx = blockIdx.x;           // bt*G + g
    const int bt = idx >> 2, g = idx & 3;
    const int b = bt >> 11, t = bt & 2047;
    const int d = threadIdx.x;
    float x = kraw[(size_t)idx * 128 + d];
    float ss = x * x;
    #pragma unroll
    for (int o = 16; o; o >>= 1) ss += __shfl_xor_sync(0xffffffffu, ss, o);
    __shared__ float wsum[4];
    __shared__ float sn[128];
    if ((d & 31) == 0) wsum[d >> 5] = ss;
    __syncthreads();
    float tot = wsum[0] + wsum[1] + wsum[2] + wsum[3];
    float r = rsqrtf(tot * (1.0f / 128.0f) + EPS);
    sn[d] = x * r * w[d];
    __syncthreads();
    float c = cosp[(size_t)bt * KH + d];
    float s = sinp[(size_t)bt * KH + d];
    float out = (d < 64) ? sn[d] * c - sn[d + 64] * s : sn[d] * c + sn[d - 64] * s;
    size_t o = ((size_t)(b * G_ + g) * T_ + t) * KH + d;
    __nv_bfloat16 hv = __float2bfloat16_rn(out);
    outh[o] = hv;
    outl[o] = __float2bfloat16_rn(out - __bfloat162float(hv));
}

// ================= tensor-core flash attention (v2: 2 CTAs/SM) ===============
// CTA: 64 q-rows, 32-key tiles, 128 threads (4 warps x 16 rows), 2-stage.
// smem: Qh 64x272, Ql 64x272, 2 stages x (Kh,Kl,Vh,Vl each 32x272), seg.
#define AT_ST 272
#define AT_QL 17408            // Q lo offset
#define AT_KV 34816            // stage base (after Q hi+lo)
#define AT_KVSTG 34816         // per stage: 4 x 32 x 272
#define AT_SKL 8704            // K lo offset within stage
#define AT_SVH 17408           // V hi offset within stage
#define AT_SVL 26112           // V lo offset within stage
#define AT_SEG 104448
#define AT_SMEM 104704

__global__ __launch_bounds__(128, 2)
void attn_tc_kernel(const __nv_bfloat16* __restrict__ qh, const __nv_bfloat16* __restrict__ ql,
                    const __nv_bfloat16* __restrict__ kh, const __nv_bfloat16* __restrict__ kl,
                    const __nv_bfloat16* __restrict__ vh, const __nv_bfloat16* __restrict__ vl,
                    const float* __restrict__ qraw, const int* __restrict__ seg,
                    __nv_bfloat16* __restrict__ oh, __nv_bfloat16* __restrict__ ol) {
    extern __shared__ char sa[];
    uint32_t smb = smem_u32(sa);
    const int tid = threadIdx.x, wid = tid >> 5, lane = tid & 31;
    const int qt = (int)(gridDim.x - 1 - blockIdx.x);   // heavy tiles first
    const int q0 = qt * 64;
    const int bh_ = blockIdx.y;
    const int b = bh_ >> 4, h = bh_ & 15;
    const int g = h >> 2;
    const int wm = wid * 16;

    const __nv_bfloat16* qhb = qh + ((size_t)(b * H_ + h) * T_ + q0) * KH;
    const __nv_bfloat16* qlb = ql + ((size_t)(b * H_ + h) * T_ + q0) * KH;
    const __nv_bfloat16* khb = kh + (size_t)(b * G_ + g) * T_ * KH;
    const __nv_bfloat16* klb = kl + (size_t)(b * G_ + g) * T_ * KH;
    const __nv_bfloat16* vhb = vh + (size_t)(b * G_ + g) * T_ * KH;
    const __nv_bfloat16* vlb = vl + (size_t)(b * G_ + g) * T_ * KH;

    // Q prologue loads (64 rows x 128 cols, hi + lo)
    #pragma unroll
    for (int j = 0; j < 8; j++) {
        int i = tid + 128 * j; int r = i >> 4, cc = i & 15;
        cpa16(smb + r * AT_ST + cc * 16, qhb + (size_t)r * KH + cc * 8);
        cpa16(smb + AT_QL + r * AT_ST + cc * 16, qlb + (size_t)r * KH + cc * 8);
    }

    const int nT = (q0 + 64) / 32;

    #define AT_ISSUE(t) do { \
        int _s = (t) & 1; int _s0 = (t) * 32; \
        uint32_t _bs = smb + AT_KV + _s * AT_KVSTG; \
        _Pragma("unroll") \
        for (int _j = 0; _j < 4; _j++) { \
            int _i = tid + 128 * _j; int _r = _i >> 4, _cc = _i & 15; \
            size_t _go = (size_t)(_s0 + _r) * KH + _cc * 8; \
            cpa16(_bs + _r * AT_ST + _cc * 16, khb + _go); \
            cpa16(_bs + AT_SKL + _r * AT_ST + _cc * 16, klb + _go); \
            cpa16(_bs + AT_SVH + _r * AT_ST + _cc * 16, vhb + _go); \
            cpa16(_bs + AT_SVL + _r * AT_ST + _cc * 16, vlb + _go); \
        } \
        if (tid < 8) cpa16(smb + AT_SEG + _s * 128 + tid * 16, seg + (size_t)b * T_ + _s0 + tid * 4); \
        cpa_commit(); \
    } while (0)

    AT_ISSUE(0);

    const int qp0 = q0 + wm + (lane >> 2), qp1 = qp0 + 8;
    const int qs0 = seg[(size_t)b * T_ + qp0];
    const int qs1 = seg[(size_t)b * T_ + qp1];

    float rm0 = -1e30f, rm1 = -1e30f, rl0 = 0.0f, rl1 = 0.0f;
    float oacc[16][4];
    #pragma unroll
    for (int i = 0; i < 16; i++)
        #pragma unroll
        for (int e = 0; e < 4; e++) oacc[i][e] = 0.0f;

    const uint32_t aQh = smb + (wm + (lane & 15)) * AT_ST + (lane >> 4) * 16;
    const uint32_t aQl = aQh + AT_QL;
    const int vb_k = (((lane >> 3) & 1) << 3) + (lane & 7);
    const int vb_cb = ((lane >> 3) & 2) ? 16 : 0;
    const float SC = SCALE * 1.4426950408889634f;
    const float NEGINF = -__int_as_float(0x7f800000);

    for (int t = 0; t < nT; t++) {
        if (t + 1 < nT) { AT_ISSUE(t + 1); cpa_wait<1>(); }
        else cpa_wait<0>();
        __syncthreads();
        const int s0 = t * 32;
        uint32_t kst = smb + AT_KV + (t & 1) * AT_KVSTG;
        const int* kseg = (const int*)(sa + AT_SEG + (t & 1) * 128);

        // ---- S = Q K^T (3-term), 64x32 tile, warp does 16x32 ----
        float sacc[4][4];
        #pragma unroll
        for (int i = 0; i < 4; i++)
            #pragma unroll
            for (int e = 0; e < 4; e++) sacc[i][e] = 0.0f;

        #pragma unroll
        for (int kc = 0; kc < 8; kc++) {
            uint32_t ahf[4], alf[4];
            ldsm_x4(ahf, aQh + kc * 32);
            ldsm_x4(alf, aQl + kc * 32);
            #pragma unroll
            for (int ng = 0; ng < 2; ng++) {
                uint32_t kbh[4], kbl[4];
                uint32_t ka = kst + (ng * 16 + (lane & 15)) * AT_ST + (lane >> 4) * 16 + kc * 32;
                ldsm_x4(kbh, ka);
                ldsm_x4(kbl, ka + AT_SKL);
                mma2(sacc[2*ng],   ahf, kbh[0], kbh[2]);
                mma2(sacc[2*ng+1], ahf, kbh[1], kbh[3]);
                mma2(sacc[2*ng],   ahf, kbl[0], kbl[2]);
                mma2(sacc[2*ng+1], ahf, kbl[1], kbl[3]);
                mma2(sacc[2*ng],   alf, kbh[0], kbh[2]);
                mma2(sacc[2*ng+1], alf, kbh[1], kbh[3]);
            }
        }

        // ---- scale + mask ----
        const int lc = (lane & 3) * 2;
        #pragma unroll
        for (int gi = 0; gi < 4; gi++) {
            int c0c = s0 + gi * 8 + lc, c1c = c0c + 1;
            int ks0 = kseg[gi * 8 + lc], ks1 = kseg[gi * 8 + lc + 1];
            float v;
            v = sacc[gi][0] * SC; sacc[gi][0] = (c0c <= qp0 && ks0 == qs0) ? v : NEGINF;
            v = sacc[gi][1] * SC; sacc[gi][1] = (c1c <= qp0 && ks1 == qs0) ? v : NEGINF;
            v = sacc[gi][2] * SC; sacc[gi][2] = (c0c <= qp1 && ks0 == qs1) ? v : NEGINF;
            v = sacc[gi][3] * SC; sacc[gi][3] = (c1c <= qp1 && ks1 == qs1) ? v : NEGINF;
        }

        // ---- online softmax ----
        float mx0 = NEGINF, mx1 = NEGINF;
        #pragma unroll
        for (int gi = 0; gi < 4; gi++) {
            mx0 = fmaxf(mx0, fmaxf(sacc[gi][0], sacc[gi][1]));
            mx1 = fmaxf(mx1, fmaxf(sacc[gi][2], sacc[gi][3]));
        }
        mx0 = fmaxf(mx0, __shfl_xor_sync(0xffffffffu, mx0, 1));
        mx0 = fmaxf(mx0, __shfl_xor_sync(0xffffffffu, mx0, 2));
        mx1 = fmaxf(mx1, __shfl_xor_sync(0xffffffffu, mx1, 1));
        mx1 = fmaxf(mx1, __shfl_xor_sync(0xffffffffu, mx1, 2));
        float nm0 = fmaxf(rm0, mx0), nm1 = fmaxf(rm1, mx1);
        float al0 = ex2f(rm0 - nm0), al1 = ex2f(rm1 - nm1);
        rm0 = nm0; rm1 = nm1;
        float sum0 = 0.0f, sum1 = 0.0f;
        #pragma unroll
        for (int gi = 0; gi < 4; gi++) {
            float p;
            p = ex2f(sacc[gi][0] - nm0); sum0 += p; sacc[gi][0] = p;
            p = ex2f(sacc[gi][1] - nm0); sum0 += p; sacc[gi][1] = p;
            p = ex2f(sacc[gi][2] - nm1); sum1 += p; sacc[gi][2] = p;
            p = ex2f(sacc[gi][3] - nm1); sum1 += p; sacc[gi][3] = p;
        }
        rl0 = rl0 * al0 + sum0;
        rl1 = rl1 * al1 + sum1;
        #pragma unroll
        for (int og = 0; og < 16; og++) {
            oacc[og][0] *= al0; oacc[og][1] *= al0;
            oacc[og][2] *= al1; oacc[og][3] *= al1;
        }

        // ---- O += P V (3-term: Ph*Vh + Pl*Vh + Ph*Vl) ----
        #pragma unroll
        for (int kc2 = 0; kc2 < 2; kc2++) {
            uint32_t pa[4], pl[4];
            pa[0] = pack2(sacc[2*kc2][0],   sacc[2*kc2][1],   pl[0]);
            pa[1] = pack2(sacc[2*kc2][2],   sacc[2*kc2][3],   pl[1]);
            pa[2] = pack2(sacc[2*kc2+1][0], sacc[2*kc2+1][1], pl[2]);
            pa[3] = pack2(sacc[2*kc2+1][2], sacc[2*kc2+1][3], pl[3]);
            uint32_t vbase = kst + AT_SVH + (kc2 * 16 + vb_k) * AT_ST + vb_cb;
            #pragma unroll
            for (int nd = 0; nd < 8; nd++) {
                uint32_t vbh[4], vbl[4];
                ldsm_x4_t(vbh, vbase + nd * 32);
                ldsm_x4_t(vbl, vbase + (AT_SVL - AT_SVH) + nd * 32);
                mma2(oacc[2*nd],   pa, vbh[0], vbh[1]);
                mma2(oacc[2*nd+1], pa, vbh[2], vbh[3]);
                mma2(oacc[2*nd],   pl, vbh[0], vbh[1]);
                mma2(oacc[2*nd+1], pl, vbh[2], vbh[3]);
                mma2(oacc[2*nd],   pa, vbl[0], vbl[1]);
                mma2(oacc[2*nd+1], pa, vbl[2], vbl[3]);
            }
        }
        __syncthreads();
    }

    // ---- epilogue: normalize, gate, split to bf16 hi/lo ----
    rl0 += __shfl_xor_sync(0xffffffffu, rl0, 1);
    rl0 += __shfl_xor_sync(0xffffffffu, rl0, 2);
    rl1 += __shfl_xor_sync(0xffffffffu, rl1, 1);
    rl1 += __shfl_xor_sync(0xffffffffu, rl1, 2);
    float inv0 = 1.0f / rl0, inv1 = 1.0f / rl1;
    const float L2E = 1.4426950408889634f;
    #pragma unroll
    for (int og = 0; og < 16; og++) {
        int d = og * 8 + (lane & 3) * 2;
        // row 0
        {
            float2 gt = *(const float2*)&qraw[((size_t)(b * T_ + qp0) * H_ + h) * 256 + 128 + d];
            float s0v = 1.0f / (1.0f + ex2f(-gt.x * L2E));
            float s1v = 1.0f / (1.0f + ex2f(-gt.y * L2E));
            float x0 = oacc[og][0] * inv0 * s0v;
            float x1 = oacc[og][1] * inv0 * s1v;
            uint32_t lo; uint32_t hi = pack2(x0, x1, lo);
            size_t o = (size_t)(b * T_ + qp0) * (H_ * KH) + h * KH + d;
            *(uint32_t*)&oh[o] = hi; *(uint32_t*)&ol[o] = lo;
        }
        // row 1
        {
            float2 gt = *(const float2*)&qraw[((size_t)(b * T_ + qp1) * H_ + h) * 256 + 128 + d];
            float s0v = 1.0f / (1.0f + ex2f(-gt.x * L2E));
            float s1v = 1.0f / (1.0f + ex2f(-gt.y * L2E));
            float x0 = oacc[og][2] * inv1 * s0v;
            float x1 = oacc[og][3] * inv1 * s1v;
            uint32_t lo; uint32_t hi = pack2(x0, x1, lo);
            size_t o = (size_t)(b * T_ + qp1) * (H_ * KH) + h * KH + d;
            *(uint32_t*)&oh[o] = hi; *(uint32_t*)&ol[o] = lo;
        }
    }
}

// ---------------- launch -----------------------------------------------------
extern "C" void kernel_launch(void* const* d_in, const int* in_sizes, int n_in,
                              void* d_out, int out_size) {
    const float* hidden = (const float*)d_in[0];
    const float* cosp   = (const float*)d_in[1];
    const float* sinp   = (const float*)d_in[2];
    const int*   seg    = (const int*)d_in[3];
    const float* Wq = (const float*)d_in[5];
    const float* Wk = (const float*)d_in[6];
    const float* Wv = (const float*)d_in[7];
    const float* Wo = (const float*)d_in[8];
    const float* qw = (const float*)d_in[9];
    const float* kw = (const float*)d_in[10];
    float* out = (float*)d_out;

    float *qraw, *kraw;
    __nv_bfloat16 *hidh, *hidl, *wqh, *wql, *wkh, *wkl, *wvh, *wvl, *woh, *wol;
    __nv_bfloat16 *qbh, *qbl, *kbh, *kbl, *vbh, *vbl, *aoh, *aol;
    cudaGetSymbolAddress((void**)&qraw, g_qraw);
    cudaGetSymbolAddress((void**)&kraw, g_kraw);
    cudaGetSymbolAddress((void**)&hidh, g_hid_h); cudaGetSymbolAddress((void**)&hidl, g_hid_l);
    cudaGetSymbolAddress((void**)&wqh, g_wq_h);   cudaGetSymbolAddress((void**)&wql, g_wq_l);
    cudaGetSymbolAddress((void**)&wkh, g_wk_h);   cudaGetSymbolAddress((void**)&wkl, g_wk_l);
    cudaGetSymbolAddress((void**)&wvh, g_wv_h);   cudaGetSymbolAddress((void**)&wvl, g_wv_l);
    cudaGetSymbolAddress((void**)&woh, g_wo_h);   cudaGetSymbolAddress((void**)&wol, g_wo_l);
    cudaGetSymbolAddress((void**)&qbh, g_qb_h);   cudaGetSymbolAddress((void**)&qbl, g_qb_l);
    cudaGetSymbolAddress((void**)&kbh, g_kb_h);   cudaGetSymbolAddress((void**)&kbl, g_kb_l);
    cudaGetSymbolAddress((void**)&vbh, g_vb_h);   cudaGetSymbolAddress((void**)&vbl, g_vb_l);
    cudaGetSymbolAddress((void**)&aoh, g_ao_h);   cudaGetSymbolAddress((void**)&aol, g_ao_l);

    cudaFuncSetAttribute(gemm_bf3_kernel, cudaFuncAttributeMaxDynamicSharedMemorySize, G_SMEM);
    cudaFuncSetAttribute(attn_tc_kernel,  cudaFuncAttributeMaxDynamicSharedMemorySize, AT_SMEM);

    // 1. split operands to bf16 hi/lo
    split4_kernel<<<(B_*T_*D_) / 1024, 256>>>(hidden, hidh, hidl);
    split4_kernel<<<(D_*H_*2*KH) / 1024, 256>>>(Wq, wqh, wql);
    split4_kernel<<<(D_*G_*KH) / 1024, 256>>>(Wk, wkh, wkl);
    split4_kernel<<<(D_*G_*KH) / 1024, 256>>>(Wv, wvh, wvl);
    split4_kernel<<<(H_*KH*D_) / 1024, 256>>>(Wo, woh, wol);

    // 2. merged Q/K/V projection (V written directly as bf16 hi/lo [b,g,t,d])
    gemm_bf3_kernel<<<dim3(20, 32), 256, G_SMEM>>>(hidh, hidl, wqh, wql, wkh, wkl,
                                                   wvh, wvl, qraw, kraw, vbh, vbl,
                                                   0, 2048, 1);

    // 3. rmsnorm + rope -> bf16 hi/lo
    rope_norm_q_kernel<<<B_*T_*H_, 128>>>(qraw, cosp, sinp, qw, qbh, qbl);
    rope_norm_k_kernel<<<B_*T_*G_, 128>>>(kraw, cosp, sinp, kw, kbh, kbl);

    // 4. attention (gate fused, 2 CTAs/SM)
    attn_tc_kernel<<<dim3(T_/64, B_*H_), 128, AT_SMEM>>>(qbh, qbl, kbh, kbl, vbh, vbl,
                                                         qraw, seg, aoh, aol);

    // 5. output projection
    gemm_bf3_kernel<<<dim3(8, 32), 256, G_SMEM>>>(aoh, aol, woh, wol, nullptr, nullptr,
                                                  nullptr, nullptr, out, nullptr,
                                                  nullptr, nullptr, 2048, 2048, 0);
}

// round 10
// speedup vs baseline: 4.4887x; 1.4158x over previous
#include <cuda_runtime.h>
#include <cuda_fp16.h>
#include <cstdint>

// Problem constants
#define B_  2
#define T_  2048
#define D_  2048
#define H_  16
#define G_  4
#define KH  128
#define EPS 1e-6f
static const float SCALE = 0.088388347648318447f; // 128^-0.5

// ---------------- scratch (device globals) -----------------------------------
__device__ float g_qraw[B_*T_*H_*2*KH];       // fp32 (gate kept here)
__device__ float g_kraw[B_*T_*G_*KH];
// fp16 operands: A-side single, B-side hi/lo
__device__ __half g_hid[B_*T_*D_];
__device__ __half g_wq_h[D_*H_*2*KH], g_wq_l[D_*H_*2*KH];
__device__ __half g_wk_h[D_*G_*KH],   g_wk_l[D_*G_*KH];
__device__ __half g_wv_h[D_*G_*KH],   g_wv_l[D_*G_*KH];
__device__ __half g_wo_h[H_*KH*D_],   g_wo_l[H_*KH*D_];
__device__ __half g_qb[B_*H_*T_*KH];                      // Q single  [b,h,t,d]
__device__ __half g_kb_h[B_*G_*T_*KH], g_kb_l[B_*G_*T_*KH]; // K hi/lo [b,g,t,d]
__device__ __half g_vb[B_*G_*T_*KH];                      // V single [b,g,t,d]
__device__ __half g_ao[B_*T_*H_*KH];                      // gated attn single

// ============================ helpers ========================================
__device__ __forceinline__ uint32_t smem_u32(const void* p) {
    return (uint32_t)__cvta_generic_to_shared((void*)p);
}
__device__ __forceinline__ void ldsm_x4(uint32_t* r, uint32_t addr) {
    asm volatile("ldmatrix.sync.aligned.m8n8.x4.shared.b16 {%0,%1,%2,%3}, [%4];"
        : "=r"(r[0]), "=r"(r[1]), "=r"(r[2]), "=r"(r[3]) : "r"(addr));
}
__device__ __forceinline__ void ldsm_x4_t(uint32_t* r, uint32_t addr) {
    asm volatile("ldmatrix.sync.aligned.m8n8.x4.trans.shared.b16 {%0,%1,%2,%3}, [%4];"
        : "=r"(r[0]), "=r"(r[1]), "=r"(r[2]), "=r"(r[3]) : "r"(addr));
}
__device__ __forceinline__ void mma2(float* d, const uint32_t* a, uint32_t b0, uint32_t b1) {
    asm volatile("mma.sync.aligned.m16n8k16.row.col.f32.f16.f16.f32 "
        "{%0,%1,%2,%3}, {%4,%5,%6,%7}, {%8,%9}, {%0,%1,%2,%3};"
        : "+f"(d[0]), "+f"(d[1]), "+f"(d[2]), "+f"(d[3])
        : "r"(a[0]), "r"(a[1]), "r"(a[2]), "r"(a[3]), "r"(b0), "r"(b1));
}
__device__ __forceinline__ void cpa16(uint32_t s, const void* g) {
    asm volatile("cp.async.cg.shared.global [%0], [%1], 16;" :: "r"(s), "l"(g));
}
__device__ __forceinline__ void cpa_commit() { asm volatile("cp.async.commit_group;"); }
template<int N> __device__ __forceinline__ void cpa_wait() {
    asm volatile("cp.async.wait_group %0;" :: "n"(N));
}
__device__ __forceinline__ float ex2f(float x) {
    float y; asm("ex2.approx.ftz.f32 %0, %1;" : "=f"(y) : "f"(x)); return y;
}
// pack 2 fp32 -> fp16x2 hi + fp16x2 residual lo
__device__ __forceinline__ uint32_t pack2h(float a, float b, uint32_t& lo) {
    __half ha = __float2half_rn(a);
    __half hb = __float2half_rn(b);
    __half2 hp = __halves2half2(ha, hb);
    __half2 lp = __floats2half2_rn(a - __half2float(ha), b - __half2float(hb));
    lo = *reinterpret_cast<uint32_t*>(&lp);
    return *reinterpret_cast<uint32_t*>(&hp);
}
__device__ __forceinline__ uint32_t f22h(float a, float b) {
    __half2 t = __floats2half2_rn(a, b);
    return *reinterpret_cast<uint32_t*>(&t);
}

// ---------------- convert fp32 -> single fp16 --------------------------------
__global__ __launch_bounds__(256)
void cvt4_kernel(const float* __restrict__ in, __half* __restrict__ out) {
    size_t i = ((size_t)blockIdx.x * 256 + threadIdx.x) * 4;
    float4 v = *(const float4*)(in + i);
    uint32_t h0 = f22h(v.x, v.y);
    uint32_t h1 = f22h(v.z, v.w);
    *(uint32_t*)(out + i) = h0; *(uint32_t*)(out + i + 2) = h1;
}
// ---------------- split fp32 -> fp16 hi/lo -----------------------------------
__global__ __launch_bounds__(256)
void split4_kernel(const float* __restrict__ in, __half* __restrict__ hi,
                   __half* __restrict__ lo) {
    size_t i = ((size_t)blockIdx.x * 256 + threadIdx.x) * 4;
    float4 v = *(const float4*)(in + i);
    uint32_t l0, l1;
    uint32_t h0 = pack2h(v.x, v.y, l0);
    uint32_t h1 = pack2h(v.z, v.w, l1);
    *(uint32_t*)(hi + i) = h0; *(uint32_t*)(hi + i + 2) = h1;
    *(uint32_t*)(lo + i) = l0; *(uint32_t*)(lo + i + 2) = l1;
}

// ================= GEMM: C[M,N] = A @ B, fp16 2-term (A single, B hi/lo) =====
// CTA 128x256, BK=64, 256 thr, 8 warps x (64x64), 2-stage cp.async.
// qkv mode: n-tiles 0-15 -> Wq (fp32), 16-17 -> Wk (fp32), 18-19 -> Wv (fp16).
#define GA_ST 144
#define GB_ST 528
#define G_A  0
#define G_BH 18432
#define G_BL 52224
#define G_STAGE 86016
#define G_SMEM 172032

__global__ __launch_bounds__(256, 1)
void gemm_h2_kernel(const __half* __restrict__ A,
                    const __half* __restrict__ Bh0, const __half* __restrict__ Bl0,
                    const __half* __restrict__ Bkh, const __half* __restrict__ Bkl,
                    const __half* __restrict__ Bvh, const __half* __restrict__ Bvl,
                    float* __restrict__ Cq, float* __restrict__ Ck,
                    __half* __restrict__ Vo,
                    int N0, int Kd, int qkv) {
    extern __shared__ char sg[];
    uint32_t smb = smem_u32(sg);
    const int tid = threadIdx.x, wid = tid >> 5, lane = tid & 31;
    const int m0 = blockIdx.y * 128;
    const int x = blockIdx.x;

    const __half *bh, *bl;
    float* c = nullptr;
    int bst, n0, isV = 0;
    if (!qkv) { bh = Bh0; bl = Bl0; bst = N0; n0 = x * 256; c = Cq; }
    else if (x < 16) { bh = Bh0; bl = Bl0; bst = 4096; n0 = x * 256; c = Cq; }
    else if (x < 18) { bh = Bkh; bl = Bkl; bst = 512; n0 = (x - 16) * 256; c = Ck; }
    else            { bh = Bvh; bl = Bvl; bst = 512; n0 = (x - 18) * 256; isV = 1; }

    const int wm = (wid & 1) * 64, wn = (wid >> 1) * 64;

    float acc[4][8][4];
    #pragma unroll
    for (int i = 0; i < 4; i++)
        #pragma unroll
        for (int j = 0; j < 8; j++)
            #pragma unroll
            for (int e = 0; e < 4; e++) acc[i][j][e] = 0.0f;

    const int NC = Kd >> 6;

    #define G_ISSUE(ch) do { \
        int _s = (ch) & 1; int _k0 = (ch) << 6; \
        uint32_t _st = smb + _s * G_STAGE; \
        _Pragma("unroll") \
        for (int _j = 0; _j < 4; _j++) { \
            int _i = tid + 256 * _j; int _r = _i >> 3, _cc = _i & 7; \
            cpa16(_st + G_A + _r * GA_ST + _cc * 16, A + (size_t)(m0 + _r) * Kd + _k0 + _cc * 8); \
        } \
        _Pragma("unroll") \
        for (int _j = 0; _j < 8; _j++) { \
            int _i = tid + 256 * _j; int _r = _i >> 5, _cc = _i & 31; \
            size_t _go = (size_t)(_k0 + _r) * bst + n0 + _cc * 8; \
            cpa16(_st + G_BH + _r * GB_ST + _cc * 16, bh + _go); \
            cpa16(_st + G_BL + _r * GB_ST + _cc * 16, bl + _go); \
        } \
        cpa_commit(); \
    } while (0)

    G_ISSUE(0);

    const int a_r = lane & 15;
    const int a_cb = (lane >> 4) * 16;
    const int b_k = (((lane >> 3) & 1) << 3) + (lane & 7);
    const int b_cb = ((lane >> 3) & 2) ? 16 : 0;

    for (int ch = 0; ch < NC; ch++) {
        if (ch + 1 < NC) { G_ISSUE(ch + 1); cpa_wait<1>(); }
        else cpa_wait<0>();
        __syncthreads();
        uint32_t st = smb + (ch & 1) * G_STAGE;
        uint32_t aB  = st + G_A  + (wm + a_r) * GA_ST + a_cb;
        uint32_t bHb = st + G_BH + b_k * GB_ST + wn * 2 + b_cb;
        uint32_t bLb = st + G_BL + b_k * GB_ST + wn * 2 + b_cb;

        #pragma unroll
        for (int kc = 0; kc < 4; kc++) {
            uint32_t ah[4][4];
            #pragma unroll
            for (int mi = 0; mi < 4; mi++)
                ldsm_x4(ah[mi], aB + mi * (16 * GA_ST) + kc * 32);
            #pragma unroll
            for (int bj = 0; bj < 4; bj++) {
                uint32_t bhf[4], blf[4];
                ldsm_x4_t(bhf, bHb + kc * (16 * GB_ST) + bj * 32);
                ldsm_x4_t(blf, bLb + kc * (16 * GB_ST) + bj * 32);
                #pragma unroll
                for (int mi = 0; mi < 4; mi++) {
                    mma2(acc[mi][2*bj],   ah[mi], bhf[0], bhf[1]);
                    mma2(acc[mi][2*bj+1], ah[mi], bhf[2], bhf[3]);
                    mma2(acc[mi][2*bj],   ah[mi], blf[0], blf[1]);
                    mma2(acc[mi][2*bj+1], ah[mi], blf[2], blf[3]);
                }
            }
        }
        __syncthreads();
    }

    const int r0 = m0 + wm + (lane >> 2);
    const int c0 = n0 + wn + (lane & 3) * 2;
    if (!isV) {
        #pragma unroll
        for (int mi = 0; mi < 4; mi++) {
            #pragma unroll
            for (int nj = 0; nj < 8; nj++) {
                float2 lo2; lo2.x = acc[mi][nj][0]; lo2.y = acc[mi][nj][1];
                float2 hi2; hi2.x = acc[mi][nj][2]; hi2.y = acc[mi][nj][3];
                *(float2*)&c[(size_t)(r0 + mi * 16) * bst + c0 + nj * 8] = lo2;
                *(float2*)&c[(size_t)(r0 + mi * 16 + 8) * bst + c0 + nj * 8] = hi2;
            }
        }
    } else {
        // V: fused single-fp16 convert + [b,g,t,d] remap
        #pragma unroll
        for (int mi = 0; mi < 4; mi++) {
            #pragma unroll
            for (int nj = 0; nj < 8; nj++) {
                int cg = c0 + nj * 8;
                int g = cg >> 7, d = cg & 127;
                #pragma unroll
                for (int half_ = 0; half_ < 2; half_++) {
                    int r = r0 + mi * 16 + half_ * 8;
                    int b = r >> 11, t = r & 2047;
                    uint32_t hv = f22h(acc[mi][nj][half_*2], acc[mi][nj][half_*2+1]);
                    size_t o = ((size_t)(b * G_ + g) * T_ + t) * KH + d;
                    *(uint32_t*)&Vo[o] = hv;
                }
            }
        }
    }
}

// ---------------- RMSNorm + RoPE -> fp16 (Q single) --------------------------
__global__ __launch_bounds__(128)
void rope_norm_q_kernel(const float* __restrict__ qraw, const float* __restrict__ cosp,
                        const float* __restrict__ sinp, const float* __restrict__ w,
                        __half* __restrict__ outq) {
    const int idx = blockIdx.x;           // bt*H + h
    const int bt = idx >> 4, h = idx & 15;
    const int b = bt >> 11, t = bt & 2047;
    const int d = threadIdx.x;
    float x = qraw[(size_t)idx * 256 + d];
    float ss = x * x;
    #pragma unroll
    for (int o = 16; o; o >>= 1) ss += __shfl_xor_sync(0xffffffffu, ss, o);
    __shared__ float wsum[4];
    __shared__ float sn[128];
    if ((d & 31) == 0) wsum[d >> 5] = ss;
    __syncthreads();
    float tot = wsum[0] + wsum[1] + wsum[2] + wsum[3];
    float r = rsqrtf(tot * (1.0f / 128.0f) + EPS);
    sn[d] = x * r * w[d];
    __syncthreads();
    float c = cosp[(size_t)bt * KH + d];
    float s = sinp[(size_t)bt * KH + d];
    float out = (d < 64) ? sn[d] * c - sn[d + 64] * s : sn[d] * c + sn[d - 64] * s;
    size_t o = ((size_t)(b * H_ + h) * T_ + t) * KH + d;
    outq[o] = __float2half_rn(out);
}

// ---------------- RMSNorm + RoPE -> fp16 hi/lo (K) ---------------------------
__global__ __launch_bounds__(128)
void rope_norm_k_kernel(const float* __restrict__ kraw, const float* __restrict__ cosp,
                        const float* __restrict__ sinp, const float* __restrict__ w,
                        __half* __restrict__ outh, __half* __restrict__ outl) {
    const int idx = blockIdx.x;           // bt*G + g
    const int bt = idx >> 2, g = idx & 3;
    const int b = bt >> 11, t = bt & 2047;
    const int d = threadIdx.x;
    float x = kraw[(size_t)idx * 128 + d];
    float ss = x * x;
    #pragma unroll
    for (int o = 16; o; o >>= 1) ss += __shfl_xor_sync(0xffffffffu, ss, o);
    __shared__ float wsum[4];
    __shared__ float sn[128];
    if ((d & 31) == 0) wsum[d >> 5] = ss;
    __syncthreads();
    float tot = wsum[0] + wsum[1] + wsum[2] + wsum[3];
    float r = rsqrtf(tot * (1.0f / 128.0f) + EPS);
    sn[d] = x * r * w[d];
    __syncthreads();
    float c = cosp[(size_t)bt * KH + d];
    float s = sinp[(size_t)bt * KH + d];
    float out = (d < 64) ? sn[d] * c - sn[d + 64] * s : sn[d] * c + sn[d - 64] * s;
    size_t o = ((size_t)(b * G_ + g) * T_ + t) * KH + d;
    __half hv = __float2half_rn(out);
    outh[o] = hv;
    outl[o] = __float2half_rn(out - __half2float(hv));
}

// ================= tensor-core flash attention (fp16) ========================
// CTA: 64 q-rows, 32-key tiles, 128 threads (4 warps x 16 rows), 2-stage.
// Q single, K hi/lo (2-term S), V single (1-term PV with single-fp16 P).
#define AT_ST 272
#define AT_KV 17408            // stage base (after Q single 64x272)
#define AT_KVSTG 26112         // per stage: Kh,Kl,V each 32x272
#define AT_SKL 8704            // K lo offset within stage
#define AT_SV  17408           // V offset within stage
#define AT_SEG 69632
#define AT_SMEM 69888

__global__ __launch_bounds__(128, 3)
void attn_tc_kernel(const __half* __restrict__ qv, const __half* __restrict__ kh,
                    const __half* __restrict__ kl, const __half* __restrict__ vv,
                    const float* __restrict__ qraw, const int* __restrict__ seg,
                    __half* __restrict__ ao) {
    extern __shared__ char sa[];
    uint32_t smb = smem_u32(sa);
    const int tid = threadIdx.x, wid = tid >> 5, lane = tid & 31;
    const int qt = (int)(gridDim.x - 1 - blockIdx.x);   // heavy tiles first
    const int q0 = qt * 64;
    const int bh_ = blockIdx.y;
    const int b = bh_ >> 4, h = bh_ & 15;
    const int g = h >> 2;
    const int wm = wid * 16;

    const __half* qb = qv + ((size_t)(b * H_ + h) * T_ + q0) * KH;
    const __half* khb = kh + (size_t)(b * G_ + g) * T_ * KH;
    const __half* klb = kl + (size_t)(b * G_ + g) * T_ * KH;
    const __half* vb  = vv + (size_t)(b * G_ + g) * T_ * KH;

    // Q prologue loads (64 rows x 128 fp16)
    #pragma unroll
    for (int j = 0; j < 8; j++) {
        int i = tid + 128 * j; int r = i >> 4, cc = i & 15;
        cpa16(smb + r * AT_ST + cc * 16, qb + (size_t)r * KH + cc * 8);
    }

    const int nT = (q0 + 64) / 32;

    #define AT_ISSUE(t) do { \
        int _s = (t) & 1; int _s0 = (t) * 32; \
        uint32_t _bs = smb + AT_KV + _s * AT_KVSTG; \
        _Pragma("unroll") \
        for (int _j = 0; _j < 4; _j++) { \
            int _i = tid + 128 * _j; int _r = _i >> 4, _cc = _i & 15; \
            size_t _go = (size_t)(_s0 + _r) * KH + _cc * 8; \
            cpa16(_bs + _r * AT_ST + _cc * 16, khb + _go); \
            cpa16(_bs + AT_SKL + _r * AT_ST + _cc * 16, klb + _go); \
            cpa16(_bs + AT_SV  + _r * AT_ST + _cc * 16, vb  + _go); \
        } \
        if (tid < 8) cpa16(smb + AT_SEG + _s * 128 + tid * 16, seg + (size_t)b * T_ + _s0 + tid * 4); \
        cpa_commit(); \
    } while (0)

    AT_ISSUE(0);

    const int qp0 = q0 + wm + (lane >> 2), qp1 = qp0 + 8;
    const int qs0 = seg[(size_t)b * T_ + qp0];
    const int qs1 = seg[(size_t)b * T_ + qp1];

    float rm0 = -1e30f, rm1 = -1e30f, rl0 = 0.0f, rl1 = 0.0f;
    float oacc[16][4];
    #pragma unroll
    for (int i = 0; i < 16; i++)
        #pragma unroll
        for (int e = 0; e < 4; e++) oacc[i][e] = 0.0f;

    const uint32_t aQ = smb + (wm + (lane & 15)) * AT_ST + (lane >> 4) * 16;
    const int vb_k = (((lane >> 3) & 1) << 3) + (lane & 7);
    const int vb_cb = ((lane >> 3) & 2) ? 16 : 0;
    const float SC = SCALE * 1.4426950408889634f;
    const float NEGINF = -__int_as_float(0x7f800000);

    for (int t = 0; t < nT; t++) {
        if (t + 1 < nT) { AT_ISSUE(t + 1); cpa_wait<1>(); }
        else cpa_wait<0>();
        __syncthreads();
        const int s0 = t * 32;
        uint32_t kst = smb + AT_KV + (t & 1) * AT_KVSTG;
        const int* kseg = (const int*)(sa + AT_SEG + (t & 1) * 128);

        // ---- S = Q K^T (2-term: Q*Kh + Q*Kl) ----
        float sacc[4][4];
        #pragma unroll
        for (int i = 0; i < 4; i++)
            #pragma unroll
            for (int e = 0; e < 4; e++) sacc[i][e] = 0.0f;

        #pragma unroll
        for (int kc = 0; kc < 8; kc++) {
            uint32_t aq[4];
            ldsm_x4(aq, aQ + kc * 32);
            #pragma unroll
            for (int ng = 0; ng < 2; ng++) {
                uint32_t kbh[4], kbl[4];
                uint32_t ka = kst + (ng * 16 + (lane & 15)) * AT_ST + (lane >> 4) * 16 + kc * 32;
                ldsm_x4(kbh, ka);
                ldsm_x4(kbl, ka + AT_SKL);
                mma2(sacc[2*ng],   aq, kbh[0], kbh[2]);
                mma2(sacc[2*ng+1], aq, kbh[1], kbh[3]);
                mma2(sacc[2*ng],   aq, kbl[0], kbl[2]);
                mma2(sacc[2*ng+1], aq, kbl[1], kbl[3]);
            }
        }

        // ---- scale + mask ----
        const int lc = (lane & 3) * 2;
        #pragma unroll
        for (int gi = 0; gi < 4; gi++) {
            int c0c = s0 + gi * 8 + lc, c1c = c0c + 1;
            int ks0 = kseg[gi * 8 + lc], ks1 = kseg[gi * 8 + lc + 1];
            float v;
            v = sacc[gi][0] * SC; sacc[gi][0] = (c0c <= qp0 && ks0 == qs0) ? v : NEGINF;
            v = sacc[gi][1] * SC; sacc[gi][1] = (c1c <= qp0 && ks1 == qs0) ? v : NEGINF;
            v = sacc[gi][2] * SC; sacc[gi][2] = (c0c <= qp1 && ks0 == qs1) ? v : NEGINF;
            v = sacc[gi][3] * SC; sacc[gi][3] = (c1c <= qp1 && ks1 == qs1) ? v : NEGINF;
        }

        // ---- online softmax ----
        float mx0 = NEGINF, mx1 = NEGINF;
        #pragma unroll
        for (int gi = 0; gi < 4; gi++) {
            mx0 = fmaxf(mx0, fmaxf(sacc[gi][0], sacc[gi][1]));
            mx1 = fmaxf(mx1, fmaxf(sacc[gi][2], sacc[gi][3]));
        }
        mx0 = fmaxf(mx0, __shfl_xor_sync(0xffffffffu, mx0, 1));
        mx0 = fmaxf(mx0, __shfl_xor_sync(0xffffffffu, mx0, 2));
        mx1 = fmaxf(mx1, __shfl_xor_sync(0xffffffffu, mx1, 1));
        mx1 = fmaxf(mx1, __shfl_xor_sync(0xffffffffu, mx1, 2));
        float nm0 = fmaxf(rm0, mx0), nm1 = fmaxf(rm1, mx1);
        float al0 = ex2f(rm0 - nm0), al1 = ex2f(rm1 - nm1);
        rm0 = nm0; rm1 = nm1;
        float sum0 = 0.0f, sum1 = 0.0f;
        #pragma unroll
        for (int gi = 0; gi < 4; gi++) {
            float p;
            p = ex2f(sacc[gi][0] - nm0); sum0 += p; sacc[gi][0] = p;
            p = ex2f(sacc[gi][1] - nm0); sum0 += p; sacc[gi][1] = p;
            p = ex2f(sacc[gi][2] - nm1); sum1 += p; sacc[gi][2] = p;
            p = ex2f(sacc[gi][3] - nm1); sum1 += p; sacc[gi][3] = p;
        }
        rl0 = rl0 * al0 + sum0;
        rl1 = rl1 * al1 + sum1;
        #pragma unroll
        for (int og = 0; og < 16; og++) {
            oacc[og][0] *= al0; oacc[og][1] *= al0;
            oacc[og][2] *= al1; oacc[og][3] *= al1;
        }

        // ---- O += P V (single-term: P fp16 x V fp16) ----
        #pragma unroll
        for (int kc2 = 0; kc2 < 2; kc2++) {
            uint32_t pa[4];
            pa[0] = f22h(sacc[2*kc2][0],   sacc[2*kc2][1]);
            pa[1] = f22h(sacc[2*kc2][2],   sacc[2*kc2][3]);
            pa[2] = f22h(sacc[2*kc2+1][0], sacc[2*kc2+1][1]);
            pa[3] = f22h(sacc[2*kc2+1][2], sacc[2*kc2+1][3]);
            uint32_t vbase = kst + AT_SV + (kc2 * 16 + vb_k) * AT_ST + vb_cb;
            #pragma unroll
            for (int nd = 0; nd < 8; nd++) {
                uint32_t vbf[4];
                ldsm_x4_t(vbf, vbase + nd * 32);
                mma2(oacc[2*nd],   pa, vbf[0], vbf[1]);
                mma2(oacc[2*nd+1], pa, vbf[2], vbf[3]);
            }
        }
        __syncthreads();
    }

    // ---- epilogue: normalize, gate, convert to single fp16 ----
    rl0 += __shfl_xor_sync(0xffffffffu, rl0, 1);
    rl0 += __shfl_xor_sync(0xffffffffu, rl0, 2);
    rl1 += __shfl_xor_sync(0xffffffffu, rl1, 1);
    rl1 += __shfl_xor_sync(0xffffffffu, rl1, 2);
    float inv0 = 1.0f / rl0, inv1 = 1.0f / rl1;
    const float L2E = 1.4426950408889634f;
    #pragma unroll
    for (int og = 0; og < 16; og++) {
        int d = og * 8 + (lane & 3) * 2;
        // row 0
        {
            float2 gt = *(const float2*)&qraw[((size_t)(b * T_ + qp0) * H_ + h) * 256 + 128 + d];
            float s0v = 1.0f / (1.0f + ex2f(-gt.x * L2E));
            float s1v = 1.0f / (1.0f + ex2f(-gt.y * L2E));
            uint32_t hv = f22h(oacc[og][0] * inv0 * s0v, oacc[og][1] * inv0 * s1v);
            size_t o = (size_t)(b * T_ + qp0) * (H_ * KH) + h * KH + d;
            *(uint32_t*)&ao[o] = hv;
        }
        // row 1
        {
            float2 gt = *(const float2*)&qraw[((size_t)(b * T_ + qp1) * H_ + h) * 256 + 128 + d];
            float s0v = 1.0f / (1.0f + ex2f(-gt.x * L2E));
            float s1v = 1.0f / (1.0f + ex2f(-gt.y * L2E));
            uint32_t hv = f22h(oacc[og][2] * inv1 * s0v, oacc[og][3] * inv1 * s1v);
            size_t o = (size_t)(b * T_ + qp1) * (H_ * KH) + h * KH + d;
            *(uint32_t*)&ao[o] = hv;
        }
    }
}

// ---------------- launch -----------------------------------------------------
extern "C" void kernel_launch(void* const* d_in, const int* in_sizes, int n_in,
                              void* d_out, int out_size) {
    const float* hidden = (const float*)d_in[0];
    const float* cosp   = (const float*)d_in[1];
    const float* sinp   = (const float*)d_in[2];
    const int*   seg    = (const int*)d_in[3];
    const float* Wq = (const float*)d_in[5];
    const float* Wk = (const float*)d_in[6];
    const float* Wv = (const float*)d_in[7];
    const float* Wo = (const float*)d_in[8];
    const float* qw = (const float*)d_in[9];
    const float* kw = (const float*)d_in[10];
    float* out = (float*)d_out;

    float *qraw, *kraw;
    __half *hid, *wqh, *wql, *wkh, *wkl, *wvh, *wvl, *woh, *wol;
    __half *qb, *kbh, *kbl, *vb, *ao;
    cudaGetSymbolAddress((void**)&qraw, g_qraw);
    cudaGetSymbolAddress((void**)&kraw, g_kraw);
    cudaGetSymbolAddress((void**)&hid, g_hid);
    cudaGetSymbolAddress((void**)&wqh, g_wq_h);   cudaGetSymbolAddress((void**)&wql, g_wq_l);
    cudaGetSymbolAddress((void**)&wkh, g_wk_h);   cudaGetSymbolAddress((void**)&wkl, g_wk_l);
    cudaGetSymbolAddress((void**)&wvh, g_wv_h);   cudaGetSymbolAddress((void**)&wvl, g_wv_l);
    cudaGetSymbolAddress((void**)&woh, g_wo_h);   cudaGetSymbolAddress((void**)&wol, g_wo_l);
    cudaGetSymbolAddress((void**)&qb, g_qb);
    cudaGetSymbolAddress((void**)&kbh, g_kb_h);   cudaGetSymbolAddress((void**)&kbl, g_kb_l);
    cudaGetSymbolAddress((void**)&vb, g_vb);
    cudaGetSymbolAddress((void**)&ao, g_ao);

    cudaFuncSetAttribute(gemm_h2_kernel, cudaFuncAttributeMaxDynamicSharedMemorySize, G_SMEM);
    cudaFuncSetAttribute(attn_tc_kernel, cudaFuncAttributeMaxDynamicSharedMemorySize, AT_SMEM);

    // 1. convert/split operands to fp16
    cvt4_kernel<<<(B_*T_*D_) / 1024, 256>>>(hidden, hid);
    split4_kernel<<<(D_*H_*2*KH) / 1024, 256>>>(Wq, wqh, wql);
    split4_kernel<<<(D_*G_*KH) / 1024, 256>>>(Wk, wkh, wkl);
    split4_kernel<<<(D_*G_*KH) / 1024, 256>>>(Wv, wvh, wvl);
    split4_kernel<<<(H_*KH*D_) / 1024, 256>>>(Wo, woh, wol);

    // 2. merged Q/K/V projection (V written directly as fp16 [b,g,t,d])
    gemm_h2_kernel<<<dim3(20, 32), 256, G_SMEM>>>(hid, wqh, wql, wkh, wkl,
                                                  wvh, wvl, qraw, kraw, vb,
                                                  0, 2048, 1);

    // 3. rmsnorm + rope
    rope_norm_q_kernel<<<B_*T_*H_, 128>>>(qraw, cosp, sinp, qw, qb);
    rope_norm_k_kernel<<<B_*T_*G_, 128>>>(kraw, cosp, sinp, kw, kbh, kbl);

    // 4. attention (gate fused, 3 CTAs/SM)
    attn_tc_kernel<<<dim3(T_/64, B_*H_), 128, AT_SMEM>>>(qb, kbh, kbl, vb,
                                                         qraw, seg, ao);

    // 5. output projection
    gemm_h2_kernel<<<dim3(8, 32), 256, G_SMEM>>>(ao, woh, wol, nullptr, nullptr,
                                                 nullptr, nullptr, out, nullptr,
                                                 nullptr, 2048, 2048, 0);
}

// round 11
// speedup vs baseline: 6.8004x; 1.5150x over previous
#include <cuda_runtime.h>
#include <cuda_fp16.h>
#include <cstdint>

// Problem constants
#define B_  2
#define T_  2048
#define D_  2048
#define H_  16
#define G_  4
#define KH  128
#define EPS 1e-6f
static const float SCALE = 0.088388347648318447f; // 128^-0.5

// ---------------- scratch (device globals) -----------------------------------
__device__ float g_qraw[B_*T_*H_*2*KH];       // fp32 (gate kept here)
__device__ float g_kraw[B_*T_*G_*KH];
// fp16 single-precision operands everywhere
__device__ __half g_hid[B_*T_*D_];
__device__ __half g_wq[D_*H_*2*KH];
__device__ __half g_wk[D_*G_*KH];
__device__ __half g_wv[D_*G_*KH];
__device__ __half g_wo[H_*KH*D_];
__device__ __half g_qb[B_*H_*T_*KH];   // Q  [b,h,t,d]
__device__ __half g_kb[B_*G_*T_*KH];   // K  [b,g,t,d]
__device__ __half g_vb[B_*G_*T_*KH];   // V  [b,g,t,d]
__device__ __half g_ao[B_*T_*H_*KH];   // gated attn out

// ============================ helpers ========================================
__device__ __forceinline__ uint32_t smem_u32(const void* p) {
    return (uint32_t)__cvta_generic_to_shared((void*)p);
}
__device__ __forceinline__ void ldsm_x4(uint32_t* r, uint32_t addr) {
    asm volatile("ldmatrix.sync.aligned.m8n8.x4.shared.b16 {%0,%1,%2,%3}, [%4];"
        : "=r"(r[0]), "=r"(r[1]), "=r"(r[2]), "=r"(r[3]) : "r"(addr));
}
__device__ __forceinline__ void ldsm_x4_t(uint32_t* r, uint32_t addr) {
    asm volatile("ldmatrix.sync.aligned.m8n8.x4.trans.shared.b16 {%0,%1,%2,%3}, [%4];"
        : "=r"(r[0]), "=r"(r[1]), "=r"(r[2]), "=r"(r[3]) : "r"(addr));
}
__device__ __forceinline__ void mma2(float* d, const uint32_t* a, uint32_t b0, uint32_t b1) {
    asm volatile("mma.sync.aligned.m16n8k16.row.col.f32.f16.f16.f32 "
        "{%0,%1,%2,%3}, {%4,%5,%6,%7}, {%8,%9}, {%0,%1,%2,%3};"
        : "+f"(d[0]), "+f"(d[1]), "+f"(d[2]), "+f"(d[3])
        : "r"(a[0]), "r"(a[1]), "r"(a[2]), "r"(a[3]), "r"(b0), "r"(b1));
}
__device__ __forceinline__ void cpa16(uint32_t s, const void* g) {
    asm volatile("cp.async.cg.shared.global [%0], [%1], 16;" :: "r"(s), "l"(g));
}
__device__ __forceinline__ void cpa_commit() { asm volatile("cp.async.commit_group;"); }
template<int N> __device__ __forceinline__ void cpa_wait() {
    asm volatile("cp.async.wait_group %0;" :: "n"(N));
}
__device__ __forceinline__ float ex2f(float x) {
    float y; asm("ex2.approx.ftz.f32 %0, %1;" : "=f"(y) : "f"(x)); return y;
}
__device__ __forceinline__ uint32_t f22h(float a, float b) {
    __half2 t = __floats2half2_rn(a, b);
    return *reinterpret_cast<uint32_t*>(&t);
}

// ---------------- convert fp32 -> single fp16 --------------------------------
__global__ __launch_bounds__(256)
void cvt4_kernel(const float* __restrict__ in, __half* __restrict__ out) {
    size_t i = ((size_t)blockIdx.x * 256 + threadIdx.x) * 4;
    float4 v = *(const float4*)(in + i);
    *(uint32_t*)(out + i)     = f22h(v.x, v.y);
    *(uint32_t*)(out + i + 2) = f22h(v.z, v.w);
}

// ================= GEMM: C[M,N] = A @ B, single fp16, 1-term =================
// CTA 128x256, BK=64, 256 thr, 8 warps x (64x64), 3-stage cp.async.
// qkv mode: n-tiles 0-15 -> Wq (fp32 out), 16-17 -> Wk (fp32), 18-19 -> Wv
// (fp16 out, [b,g,t,d] remap).
#define GA_ST 144
#define GB_ST 528
#define G_A  0
#define G_B  18432
#define G_STAGE 52224
#define G_SMEM 156672

__global__ __launch_bounds__(256, 1)
void gemm_h1_kernel(const __half* __restrict__ A,
                    const __half* __restrict__ B0, const __half* __restrict__ Bk,
                    const __half* __restrict__ Bv,
                    float* __restrict__ Cq, float* __restrict__ Ck,
                    __half* __restrict__ Vo,
                    int N0, int Kd, int qkv) {
    extern __shared__ char sg[];
    uint32_t smb = smem_u32(sg);
    const int tid = threadIdx.x, wid = tid >> 5, lane = tid & 31;
    const int m0 = blockIdx.y * 128;
    const int x = blockIdx.x;

    const __half* bp;
    float* c = nullptr;
    int bst, n0, isV = 0;
    if (!qkv) { bp = B0; bst = N0; n0 = x * 256; c = Cq; }
    else if (x < 16) { bp = B0; bst = 4096; n0 = x * 256; c = Cq; }
    else if (x < 18) { bp = Bk; bst = 512; n0 = (x - 16) * 256; c = Ck; }
    else            { bp = Bv; bst = 512; n0 = (x - 18) * 256; isV = 1; }

    const int wm = (wid & 1) * 64, wn = (wid >> 1) * 64;

    float acc[4][8][4];
    #pragma unroll
    for (int i = 0; i < 4; i++)
        #pragma unroll
        for (int j = 0; j < 8; j++)
            #pragma unroll
            for (int e = 0; e < 4; e++) acc[i][j][e] = 0.0f;

    const int NC = Kd >> 6;   // 32

    #define G_ISSUE(ch) do { \
        int _sg_ = (ch) % 3; int _k0 = (ch) << 6; \
        uint32_t _st = smb + _sg_ * G_STAGE; \
        _Pragma("unroll") \
        for (int _j = 0; _j < 4; _j++) { \
            int _i = tid + 256 * _j; int _r = _i >> 3, _cc = _i & 7; \
            cpa16(_st + G_A + _r * GA_ST + _cc * 16, A + (size_t)(m0 + _r) * Kd + _k0 + _cc * 8); \
        } \
        _Pragma("unroll") \
        for (int _j = 0; _j < 8; _j++) { \
            int _i = tid + 256 * _j; int _r = _i >> 5, _cc = _i & 31; \
            cpa16(_st + G_B + _r * GB_ST + _cc * 16, bp + (size_t)(_k0 + _r) * bst + n0 + _cc * 8); \
        } \
        cpa_commit(); \
    } while (0)

    G_ISSUE(0);
    G_ISSUE(1);

    const int a_r = lane & 15;
    const int a_cb = (lane >> 4) * 16;
    const int b_k = (((lane >> 3) & 1) << 3) + (lane & 7);
    const int b_cb = ((lane >> 3) & 2) ? 16 : 0;

    for (int ch = 0; ch < NC; ch++) {
        if (ch + 2 < NC) { G_ISSUE(ch + 2); cpa_wait<2>(); }
        else if (ch + 1 < NC) { cpa_wait<1>(); }
        else cpa_wait<0>();
        __syncthreads();
        uint32_t st = smb + (ch % 3) * G_STAGE;
        uint32_t aB = st + G_A + (wm + a_r) * GA_ST + a_cb;
        uint32_t bB = st + G_B + b_k * GB_ST + wn * 2 + b_cb;

        #pragma unroll
        for (int kc = 0; kc < 4; kc++) {
            uint32_t ah[4][4];
            #pragma unroll
            for (int mi = 0; mi < 4; mi++)
                ldsm_x4(ah[mi], aB + mi * (16 * GA_ST) + kc * 32);
            #pragma unroll
            for (int bj = 0; bj < 4; bj++) {
                uint32_t bf[4];
                ldsm_x4_t(bf, bB + kc * (16 * GB_ST) + bj * 32);
                #pragma unroll
                for (int mi = 0; mi < 4; mi++) {
                    mma2(acc[mi][2*bj],   ah[mi], bf[0], bf[1]);
                    mma2(acc[mi][2*bj+1], ah[mi], bf[2], bf[3]);
                }
            }
        }
        __syncthreads();
    }

    const int r0 = m0 + wm + (lane >> 2);
    const int c0 = n0 + wn + (lane & 3) * 2;
    if (!isV) {
        #pragma unroll
        for (int mi = 0; mi < 4; mi++) {
            #pragma unroll
            for (int nj = 0; nj < 8; nj++) {
                float2 lo2; lo2.x = acc[mi][nj][0]; lo2.y = acc[mi][nj][1];
                float2 hi2; hi2.x = acc[mi][nj][2]; hi2.y = acc[mi][nj][3];
                *(float2*)&c[(size_t)(r0 + mi * 16) * bst + c0 + nj * 8] = lo2;
                *(float2*)&c[(size_t)(r0 + mi * 16 + 8) * bst + c0 + nj * 8] = hi2;
            }
        }
    } else {
        // V: fused fp16 convert + [b,g,t,d] remap
        #pragma unroll
        for (int mi = 0; mi < 4; mi++) {
            #pragma unroll
            for (int nj = 0; nj < 8; nj++) {
                int cg = c0 + nj * 8;
                int g = cg >> 7, d = cg & 127;
                #pragma unroll
                for (int half_ = 0; half_ < 2; half_++) {
                    int r = r0 + mi * 16 + half_ * 8;
                    int b = r >> 11, t = r & 2047;
                    uint32_t hv = f22h(acc[mi][nj][half_*2], acc[mi][nj][half_*2+1]);
                    size_t o = ((size_t)(b * G_ + g) * T_ + t) * KH + d;
                    *(uint32_t*)&Vo[o] = hv;
                }
            }
        }
    }
}

// ---------------- RMSNorm + RoPE -> fp16 (Q) ---------------------------------
__global__ __launch_bounds__(128)
void rope_norm_q_kernel(const float* __restrict__ qraw, const float* __restrict__ cosp,
                        const float* __restrict__ sinp, const float* __restrict__ w,
                        __half* __restrict__ outq) {
    const int idx = blockIdx.x;           // bt*H + h
    const int bt = idx >> 4, h = idx & 15;
    const int b = bt >> 11, t = bt & 2047;
    const int d = threadIdx.x;
    float x = qraw[(size_t)idx * 256 + d];
    float ss = x * x;
    #pragma unroll
    for (int o = 16; o; o >>= 1) ss += __shfl_xor_sync(0xffffffffu, ss, o);
    __shared__ float wsum[4];
    __shared__ float sn[128];
    if ((d & 31) == 0) wsum[d >> 5] = ss;
    __syncthreads();
    float tot = wsum[0] + wsum[1] + wsum[2] + wsum[3];
    float r = rsqrtf(tot * (1.0f / 128.0f) + EPS);
    sn[d] = x * r * w[d];
    __syncthreads();
    float c = cosp[(size_t)bt * KH + d];
    float s = sinp[(size_t)bt * KH + d];
    float out = (d < 64) ? sn[d] * c - sn[d + 64] * s : sn[d] * c + sn[d - 64] * s;
    size_t o = ((size_t)(b * H_ + h) * T_ + t) * KH + d;
    outq[o] = __float2half_rn(out);
}

// ---------------- RMSNorm + RoPE -> fp16 (K) ---------------------------------
__global__ __launch_bounds__(128)
void rope_norm_k_kernel(const float* __restrict__ kraw, const float* __restrict__ cosp,
                        const float* __restrict__ sinp, const float* __restrict__ w,
                        __half* __restrict__ outk) {
    const int idx = blockIdx.x;           // bt*G + g
    const int bt = idx >> 2, g = idx & 3;
    const int b = bt >> 11, t = bt & 2047;
    const int d = threadIdx.x;
    float x = kraw[(size_t)idx * 128 + d];
    float ss = x * x;
    #pragma unroll
    for (int o = 16; o; o >>= 1) ss += __shfl_xor_sync(0xffffffffu, ss, o);
    __shared__ float wsum[4];
    __shared__ float sn[128];
    if ((d & 31) == 0) wsum[d >> 5] = ss;
    __syncthreads();
    float tot = wsum[0] + wsum[1] + wsum[2] + wsum[3];
    float r = rsqrtf(tot * (1.0f / 128.0f) + EPS);
    sn[d] = x * r * w[d];
    __syncthreads();
    float c = cosp[(size_t)bt * KH + d];
    float s = sinp[(size_t)bt * KH + d];
    float out = (d < 64) ? sn[d] * c - sn[d + 64] * s : sn[d] * c + sn[d - 64] * s;
    size_t o = ((size_t)(b * G_ + g) * T_ + t) * KH + d;
    outk[o] = __float2half_rn(out);
}

// ================= tensor-core flash attention (all single fp16) =============
// CTA: 64 q-rows, 32-key tiles, 128 threads (4 warps x 16 rows), 2-stage.
// S = Q*K 1-term, PV 1-term.
#define AT_ST 272
#define AT_KV 17408            // stage base (after Q 64x272)
#define AT_KVSTG 17408         // per stage: K, V each 32x272
#define AT_SV  8704            // V offset within stage
#define AT_SEG 52224
#define AT_SMEM 52480

__global__ __launch_bounds__(128, 4)
void attn_tc_kernel(const __half* __restrict__ qv, const __half* __restrict__ kv,
                    const __half* __restrict__ vv,
                    const float* __restrict__ qraw, const int* __restrict__ seg,
                    __half* __restrict__ ao) {
    extern __shared__ char sa[];
    uint32_t smb = smem_u32(sa);
    const int tid = threadIdx.x, wid = tid >> 5, lane = tid & 31;
    const int qt = (int)(gridDim.x - 1 - blockIdx.x);   // heavy tiles first
    const int q0 = qt * 64;
    const int bh_ = blockIdx.y;
    const int b = bh_ >> 4, h = bh_ & 15;
    const int g = h >> 2;
    const int wm = wid * 16;

    const __half* qb  = qv + ((size_t)(b * H_ + h) * T_ + q0) * KH;
    const __half* kb  = kv + (size_t)(b * G_ + g) * T_ * KH;
    const __half* vb  = vv + (size_t)(b * G_ + g) * T_ * KH;

    // Q prologue loads (64 rows x 128 fp16)
    #pragma unroll
    for (int j = 0; j < 8; j++) {
        int i = tid + 128 * j; int r = i >> 4, cc = i & 15;
        cpa16(smb + r * AT_ST + cc * 16, qb + (size_t)r * KH + cc * 8);
    }

    const int nT = (q0 + 64) / 32;

    #define AT_ISSUE(t) do { \
        int _s = (t) & 1; int _s0 = (t) * 32; \
        uint32_t _bs = smb + AT_KV + _s * AT_KVSTG; \
        _Pragma("unroll") \
        for (int _j = 0; _j < 4; _j++) { \
            int _i = tid + 128 * _j; int _r = _i >> 4, _cc = _i & 15; \
            size_t _go = (size_t)(_s0 + _r) * KH + _cc * 8; \
            cpa16(_bs + _r * AT_ST + _cc * 16, kb + _go); \
            cpa16(_bs + AT_SV + _r * AT_ST + _cc * 16, vb + _go); \
        } \
        if (tid < 8) cpa16(smb + AT_SEG + _s * 128 + tid * 16, seg + (size_t)b * T_ + _s0 + tid * 4); \
        cpa_commit(); \
    } while (0)

    AT_ISSUE(0);

    const int qp0 = q0 + wm + (lane >> 2), qp1 = qp0 + 8;
    const int qs0 = seg[(size_t)b * T_ + qp0];
    const int qs1 = seg[(size_t)b * T_ + qp1];

    float rm0 = -1e30f, rm1 = -1e30f, rl0 = 0.0f, rl1 = 0.0f;
    float oacc[16][4];
    #pragma unroll
    for (int i = 0; i < 16; i++)
        #pragma unroll
        for (int e = 0; e < 4; e++) oacc[i][e] = 0.0f;

    const uint32_t aQ = smb + (wm + (lane & 15)) * AT_ST + (lane >> 4) * 16;
    const int vb_k = (((lane >> 3) & 1) << 3) + (lane & 7);
    const int vb_cb = ((lane >> 3) & 2) ? 16 : 0;
    const float SC = SCALE * 1.4426950408889634f;
    const float NEGINF = -__int_as_float(0x7f800000);

    for (int t = 0; t < nT; t++) {
        if (t + 1 < nT) { AT_ISSUE(t + 1); cpa_wait<1>(); }
        else cpa_wait<0>();
        __syncthreads();
        const int s0 = t * 32;
        uint32_t kst = smb + AT_KV + (t & 1) * AT_KVSTG;
        const int* kseg = (const int*)(sa + AT_SEG + (t & 1) * 128);

        // ---- S = Q K^T (1-term) ----
        float sacc[4][4];
        #pragma unroll
        for (int i = 0; i < 4; i++)
            #pragma unroll
            for (int e = 0; e < 4; e++) sacc[i][e] = 0.0f;

        #pragma unroll
        for (int kc = 0; kc < 8; kc++) {
            uint32_t aq[4];
            ldsm_x4(aq, aQ + kc * 32);
            #pragma unroll
            for (int ng = 0; ng < 2; ng++) {
                uint32_t kf[4];
                uint32_t ka = kst + (ng * 16 + (lane & 15)) * AT_ST + (lane >> 4) * 16 + kc * 32;
                ldsm_x4(kf, ka);
                mma2(sacc[2*ng],   aq, kf[0], kf[2]);
                mma2(sacc[2*ng+1], aq, kf[1], kf[3]);
            }
        }

        // ---- scale + mask ----
        const int lc = (lane & 3) * 2;
        #pragma unroll
        for (int gi = 0; gi < 4; gi++) {
            int c0c = s0 + gi * 8 + lc, c1c = c0c + 1;
            int ks0 = kseg[gi * 8 + lc], ks1 = kseg[gi * 8 + lc + 1];
            float v;
            v = sacc[gi][0] * SC; sacc[gi][0] = (c0c <= qp0 && ks0 == qs0) ? v : NEGINF;
            v = sacc[gi][1] * SC; sacc[gi][1] = (c1c <= qp0 && ks1 == qs0) ? v : NEGINF;
            v = sacc[gi][2] * SC; sacc[gi][2] = (c0c <= qp1 && ks0 == qs1) ? v : NEGINF;
            v = sacc[gi][3] * SC; sacc[gi][3] = (c1c <= qp1 && ks1 == qs1) ? v : NEGINF;
        }

        // ---- online softmax ----
        float mx0 = NEGINF, mx1 = NEGINF;
        #pragma unroll
        for (int gi = 0; gi < 4; gi++) {
            mx0 = fmaxf(mx0, fmaxf(sacc[gi][0], sacc[gi][1]));
            mx1 = fmaxf(mx1, fmaxf(sacc[gi][2], sacc[gi][3]));
        }
        mx0 = fmaxf(mx0, __shfl_xor_sync(0xffffffffu, mx0, 1));
        mx0 = fmaxf(mx0, __shfl_xor_sync(0xffffffffu, mx0, 2));
        mx1 = fmaxf(mx1, __shfl_xor_sync(0xffffffffu, mx1, 1));
        mx1 = fmaxf(mx1, __shfl_xor_sync(0xffffffffu, mx1, 2));
        float nm0 = fmaxf(rm0, mx0), nm1 = fmaxf(rm1, mx1);
        float al0 = ex2f(rm0 - nm0), al1 = ex2f(rm1 - nm1);
        rm0 = nm0; rm1 = nm1;
        float sum0 = 0.0f, sum1 = 0.0f;
        #pragma unroll
        for (int gi = 0; gi < 4; gi++) {
            float p;
            p = ex2f(sacc[gi][0] - nm0); sum0 += p; sacc[gi][0] = p;
            p = ex2f(sacc[gi][1] - nm0); sum0 += p; sacc[gi][1] = p;
            p = ex2f(sacc[gi][2] - nm1); sum1 += p; sacc[gi][2] = p;
            p = ex2f(sacc[gi][3] - nm1); sum1 += p; sacc[gi][3] = p;
        }
        rl0 = rl0 * al0 + sum0;
        rl1 = rl1 * al1 + sum1;
        #pragma unroll
        for (int og = 0; og < 16; og++) {
            oacc[og][0] *= al0; oacc[og][1] *= al0;
            oacc[og][2] *= al1; oacc[og][3] *= al1;
        }

        // ---- O += P V (1-term) ----
        #pragma unroll
        for (int kc2 = 0; kc2 < 2; kc2++) {
            uint32_t pa[4];
            pa[0] = f22h(sacc[2*kc2][0],   sacc[2*kc2][1]);
            pa[1] = f22h(sacc[2*kc2][2],   sacc[2*kc2][3]);
            pa[2] = f22h(sacc[2*kc2+1][0], sacc[2*kc2+1][1]);
            pa[3] = f22h(sacc[2*kc2+1][2], sacc[2*kc2+1][3]);
            uint32_t vbase = kst + AT_SV + (kc2 * 16 + vb_k) * AT_ST + vb_cb;
            #pragma unroll
            for (int nd = 0; nd < 8; nd++) {
                uint32_t vbf[4];
                ldsm_x4_t(vbf, vbase + nd * 32);
                mma2(oacc[2*nd],   pa, vbf[0], vbf[1]);
                mma2(oacc[2*nd+1], pa, vbf[2], vbf[3]);
            }
        }
        __syncthreads();
    }

    // ---- epilogue: normalize, gate, convert to fp16 ----
    rl0 += __shfl_xor_sync(0xffffffffu, rl0, 1);
    rl0 += __shfl_xor_sync(0xffffffffu, rl0, 2);
    rl1 += __shfl_xor_sync(0xffffffffu, rl1, 1);
    rl1 += __shfl_xor_sync(0xffffffffu, rl1, 2);
    float inv0 = 1.0f / rl0, inv1 = 1.0f / rl1;
    const float L2E = 1.4426950408889634f;
    #pragma unroll
    for (int og = 0; og < 16; og++) {
        int d = og * 8 + (lane & 3) * 2;
        // row 0
        {
            float2 gt = *(const float2*)&qraw[((size_t)(b * T_ + qp0) * H_ + h) * 256 + 128 + d];
            float s0v = 1.0f / (1.0f + ex2f(-gt.x * L2E));
            float s1v = 1.0f / (1.0f + ex2f(-gt.y * L2E));
            uint32_t hv = f22h(oacc[og][0] * inv0 * s0v, oacc[og][1] * inv0 * s1v);
            size_t o = (size_t)(b * T_ + qp0) * (H_ * KH) + h * KH + d;
            *(uint32_t*)&ao[o] = hv;
        }
        // row 1
        {
            float2 gt = *(const float2*)&qraw[((size_t)(b * T_ + qp1) * H_ + h) * 256 + 128 + d];
            float s0v = 1.0f / (1.0f + ex2f(-gt.x * L2E));
            float s1v = 1.0f / (1.0f + ex2f(-gt.y * L2E));
            uint32_t hv = f22h(oacc[og][2] * inv1 * s0v, oacc[og][3] * inv1 * s1v);
            size_t o = (size_t)(b * T_ + qp1) * (H_ * KH) + h * KH + d;
            *(uint32_t*)&ao[o] = hv;
        }
    }
}

// ---------------- launch -----------------------------------------------------
extern "C" void kernel_launch(void* const* d_in, const int* in_sizes, int n_in,
                              void* d_out, int out_size) {
    const float* hidden = (const float*)d_in[0];
    const float* cosp   = (const float*)d_in[1];
    const float* sinp   = (const float*)d_in[2];
    const int*   seg    = (const int*)d_in[3];
    const float* Wq = (const float*)d_in[5];
    const float* Wk = (const float*)d_in[6];
    const float* Wv = (const float*)d_in[7];
    const float* Wo = (const float*)d_in[8];
    const float* qw = (const float*)d_in[9];
    const float* kw = (const float*)d_in[10];
    float* out = (float*)d_out;

    float *qraw, *kraw;
    __half *hid, *wq, *wk, *wv, *wo, *qb, *kb, *vb, *ao;
    cudaGetSymbolAddress((void**)&qraw, g_qraw);
    cudaGetSymbolAddress((void**)&kraw, g_kraw);
    cudaGetSymbolAddress((void**)&hid, g_hid);
    cudaGetSymbolAddress((void**)&wq, g_wq);
    cudaGetSymbolAddress((void**)&wk, g_wk);
    cudaGetSymbolAddress((void**)&wv, g_wv);
    cudaGetSymbolAddress((void**)&wo, g_wo);
    cudaGetSymbolAddress((void**)&qb, g_qb);
    cudaGetSymbolAddress((void**)&kb, g_kb);
    cudaGetSymbolAddress((void**)&vb, g_vb);
    cudaGetSymbolAddress((void**)&ao, g_ao);

    cudaFuncSetAttribute(gemm_h1_kernel, cudaFuncAttributeMaxDynamicSharedMemorySize, G_SMEM);
    cudaFuncSetAttribute(attn_tc_kernel, cudaFuncAttributeMaxDynamicSharedMemorySize, AT_SMEM);

    // 1. convert operands to fp16
    cvt4_kernel<<<(B_*T_*D_) / 1024, 256>>>(hidden, hid);
    cvt4_kernel<<<(D_*H_*2*KH) / 1024, 256>>>(Wq, wq);
    cvt4_kernel<<<(D_*G_*KH) / 1024, 256>>>(Wk, wk);
    cvt4_kernel<<<(D_*G_*KH) / 1024, 256>>>(Wv, wv);
    cvt4_kernel<<<(H_*KH*D_) / 1024, 256>>>(Wo, wo);

    // 2. merged Q/K/V projection (V written directly as fp16 [b,g,t,d])
    gemm_h1_kernel<<<dim3(20, 32), 256, G_SMEM>>>(hid, wq, wk, wv,
                                                  qraw, kraw, vb, 0, 2048, 1);

    // 3. rmsnorm + rope
    rope_norm_q_kernel<<<B_*T_*H_, 128>>>(qraw, cosp, sinp, qw, qb);
    rope_norm_k_kernel<<<B_*T_*G_, 128>>>(kraw, cosp, sinp, kw, kb);

    // 4. attention (gate fused, 4 CTAs/SM)
    attn_tc_kernel<<<dim3(T_/64, B_*H_), 128, AT_SMEM>>>(qb, kb, vb, qraw, seg, ao);

    // 5. output projection
    gemm_h1_kernel<<<dim3(8, 32), 256, G_SMEM>>>(ao, wo, nullptr, nullptr,
                                                 out, nullptr, nullptr, 2048, 2048, 0);
}

// round 12
// speedup vs baseline: 8.4719x; 1.2458x over previous
#include <cuda_runtime.h>
#include <cuda_fp16.h>
#include <cstdint>

// Problem constants
#define B_  2
#define T_  2048
#define D_  2048
#define H_  16
#define G_  4
#define KH  128
#define EPS 1e-6f
static const float SCALE = 0.088388347648318447f; // 128^-0.5

// ---------------- scratch (device globals) -----------------------------------
__device__ float g_qraw[B_*T_*H_*2*KH];       // fp32 (gate kept here)
__device__ float g_kraw[B_*T_*G_*KH];
__device__ __half g_hid[B_*T_*D_];
__device__ __half g_wq[D_*H_*2*KH];
__device__ __half g_wk[D_*G_*KH];
__device__ __half g_wv[D_*G_*KH];
__device__ __half g_wo[H_*KH*D_];
__device__ __half g_qb[B_*H_*T_*KH];   // Q  [b,h,t,d]
__device__ __half g_kb[B_*G_*T_*KH];   // K  [b,g,t,d]
__device__ __half g_vb[B_*G_*T_*KH];   // V  [b,g,t,d]
__device__ __half g_ao[B_*T_*H_*KH];   // gated attn out

// ============================ helpers ========================================
__device__ __forceinline__ uint32_t smem_u32(const void* p) {
    return (uint32_t)__cvta_generic_to_shared((void*)p);
}
__device__ __forceinline__ void ldsm_x4(uint32_t* r, uint32_t addr) {
    asm volatile("ldmatrix.sync.aligned.m8n8.x4.shared.b16 {%0,%1,%2,%3}, [%4];"
        : "=r"(r[0]), "=r"(r[1]), "=r"(r[2]), "=r"(r[3]) : "r"(addr));
}
__device__ __forceinline__ void ldsm_x4_t(uint32_t* r, uint32_t addr) {
    asm volatile("ldmatrix.sync.aligned.m8n8.x4.trans.shared.b16 {%0,%1,%2,%3}, [%4];"
        : "=r"(r[0]), "=r"(r[1]), "=r"(r[2]), "=r"(r[3]) : "r"(addr));
}
__device__ __forceinline__ void mma2(float* d, const uint32_t* a, uint32_t b0, uint32_t b1) {
    asm volatile("mma.sync.aligned.m16n8k16.row.col.f32.f16.f16.f32 "
        "{%0,%1,%2,%3}, {%4,%5,%6,%7}, {%8,%9}, {%0,%1,%2,%3};"
        : "+f"(d[0]), "+f"(d[1]), "+f"(d[2]), "+f"(d[3])
        : "r"(a[0]), "r"(a[1]), "r"(a[2]), "r"(a[3]), "r"(b0), "r"(b1));
}
__device__ __forceinline__ void cpa16(uint32_t s, const void* g) {
    asm volatile("cp.async.cg.shared.global [%0], [%1], 16;" :: "r"(s), "l"(g));
}
__device__ __forceinline__ void cpa_commit() { asm volatile("cp.async.commit_group;"); }
template<int N> __device__ __forceinline__ void cpa_wait() {
    asm volatile("cp.async.wait_group %0;" :: "n"(N));
}
__device__ __forceinline__ float ex2f(float x) {
    float y; asm("ex2.approx.ftz.f32 %0, %1;" : "=f"(y) : "f"(x)); return y;
}
__device__ __forceinline__ uint32_t f22h(float a, float b) {
    __half2 t = __floats2half2_rn(a, b);
    return *reinterpret_cast<uint32_t*>(&t);
}

// ---------------- convert fp32 -> single fp16 --------------------------------
__global__ __launch_bounds__(256)
void cvt4_kernel(const float* __restrict__ in, __half* __restrict__ out) {
    size_t i = ((size_t)blockIdx.x * 256 + threadIdx.x) * 4;
    float4 v = *(const float4*)(in + i);
    *(uint32_t*)(out + i)     = f22h(v.x, v.y);
    *(uint32_t*)(out + i + 2) = f22h(v.z, v.w);
}

// ================= GEMM: C[M,N] = A @ B, single fp16, 1-term =================
// CTA 128x256, BK=64, 256 thr, 8 warps x (64x64), 3-stage cp.async.
#define GA_ST 144
#define GB_ST 528
#define G_A  0
#define G_B  18432
#define G_STAGE 52224
#define G_SMEM 156672

__global__ __launch_bounds__(256, 1)
void gemm_h1_kernel(const __half* __restrict__ A,
                    const __half* __restrict__ B0, const __half* __restrict__ Bk,
                    const __half* __restrict__ Bv,
                    float* __restrict__ Cq, float* __restrict__ Ck,
                    __half* __restrict__ Vo,
                    int N0, int Kd, int qkv) {
    extern __shared__ char sg[];
    uint32_t smb = smem_u32(sg);
    const int tid = threadIdx.x, wid = tid >> 5, lane = tid & 31;
    const int m0 = blockIdx.y * 128;
    const int x = blockIdx.x;

    const __half* bp;
    float* c = nullptr;
    int bst, n0, isV = 0;
    if (!qkv) { bp = B0; bst = N0; n0 = x * 256; c = Cq; }
    else if (x < 16) { bp = B0; bst = 4096; n0 = x * 256; c = Cq; }
    else if (x < 18) { bp = Bk; bst = 512; n0 = (x - 16) * 256; c = Ck; }
    else            { bp = Bv; bst = 512; n0 = (x - 18) * 256; isV = 1; }

    const int wm = (wid & 1) * 64, wn = (wid >> 1) * 64;

    float acc[4][8][4];
    #pragma unroll
    for (int i = 0; i < 4; i++)
        #pragma unroll
        for (int j = 0; j < 8; j++)
            #pragma unroll
            for (int e = 0; e < 4; e++) acc[i][j][e] = 0.0f;

    const int NC = Kd >> 6;   // 32

    #define G_ISSUE(ch) do { \
        int _sg_ = (ch) % 3; int _k0 = (ch) << 6; \
        uint32_t _st = smb + _sg_ * G_STAGE; \
        _Pragma("unroll") \
        for (int _j = 0; _j < 4; _j++) { \
            int _i = tid + 256 * _j; int _r = _i >> 3, _cc = _i & 7; \
            cpa16(_st + G_A + _r * GA_ST + _cc * 16, A + (size_t)(m0 + _r) * Kd + _k0 + _cc * 8); \
        } \
        _Pragma("unroll") \
        for (int _j = 0; _j < 8; _j++) { \
            int _i = tid + 256 * _j; int _r = _i >> 5, _cc = _i & 31; \
            cpa16(_st + G_B + _r * GB_ST + _cc * 16, bp + (size_t)(_k0 + _r) * bst + n0 + _cc * 8); \
        } \
        cpa_commit(); \
    } while (0)

    G_ISSUE(0);
    G_ISSUE(1);

    const int a_r = lane & 15;
    const int a_cb = (lane >> 4) * 16;
    const int b_k = (((lane >> 3) & 1) << 3) + (lane & 7);
    const int b_cb = ((lane >> 3) & 2) ? 16 : 0;

    for (int ch = 0; ch < NC; ch++) {
        if (ch + 2 < NC) { G_ISSUE(ch + 2); cpa_wait<2>(); }
        else if (ch + 1 < NC) { cpa_wait<1>(); }
        else cpa_wait<0>();
        __syncthreads();
        uint32_t st = smb + (ch % 3) * G_STAGE;
        uint32_t aB = st + G_A + (wm + a_r) * GA_ST + a_cb;
        uint32_t bB = st + G_B + b_k * GB_ST + wn * 2 + b_cb;

        #pragma unroll
        for (int kc = 0; kc < 4; kc++) {
            uint32_t ah[4][4];
            #pragma unroll
            for (int mi = 0; mi < 4; mi++)
                ldsm_x4(ah[mi], aB + mi * (16 * GA_ST) + kc * 32);
            #pragma unroll
            for (int bj = 0; bj < 4; bj++) {
                uint32_t bf[4];
                ldsm_x4_t(bf, bB + kc * (16 * GB_ST) + bj * 32);
                #pragma unroll
                for (int mi = 0; mi < 4; mi++) {
                    mma2(acc[mi][2*bj],   ah[mi], bf[0], bf[1]);
                    mma2(acc[mi][2*bj+1], ah[mi], bf[2], bf[3]);
                }
            }
        }
        __syncthreads();
    }

    const int r0 = m0 + wm + (lane >> 2);
    const int c0 = n0 + wn + (lane & 3) * 2;
    if (!isV) {
        #pragma unroll
        for (int mi = 0; mi < 4; mi++) {
            #pragma unroll
            for (int nj = 0; nj < 8; nj++) {
                float2 lo2; lo2.x = acc[mi][nj][0]; lo2.y = acc[mi][nj][1];
                float2 hi2; hi2.x = acc[mi][nj][2]; hi2.y = acc[mi][nj][3];
                *(float2*)&c[(size_t)(r0 + mi * 16) * bst + c0 + nj * 8] = lo2;
                *(float2*)&c[(size_t)(r0 + mi * 16 + 8) * bst + c0 + nj * 8] = hi2;
            }
        }
    } else {
        #pragma unroll
        for (int mi = 0; mi < 4; mi++) {
            #pragma unroll
            for (int nj = 0; nj < 8; nj++) {
                int cg = c0 + nj * 8;
                int g = cg >> 7, d = cg & 127;
                #pragma unroll
                for (int half_ = 0; half_ < 2; half_++) {
                    int r = r0 + mi * 16 + half_ * 8;
                    int b = r >> 11, t = r & 2047;
                    uint32_t hv = f22h(acc[mi][nj][half_*2], acc[mi][nj][half_*2+1]);
                    size_t o = ((size_t)(b * G_ + g) * T_ + t) * KH + d;
                    *(uint32_t*)&Vo[o] = hv;
                }
            }
        }
    }
}

// -------- RMSNorm + RoPE, warp-per-row (shuffle-only, no smem) ---------------
// nHeads = H_ (Q, rowStride 256) or G_ (K, rowStride 128). 8 warps/block.
template<int NH, int RST>
__global__ __launch_bounds__(256)
void rope_norm_w_kernel(const float* __restrict__ raw, const float* __restrict__ cosp,
                        const float* __restrict__ sinp, const float* __restrict__ w,
                        __half* __restrict__ outp) {
    const int idx = blockIdx.x * 8 + (threadIdx.x >> 5);   // row over B*T*NH
    const int lane = threadIdx.x & 31;
    const int bt = idx / NH, hh = idx % NH;
    const int b = bt >> 11, t = bt & 2047;
    const float* row = raw + (size_t)idx * RST;

    float4 a = *(const float4*)(row + lane * 4);
    float4 w4 = *(const float4*)(w + lane * 4);
    float ss = a.x*a.x + a.y*a.y + a.z*a.z + a.w*a.w;
    #pragma unroll
    for (int o = 16; o; o >>= 1) ss += __shfl_xor_sync(0xffffffffu, ss, o);
    float r = rsqrtf(ss * (1.0f / 128.0f) + EPS);
    float4 n;
    n.x = a.x * r * w4.x; n.y = a.y * r * w4.y;
    n.z = a.z * r * w4.z; n.w = a.w * r * w4.w;
    // partner values at d ^ 64 live on lane ^ 16
    float4 p;
    p.x = __shfl_xor_sync(0xffffffffu, n.x, 16);
    p.y = __shfl_xor_sync(0xffffffffu, n.y, 16);
    p.z = __shfl_xor_sync(0xffffffffu, n.z, 16);
    p.w = __shfl_xor_sync(0xffffffffu, n.w, 16);
    const float* cr = cosp + (size_t)bt * KH + lane * 4;
    const float* sr = sinp + (size_t)bt * KH + lane * 4;
    float4 c4 = *(const float4*)cr;
    float4 s4 = *(const float4*)sr;
    float4 o4;
    if (lane < 16) {
        o4.x = n.x * c4.x - p.x * s4.x; o4.y = n.y * c4.y - p.y * s4.y;
        o4.z = n.z * c4.z - p.z * s4.z; o4.w = n.w * c4.w - p.w * s4.w;
    } else {
        o4.x = n.x * c4.x + p.x * s4.x; o4.y = n.y * c4.y + p.y * s4.y;
        o4.z = n.z * c4.z + p.z * s4.z; o4.w = n.w * c4.w + p.w * s4.w;
    }
    size_t o = ((size_t)(b * NH + hh) * T_ + t) * KH + lane * 4;
    uint2 hv;
    hv.x = f22h(o4.x, o4.y);
    hv.y = f22h(o4.z, o4.w);
    *(uint2*)&outp[o] = hv;
}

// ================= tensor-core flash attention (segment-skip) ================
// CTA: 64 q-rows, 32-key tiles, 128 threads (4 warps x 16 rows), 2-stage.
#define AT_ST 272
#define AT_KV 17408
#define AT_KVSTG 17408
#define AT_SV  8704
#define AT_SEG 52224
#define AT_SMEM 52480

__global__ __launch_bounds__(128, 4)
void attn_tc_kernel(const __half* __restrict__ qv, const __half* __restrict__ kv,
                    const __half* __restrict__ vv,
                    const float* __restrict__ qraw, const int* __restrict__ seg,
                    __half* __restrict__ ao) {
    extern __shared__ char sa[];
    uint32_t smb = smem_u32(sa);
    const int tid = threadIdx.x, wid = tid >> 5, lane = tid & 31;
    const int qt = (int)(gridDim.x - 1 - blockIdx.x);   // heavy tiles first
    const int q0 = qt * 64;
    const int bh_ = blockIdx.y;
    const int b = bh_ >> 4, h = bh_ & 15;
    const int g = h >> 2;
    const int wm = wid * 16;

    const __half* qb  = qv + ((size_t)(b * H_ + h) * T_ + q0) * KH;
    const __half* kb  = kv + (size_t)(b * G_ + g) * T_ * KH;
    const __half* vb  = vv + (size_t)(b * G_ + g) * T_ * KH;
    const int* segb = seg + (size_t)b * T_;

    // segment skip: keys with seg < seg[q0] are masked for the whole q-tile.
    const int sq_min = segb[q0];
    int lo = 0, hi = q0;
    while (lo < hi) { int mid = (lo + hi) >> 1; if (segb[mid] < sq_min) lo = mid + 1; else hi = mid; }
    const int t0 = lo >> 5;

    // Q prologue loads (64 rows x 128 fp16)
    #pragma unroll
    for (int j = 0; j < 8; j++) {
        int i = tid + 128 * j; int r = i >> 4, cc = i & 15;
        cpa16(smb + r * AT_ST + cc * 16, qb + (size_t)r * KH + cc * 8);
    }

    const int nT = (q0 + 64) / 32;

    #define AT_ISSUE(t) do { \
        int _s = (t) & 1; int _s0 = (t) * 32; \
        uint32_t _bs = smb + AT_KV + _s * AT_KVSTG; \
        _Pragma("unroll") \
        for (int _j = 0; _j < 4; _j++) { \
            int _i = tid + 128 * _j; int _r = _i >> 4, _cc = _i & 15; \
            size_t _go = (size_t)(_s0 + _r) * KH + _cc * 8; \
            cpa16(_bs + _r * AT_ST + _cc * 16, kb + _go); \
            cpa16(_bs + AT_SV + _r * AT_ST + _cc * 16, vb + _go); \
        } \
        if (tid < 8) cpa16(smb + AT_SEG + _s * 128 + tid * 16, segb + _s0 + tid * 4); \
        cpa_commit(); \
    } while (0)

    AT_ISSUE(t0);

    const int qp0 = q0 + wm + (lane >> 2), qp1 = qp0 + 8;
    const int qs0 = segb[qp0];
    const int qs1 = segb[qp1];

    float rm0 = -1e30f, rm1 = -1e30f, rl0 = 0.0f, rl1 = 0.0f;
    float oacc[16][4];
    #pragma unroll
    for (int i = 0; i < 16; i++)
        #pragma unroll
        for (int e = 0; e < 4; e++) oacc[i][e] = 0.0f;

    const uint32_t aQ = smb + (wm + (lane & 15)) * AT_ST + (lane >> 4) * 16;
    const int vb_k = (((lane >> 3) & 1) << 3) + (lane & 7);
    const int vb_cb = ((lane >> 3) & 2) ? 16 : 0;
    const float SC = SCALE * 1.4426950408889634f;
    const float NEGINF = -__int_as_float(0x7f800000);

    for (int t = t0; t < nT; t++) {
        if (t + 1 < nT) { AT_ISSUE(t + 1); cpa_wait<1>(); }
        else cpa_wait<0>();
        __syncthreads();
        const int s0 = t * 32;
        uint32_t kst = smb + AT_KV + (t & 1) * AT_KVSTG;
        const int* kseg = (const int*)(sa + AT_SEG + (t & 1) * 128);

        // ---- S = Q K^T (1-term) ----
        float sacc[4][4];
        #pragma unroll
        for (int i = 0; i < 4; i++)
            #pragma unroll
            for (int e = 0; e < 4; e++) sacc[i][e] = 0.0f;

        #pragma unroll
        for (int kc = 0; kc < 8; kc++) {
            uint32_t aq[4];
            ldsm_x4(aq, aQ + kc * 32);
            #pragma unroll
            for (int ng = 0; ng < 2; ng++) {
                uint32_t kf[4];
                uint32_t ka = kst + (ng * 16 + (lane & 15)) * AT_ST + (lane >> 4) * 16 + kc * 32;
                ldsm_x4(kf, ka);
                mma2(sacc[2*ng],   aq, kf[0], kf[2]);
                mma2(sacc[2*ng+1], aq, kf[1], kf[3]);
            }
        }

        // ---- scale + mask ----
        const int lc = (lane & 3) * 2;
        #pragma unroll
        for (int gi = 0; gi < 4; gi++) {
            int c0c = s0 + gi * 8 + lc, c1c = c0c + 1;
            int ks0 = kseg[gi * 8 + lc], ks1 = kseg[gi * 8 + lc + 1];
            float v;
            v = sacc[gi][0] * SC; sacc[gi][0] = (c0c <= qp0 && ks0 == qs0) ? v : NEGINF;
            v = sacc[gi][1] * SC; sacc[gi][1] = (c1c <= qp0 && ks1 == qs0) ? v : NEGINF;
            v = sacc[gi][2] * SC; sacc[gi][2] = (c0c <= qp1 && ks0 == qs1) ? v : NEGINF;
            v = sacc[gi][3] * SC; sacc[gi][3] = (c1c <= qp1 && ks1 == qs1) ? v : NEGINF;
        }

        // ---- online softmax ----
        float mx0 = NEGINF, mx1 = NEGINF;
        #pragma unroll
        for (int gi = 0; gi < 4; gi++) {
            mx0 = fmaxf(mx0, fmaxf(sacc[gi][0], sacc[gi][1]));
            mx1 = fmaxf(mx1, fmaxf(sacc[gi][2], sacc[gi][3]));
        }
        mx0 = fmaxf(mx0, __shfl_xor_sync(0xffffffffu, mx0, 1));
        mx0 = fmaxf(mx0, __shfl_xor_sync(0xffffffffu, mx0, 2));
        mx1 = fmaxf(mx1, __shfl_xor_sync(0xffffffffu, mx1, 1));
        mx1 = fmaxf(mx1, __shfl_xor_sync(0xffffffffu, mx1, 2));
        float nm0 = fmaxf(rm0, mx0), nm1 = fmaxf(rm1, mx1);
        float al0 = ex2f(rm0 - nm0), al1 = ex2f(rm1 - nm1);
        rm0 = nm0; rm1 = nm1;
        float sum0 = 0.0f, sum1 = 0.0f;
        #pragma unroll
        for (int gi = 0; gi < 4; gi++) {
            float p;
            p = ex2f(sacc[gi][0] - nm0); sum0 += p; sacc[gi][0] = p;
            p = ex2f(sacc[gi][1] - nm0); sum0 += p; sacc[gi][1] = p;
            p = ex2f(sacc[gi][2] - nm1); sum1 += p; sacc[gi][2] = p;
            p = ex2f(sacc[gi][3] - nm1); sum1 += p; sacc[gi][3] = p;
        }
        rl0 = rl0 * al0 + sum0;
        rl1 = rl1 * al1 + sum1;
        #pragma unroll
        for (int og = 0; og < 16; og++) {
            oacc[og][0] *= al0; oacc[og][1] *= al0;
            oacc[og][2] *= al1; oacc[og][3] *= al1;
        }

        // ---- O += P V (1-term) ----
        #pragma unroll
        for (int kc2 = 0; kc2 < 2; kc2++) {
            uint32_t pa[4];
            pa[0] = f22h(sacc[2*kc2][0],   sacc[2*kc2][1]);
            pa[1] = f22h(sacc[2*kc2][2],   sacc[2*kc2][3]);
            pa[2] = f22h(sacc[2*kc2+1][0], sacc[2*kc2+1][1]);
            pa[3] = f22h(sacc[2*kc2+1][2], sacc[2*kc2+1][3]);
            uint32_t vbase = kst + AT_SV + (kc2 * 16 + vb_k) * AT_ST + vb_cb;
            #pragma unroll
            for (int nd = 0; nd < 8; nd++) {
                uint32_t vbf[4];
                ldsm_x4_t(vbf, vbase + nd * 32);
                mma2(oacc[2*nd],   pa, vbf[0], vbf[1]);
                mma2(oacc[2*nd+1], pa, vbf[2], vbf[3]);
            }
        }
        __syncthreads();
    }

    // ---- epilogue: normalize, gate, convert to fp16 ----
    rl0 += __shfl_xor_sync(0xffffffffu, rl0, 1);
    rl0 += __shfl_xor_sync(0xffffffffu, rl0, 2);
    rl1 += __shfl_xor_sync(0xffffffffu, rl1, 1);
    rl1 += __shfl_xor_sync(0xffffffffu, rl1, 2);
    float inv0 = 1.0f / rl0, inv1 = 1.0f / rl1;
    const float L2E = 1.4426950408889634f;
    #pragma unroll
    for (int og = 0; og < 16; og++) {
        int d = og * 8 + (lane & 3) * 2;
        {
            float2 gt = *(const float2*)&qraw[((size_t)(b * T_ + qp0) * H_ + h) * 256 + 128 + d];
            float s0v = 1.0f / (1.0f + ex2f(-gt.x * L2E));
            float s1v = 1.0f / (1.0f + ex2f(-gt.y * L2E));
            uint32_t hv = f22h(oacc[og][0] * inv0 * s0v, oacc[og][1] * inv0 * s1v);
            size_t o = (size_t)(b * T_ + qp0) * (H_ * KH) + h * KH + d;
            *(uint32_t*)&ao[o] = hv;
        }
        {
            float2 gt = *(const float2*)&qraw[((size_t)(b * T_ + qp1) * H_ + h) * 256 + 128 + d];
            float s0v = 1.0f / (1.0f + ex2f(-gt.x * L2E));
            float s1v = 1.0f / (1.0f + ex2f(-gt.y * L2E));
            uint32_t hv = f22h(oacc[og][2] * inv1 * s0v, oacc[og][3] * inv1 * s1v);
            size_t o = (size_t)(b * T_ + qp1) * (H_ * KH) + h * KH + d;
            *(uint32_t*)&ao[o] = hv;
        }
    }
}

// ---------------- launch -----------------------------------------------------
extern "C" void kernel_launch(void* const* d_in, const int* in_sizes, int n_in,
                              void* d_out, int out_size) {
    const float* hidden = (const float*)d_in[0];
    const float* cosp   = (const float*)d_in[1];
    const float* sinp   = (const float*)d_in[2];
    const int*   seg    = (const int*)d_in[3];
    const float* Wq = (const float*)d_in[5];
    const float* Wk = (const float*)d_in[6];
    const float* Wv = (const float*)d_in[7];
    const float* Wo = (const float*)d_in[8];
    const float* qw = (const float*)d_in[9];
    const float* kw = (const float*)d_in[10];
    float* out = (float*)d_out;

    float *qraw, *kraw;
    __half *hid, *wq, *wk, *wv, *wo, *qb, *kb, *vb, *ao;
    cudaGetSymbolAddress((void**)&qraw, g_qraw);
    cudaGetSymbolAddress((void**)&kraw, g_kraw);
    cudaGetSymbolAddress((void**)&hid, g_hid);
    cudaGetSymbolAddress((void**)&wq, g_wq);
    cudaGetSymbolAddress((void**)&wk, g_wk);
    cudaGetSymbolAddress((void**)&wv, g_wv);
    cudaGetSymbolAddress((void**)&wo, g_wo);
    cudaGetSymbolAddress((void**)&qb, g_qb);
    cudaGetSymbolAddress((void**)&kb, g_kb);
    cudaGetSymbolAddress((void**)&vb, g_vb);
    cudaGetSymbolAddress((void**)&ao, g_ao);

    cudaFuncSetAttribute(gemm_h1_kernel, cudaFuncAttributeMaxDynamicSharedMemorySize, G_SMEM);
    cudaFuncSetAttribute(attn_tc_kernel, cudaFuncAttributeMaxDynamicSharedMemorySize, AT_SMEM);

    // 1. convert operands to fp16
    cvt4_kernel<<<(B_*T_*D_) / 1024, 256>>>(hidden, hid);
    cvt4_kernel<<<(D_*H_*2*KH) / 1024, 256>>>(Wq, wq);
    cvt4_kernel<<<(D_*G_*KH) / 1024, 256>>>(Wk, wk);
    cvt4_kernel<<<(D_*G_*KH) / 1024, 256>>>(Wv, wv);
    cvt4_kernel<<<(H_*KH*D_) / 1024, 256>>>(Wo, wo);

    // 2. merged Q/K/V projection (V written directly as fp16 [b,g,t,d])
    gemm_h1_kernel<<<dim3(20, 32), 256, G_SMEM>>>(hid, wq, wk, wv,
                                                  qraw, kraw, vb, 0, 2048, 1);

    // 3. rmsnorm + rope (warp-per-row)
    rope_norm_w_kernel<H_, 256><<<(B_*T_*H_) / 8, 256>>>(qraw, cosp, sinp, qw, qb);
    rope_norm_w_kernel<G_, 128><<<(B_*T_*G_) / 8, 256>>>(kraw, cosp, sinp, kw, kb);

    // 4. attention (gate fused, segment skip, 4 CTAs/SM)
    attn_tc_kernel<<<dim3(T_/64, B_*H_), 128, AT_SMEM>>>(qb, kb, vb, qraw, seg, ao);

    // 5. output projection
    gemm_h1_kernel<<<dim3(8, 32), 256, G_SMEM>>>(ao, wo, nullptr, nullptr,
                                                 out, nullptr, nullptr, 2048, 2048, 0);
}

// round 15
// speedup vs baseline: 8.7587x; 1.0339x over previous
#include <cuda_runtime.h>
#include <cuda_fp16.h>
#include <cstdint>

// Problem constants
#define B_  2
#define T_  2048
#define D_  2048
#define H_  16
#define G_  4
#define KH  128
#define EPS 1e-6f
static const float SCALE = 0.088388347648318447f; // 128^-0.5

// ---------------- scratch (device globals) -----------------------------------
__device__ float g_qraw[B_*T_*H_*2*KH];       // fp32 (gate kept here)
__device__ float g_kraw[B_*T_*G_*KH];
__device__ __half g_hid[B_*T_*D_];
__device__ __half g_wq[D_*H_*2*KH];
__device__ __half g_wk[D_*G_*KH];
__device__ __half g_wv[D_*G_*KH];
__device__ __half g_wo[H_*KH*D_];
__device__ __half g_qb[B_*H_*T_*KH];   // Q  [b,h,t,d]
__device__ __half g_kb[B_*G_*T_*KH];   // K  [b,g,t,d]
__device__ __half g_vb[B_*G_*T_*KH];   // V  [b,g,t,d]
__device__ __half g_ao[B_*T_*H_*KH];   // gated attn out

// ============================ helpers ========================================
__device__ __forceinline__ uint32_t smem_u32(const void* p) {
    return (uint32_t)__cvta_generic_to_shared((void*)p);
}
__device__ __forceinline__ void ldsm_x4(uint32_t* r, uint32_t addr) {
    asm volatile("ldmatrix.sync.aligned.m8n8.x4.shared.b16 {%0,%1,%2,%3}, [%4];"
        : "=r"(r[0]), "=r"(r[1]), "=r"(r[2]), "=r"(r[3]) : "r"(addr));
}
__device__ __forceinline__ void ldsm_x4_t(uint32_t* r, uint32_t addr) {
    asm volatile("ldmatrix.sync.aligned.m8n8.x4.trans.shared.b16 {%0,%1,%2,%3}, [%4];"
        : "=r"(r[0]), "=r"(r[1]), "=r"(r[2]), "=r"(r[3]) : "r"(addr));
}
__device__ __forceinline__ void mma2(float* d, const uint32_t* a, uint32_t b0, uint32_t b1) {
    asm volatile("mma.sync.aligned.m16n8k16.row.col.f32.f16.f16.f32 "
        "{%0,%1,%2,%3}, {%4,%5,%6,%7}, {%8,%9}, {%0,%1,%2,%3};"
        : "+f"(d[0]), "+f"(d[1]), "+f"(d[2]), "+f"(d[3])
        : "r"(a[0]), "r"(a[1]), "r"(a[2]), "r"(a[3]), "r"(b0), "r"(b1));
}
__device__ __forceinline__ void cpa16(uint32_t s, const void* g) {
    asm volatile("cp.async.cg.shared.global [%0], [%1], 16;" :: "r"(s), "l"(g));
}
__device__ __forceinline__ void cpa_commit() { asm volatile("cp.async.commit_group;"); }
template<int N> __device__ __forceinline__ void cpa_wait() {
    asm volatile("cp.async.wait_group %0;" :: "n"(N));
}
__device__ __forceinline__ float ex2f(float x) {
    float y; asm("ex2.approx.ftz.f32 %0, %1;" : "=f"(y) : "f"(x)); return y;
}
__device__ __forceinline__ uint32_t f22h(float a, float b) {
    __half2 t = __floats2half2_rn(a, b);
    return *reinterpret_cast<uint32_t*>(&t);
}

// ---------------- merged convert fp32 -> fp16 (all 5 operands) ---------------
// region element counts: hid 8388608, wq 8388608, wk 1048576, wv 1048576,
// wo 4194304  -> total 23068672
#define CV_S0 8388608u
#define CV_S1 16777216u
#define CV_S2 17825792u
#define CV_S3 18874368u
#define CV_S4 23068672u
__global__ __launch_bounds__(256)
void cvt_all_kernel(const float* __restrict__ hid, const float* __restrict__ wq,
                    const float* __restrict__ wk, const float* __restrict__ wv,
                    const float* __restrict__ wo,
                    __half* __restrict__ oh, __half* __restrict__ oq,
                    __half* __restrict__ ok, __half* __restrict__ ov,
                    __half* __restrict__ oo) {
    size_t i = ((size_t)blockIdx.x * 256 + threadIdx.x) * 4;
    const float* in; __half* out; size_t off;
    if (i < CV_S0)      { in = hid; out = oh; off = i; }
    else if (i < CV_S1) { in = wq;  out = oq; off = i - CV_S0; }
    else if (i < CV_S2) { in = wk;  out = ok; off = i - CV_S1; }
    else if (i < CV_S3) { in = wv;  out = ov; off = i - CV_S2; }
    else                { in = wo;  out = oo; off = i - CV_S3; }
    float4 v = *(const float4*)(in + off);
    *(uint32_t*)(out + off)     = f22h(v.x, v.y);
    *(uint32_t*)(out + off + 2) = f22h(v.z, v.w);
}

// ================= GEMM: C[M,N] = A @ B, single fp16, 1-term =================
// CTA 128x256, BK=64, 256 thr, 8 warps x (64x64), 4-stage cp.async,
// ONE barrier per chunk.
#define GA_ST 144
#define GB_ST 528
#define G_A  0
#define G_B  18432
#define G_STAGE 52224
#define G_SMEM 208896

__global__ __launch_bounds__(256, 1)
void gemm_h1_kernel(const __half* __restrict__ A,
                    const __half* __restrict__ B0, const __half* __restrict__ Bk,
                    const __half* __restrict__ Bv,
                    float* __restrict__ Cq, float* __restrict__ Ck,
                    __half* __restrict__ Vo,
                    int N0, int Kd, int qkv) {
    extern __shared__ char sg[];
    uint32_t smb = smem_u32(sg);
    const int tid = threadIdx.x, wid = tid >> 5, lane = tid & 31;
    const int m0 = blockIdx.y * 128;
    const int x = blockIdx.x;

    const __half* bp;
    float* c = nullptr;
    int bst, n0, isV = 0;
    if (!qkv) { bp = B0; bst = N0; n0 = x * 256; c = Cq; }
    else if (x < 16) { bp = B0; bst = 4096; n0 = x * 256; c = Cq; }
    else if (x < 18) { bp = Bk; bst = 512; n0 = (x - 16) * 256; c = Ck; }
    else            { bp = Bv; bst = 512; n0 = (x - 18) * 256; isV = 1; }

    const int wm = (wid & 1) * 64, wn = (wid >> 1) * 64;

    float acc[4][8][4];
    #pragma unroll
    for (int i = 0; i < 4; i++)
        #pragma unroll
        for (int j = 0; j < 8; j++)
            #pragma unroll
            for (int e = 0; e < 4; e++) acc[i][j][e] = 0.0f;

    const int NC = Kd >> 6;   // 32

    #define G_ISSUE(ch) do { \
        int _sg_ = (ch) & 3; int _k0 = (ch) << 6; \
        uint32_t _st = smb + _sg_ * G_STAGE; \
        _Pragma("unroll") \
        for (int _j = 0; _j < 4; _j++) { \
            int _i = tid + 256 * _j; int _r = _i >> 3, _cc = _i & 7; \
            cpa16(_st + G_A + _r * GA_ST + _cc * 16, A + (size_t)(m0 + _r) * Kd + _k0 + _cc * 8); \
        } \
        _Pragma("unroll") \
        for (int _j = 0; _j < 8; _j++) { \
            int _i = tid + 256 * _j; int _r = _i >> 5, _cc = _i & 31; \
            cpa16(_st + G_B + _r * GB_ST + _cc * 16, bp + (size_t)(_k0 + _r) * bst + n0 + _cc * 8); \
        } \
        cpa_commit(); \
    } while (0)

    G_ISSUE(0);
    G_ISSUE(1);
    G_ISSUE(2);

    const int a_r = lane & 15;
    const int a_cb = (lane >> 4) * 16;
    const int b_k = (((lane >> 3) & 1) << 3) + (lane & 7);
    const int b_cb = ((lane >> 3) & 2) ? 16 : 0;

    for (int ch = 0; ch < NC; ch++) {
        // commits so far = 3 + ch; allow 2 pending -> chunk ch resident.
        cpa_wait<2>();
        __syncthreads();   // publishes stage ch + releases stage (ch-1)&3 for overwrite
        if (ch + 3 < NC) G_ISSUE(ch + 3); else cpa_commit();

        uint32_t st = smb + (ch & 3) * G_STAGE;
        uint32_t aB = st + G_A + (wm + a_r) * GA_ST + a_cb;
        uint32_t bB = st + G_B + b_k * GB_ST + wn * 2 + b_cb;

        #pragma unroll
        for (int kc = 0; kc < 4; kc++) {
            uint32_t ah[4][4];
            #pragma unroll
            for (int mi = 0; mi < 4; mi++)
                ldsm_x4(ah[mi], aB + mi * (16 * GA_ST) + kc * 32);
            #pragma unroll
            for (int bj = 0; bj < 4; bj++) {
                uint32_t bf[4];
                ldsm_x4_t(bf, bB + kc * (16 * GB_ST) + bj * 32);
                #pragma unroll
                for (int mi = 0; mi < 4; mi++) {
                    mma2(acc[mi][2*bj],   ah[mi], bf[0], bf[1]);
                    mma2(acc[mi][2*bj+1], ah[mi], bf[2], bf[3]);
                }
            }
        }
    }

    const int r0 = m0 + wm + (lane >> 2);
    const int c0 = n0 + wn + (lane & 3) * 2;
    if (!isV) {
        #pragma unroll
        for (int mi = 0; mi < 4; mi++) {
            #pragma unroll
            for (int nj = 0; nj < 8; nj++) {
                float2 lo2; lo2.x = acc[mi][nj][0]; lo2.y = acc[mi][nj][1];
                float2 hi2; hi2.x = acc[mi][nj][2]; hi2.y = acc[mi][nj][3];
                *(float2*)&c[(size_t)(r0 + mi * 16) * bst + c0 + nj * 8] = lo2;
                *(float2*)&c[(size_t)(r0 + mi * 16 + 8) * bst + c0 + nj * 8] = hi2;
            }
        }
    } else {
        #pragma unroll
        for (int mi = 0; mi < 4; mi++) {
            #pragma unroll
            for (int nj = 0; nj < 8; nj++) {
                int cg = c0 + nj * 8;
                int g = cg >> 7, d = cg & 127;
                #pragma unroll
                for (int half_ = 0; half_ < 2; half_++) {
                    int r = r0 + mi * 16 + half_ * 8;
                    int b = r >> 11, t = r & 2047;
                    uint32_t hv = f22h(acc[mi][nj][half_*2], acc[mi][nj][half_*2+1]);
                    size_t o = ((size_t)(b * G_ + g) * T_ + t) * KH + d;
                    *(uint32_t*)&Vo[o] = hv;
                }
            }
        }
    }
}

// -------- RMSNorm + RoPE, warp-per-row (shuffle-only, no smem) ---------------
template<int NH, int RST>
__global__ __launch_bounds__(256)
void rope_norm_w_kernel(const float* __restrict__ raw, const float* __restrict__ cosp,
                        const float* __restrict__ sinp, const float* __restrict__ w,
                        __half* __restrict__ outp) {
    const int idx = blockIdx.x * 8 + (threadIdx.x >> 5);
    const int lane = threadIdx.x & 31;
    const int bt = idx / NH, hh = idx % NH;
    const int b = bt >> 11, t = bt & 2047;
    const float* row = raw + (size_t)idx * RST;

    float4 a = *(const float4*)(row + lane * 4);
    float4 w4 = *(const float4*)(w + lane * 4);
    float ss = a.x*a.x + a.y*a.y + a.z*a.z + a.w*a.w;
    #pragma unroll
    for (int o = 16; o; o >>= 1) ss += __shfl_xor_sync(0xffffffffu, ss, o);
    float r = rsqrtf(ss * (1.0f / 128.0f) + EPS);
    float4 n;
    n.x = a.x * r * w4.x; n.y = a.y * r * w4.y;
    n.z = a.z * r * w4.z; n.w = a.w * r * w4.w;
    float4 p;
    p.x = __shfl_xor_sync(0xffffffffu, n.x, 16);
    p.y = __shfl_xor_sync(0xffffffffu, n.y, 16);
    p.z = __shfl_xor_sync(0xffffffffu, n.z, 16);
    p.w = __shfl_xor_sync(0xffffffffu, n.w, 16);
    float4 c4 = *(const float4*)(cosp + (size_t)bt * KH + lane * 4);
    float4 s4 = *(const float4*)(sinp + (size_t)bt * KH + lane * 4);
    float4 o4;
    if (lane < 16) {
        o4.x = n.x * c4.x - p.x * s4.x; o4.y = n.y * c4.y - p.y * s4.y;
        o4.z = n.z * c4.z - p.z * s4.z; o4.w = n.w * c4.w - p.w * s4.w;
    } else {
        o4.x = n.x * c4.x + p.x * s4.x; o4.y = n.y * c4.y + p.y * s4.y;
        o4.z = n.z * c4.z + p.z * s4.z; o4.w = n.w * c4.w + p.w * s4.w;
    }
    size_t o = ((size_t)(b * NH + hh) * T_ + t) * KH + lane * 4;
    uint2 hv;
    hv.x = f22h(o4.x, o4.y);
    hv.y = f22h(o4.z, o4.w);
    *(uint2*)&outp[o] = hv;
}

// ================= tensor-core flash attention (segment-skip) ================
#define AT_ST 272
#define AT_KV 17408
#define AT_KVSTG 17408
#define AT_SV  8704
#define AT_SEG 52224
#define AT_SMEM 52480

__global__ __launch_bounds__(128, 4)
void attn_tc_kernel(const __half* __restrict__ qv, const __half* __restrict__ kv,
                    const __half* __restrict__ vv,
                    const float* __restrict__ qraw, const int* __restrict__ seg,
                    __half* __restrict__ ao) {
    extern __shared__ char sa[];
    uint32_t smb = smem_u32(sa);
    const int tid = threadIdx.x, wid = tid >> 5, lane = tid & 31;
    const int qt = (int)(gridDim.x - 1 - blockIdx.x);
    const int q0 = qt * 64;
    const int bh_ = blockIdx.y;
    const int b = bh_ >> 4, h = bh_ & 15;
    const int g = h >> 2;
    const int wm = wid * 16;

    const __half* qb  = qv + ((size_t)(b * H_ + h) * T_ + q0) * KH;
    const __half* kb  = kv + (size_t)(b * G_ + g) * T_ * KH;
    const __half* vb  = vv + (size_t)(b * G_ + g) * T_ * KH;
    const int* segb = seg + (size_t)b * T_;

    const int sq_min = segb[q0];
    int lo = 0, hi = q0;
    while (lo < hi) { int mid = (lo + hi) >> 1; if (segb[mid] < sq_min) lo = mid + 1; else hi = mid; }
    const int t0 = lo >> 5;

    #pragma unroll
    for (int j = 0; j < 8; j++) {
        int i = tid + 128 * j; int r = i >> 4, cc = i & 15;
        cpa16(smb + r * AT_ST + cc * 16, qb + (size_t)r * KH + cc * 8);
    }

    const int nT = (q0 + 64) / 32;

    #define AT_ISSUE(t) do { \
        int _s = (t) & 1; int _s0 = (t) * 32; \
        uint32_t _bs = smb + AT_KV + _s * AT_KVSTG; \
        _Pragma("unroll") \
        for (int _j = 0; _j < 4; _j++) { \
            int _i = tid + 128 * _j; int _r = _i >> 4, _cc = _i & 15; \
            size_t _go = (size_t)(_s0 + _r) * KH + _cc * 8; \
            cpa16(_bs + _r * AT_ST + _cc * 16, kb + _go); \
            cpa16(_bs + AT_SV + _r * AT_ST + _cc * 16, vb + _go); \
        } \
        if (tid < 8) cpa16(smb + AT_SEG + _s * 128 + tid * 16, segb + _s0 + tid * 4); \
        cpa_commit(); \
    } while (0)

    AT_ISSUE(t0);

    const int qp0 = q0 + wm + (lane >> 2), qp1 = qp0 + 8;
    const int qs0 = segb[qp0];
    const int qs1 = segb[qp1];

    float rm0 = -1e30f, rm1 = -1e30f, rl0 = 0.0f, rl1 = 0.0f;
    float oacc[16][4];
    #pragma unroll
    for (int i = 0; i < 16; i++)
        #pragma unroll
        for (int e = 0; e < 4; e++) oacc[i][e] = 0.0f;

    const uint32_t aQ = smb + (wm + (lane & 15)) * AT_ST + (lane >> 4) * 16;
    const int vb_k = (((lane >> 3) & 1) << 3) + (lane & 7);
    const int vb_cb = ((lane >> 3) & 2) ? 16 : 0;
    const float SC = SCALE * 1.4426950408889634f;
    const float NEGINF = -__int_as_float(0x7f800000);

    for (int t = t0; t < nT; t++) {
        if (t + 1 < nT) { AT_ISSUE(t + 1); cpa_wait<1>(); }
        else cpa_wait<0>();
        __syncthreads();
        const int s0 = t * 32;
        uint32_t kst = smb + AT_KV + (t & 1) * AT_KVSTG;
        const int* kseg = (const int*)(sa + AT_SEG + (t & 1) * 128);

        float sacc[4][4];
        #pragma unroll
        for (int i = 0; i < 4; i++)
            #pragma unroll
            for (int e = 0; e < 4; e++) sacc[i][e] = 0.0f;

        #pragma unroll
        for (int kc = 0; kc < 8; kc++) {
            uint32_t aq[4];
            ldsm_x4(aq, aQ + kc * 32);
            #pragma unroll
            for (int ng = 0; ng < 2; ng++) {
                uint32_t kf[4];
                uint32_t ka = kst + (ng * 16 + (lane & 15)) * AT_ST + (lane >> 4) * 16 + kc * 32;
                ldsm_x4(kf, ka);
                mma2(sacc[2*ng],   aq, kf[0], kf[2]);
                mma2(sacc[2*ng+1], aq, kf[1], kf[3]);
            }
        }

        const int lc = (lane & 3) * 2;
        #pragma unroll
        for (int gi = 0; gi < 4; gi++) {
            int c0c = s0 + gi * 8 + lc, c1c = c0c + 1;
            int ks0 = kseg[gi * 8 + lc], ks1 = kseg[gi * 8 + lc + 1];
            float v;
            v = sacc[gi][0] * SC; sacc[gi][0] = (c0c <= qp0 && ks0 == qs0) ? v : NEGINF;
            v = sacc[gi][1] * SC; sacc[gi][1] = (c1c <= qp0 && ks1 == qs0) ? v : NEGINF;
            v = sacc[gi][2] * SC; sacc[gi][2] = (c0c <= qp1 && ks0 == qs1) ? v : NEGINF;
            v = sacc[gi][3] * SC; sacc[gi][3] = (c1c <= qp1 && ks1 == qs1) ? v : NEGINF;
        }

        float mx0 = NEGINF, mx1 = NEGINF;
        #pragma unroll
        for (int gi = 0; gi < 4; gi++) {
            mx0 = fmaxf(mx0, fmaxf(sacc[gi][0], sacc[gi][1]));
            mx1 = fmaxf(mx1, fmaxf(sacc[gi][2], sacc[gi][3]));
        }
        mx0 = fmaxf(mx0, __shfl_xor_sync(0xffffffffu, mx0, 1));
        mx0 = fmaxf(mx0, __shfl_xor_sync(0xffffffffu, mx0, 2));
        mx1 = fmaxf(mx1, __shfl_xor_sync(0xffffffffu, mx1, 1));
        mx1 = fmaxf(mx1, __shfl_xor_sync(0xffffffffu, mx1, 2));
        float nm0 = fmaxf(rm0, mx0), nm1 = fmaxf(rm1, mx1);
        float al0 = ex2f(rm0 - nm0), al1 = ex2f(rm1 - nm1);
        rm0 = nm0; rm1 = nm1;
        float sum0 = 0.0f, sum1 = 0.0f;
        #pragma unroll
        for (int gi = 0; gi < 4; gi++) {
            float p;
            p = ex2f(sacc[gi][0] - nm0); sum0 += p; sacc[gi][0] = p;
            p = ex2f(sacc[gi][1] - nm0); sum0 += p; sacc[gi][1] = p;
            p = ex2f(sacc[gi][2] - nm1); sum1 += p; sacc[gi][2] = p;
            p = ex2f(sacc[gi][3] - nm1); sum1 += p; sacc[gi][3] = p;
        }
        rl0 = rl0 * al0 + sum0;
        rl1 = rl1 * al1 + sum1;
        #pragma unroll
        for (int og = 0; og < 16; og++) {
            oacc[og][0] *= al0; oacc[og][1] *= al0;
            oacc[og][2] *= al1; oacc[og][3] *= al1;
        }

        #pragma unroll
        for (int kc2 = 0; kc2 < 2; kc2++) {
            uint32_t pa[4];
            pa[0] = f22h(sacc[2*kc2][0],   sacc[2*kc2][1]);
            pa[1] = f22h(sacc[2*kc2][2],   sacc[2*kc2][3]);
            pa[2] = f22h(sacc[2*kc2+1][0], sacc[2*kc2+1][1]);
            pa[3] = f22h(sacc[2*kc2+1][2], sacc[2*kc2+1][3]);
            uint32_t vbase = kst + AT_SV + (kc2 * 16 + vb_k) * AT_ST + vb_cb;
            #pragma unroll
            for (int nd = 0; nd < 8; nd++) {
                uint32_t vbf[4];
                ldsm_x4_t(vbf, vbase + nd * 32);
                mma2(oacc[2*nd],   pa, vbf[0], vbf[1]);
                mma2(oacc[2*nd+1], pa, vbf[2], vbf[3]);
            }
        }
        __syncthreads();
    }

    rl0 += __shfl_xor_sync(0xffffffffu, rl0, 1);
    rl0 += __shfl_xor_sync(0xffffffffu, rl0, 2);
    rl1 += __shfl_xor_sync(0xffffffffu, rl1, 1);
    rl1 += __shfl_xor_sync(0xffffffffu, rl1, 2);
    float inv0 = 1.0f / rl0, inv1 = 1.0f / rl1;
    const float L2E = 1.4426950408889634f;
    #pragma unroll
    for (int og = 0; og < 16; og++) {
        int d = og * 8 + (lane & 3) * 2;
        {
            float2 gt = *(const float2*)&qraw[((size_t)(b * T_ + qp0) * H_ + h) * 256 + 128 + d];
            float s0v = 1.0f / (1.0f + ex2f(-gt.x * L2E));
            float s1v = 1.0f / (1.0f + ex2f(-gt.y * L2E));
            uint32_t hv = f22h(oacc[og][0] * inv0 * s0v, oacc[og][1] * inv0 * s1v);
            size_t o = (size_t)(b * T_ + qp0) * (H_ * KH) + h * KH + d;
            *(uint32_t*)&ao[o] = hv;
        }
        {
            float2 gt = *(const float2*)&qraw[((size_t)(b * T_ + qp1) * H_ + h) * 256 + 128 + d];
            float s0v = 1.0f / (1.0f + ex2f(-gt.x * L2E));
            float s1v = 1.0f / (1.0f + ex2f(-gt.y * L2E));
            uint32_t hv = f22h(oacc[og][2] * inv1 * s0v, oacc[og][3] * inv1 * s1v);
            size_t o = (size_t)(b * T_ + qp1) * (H_ * KH) + h * KH + d;
            *(uint32_t*)&ao[o] = hv;
        }
    }
}

// ---------------- launch -----------------------------------------------------
extern "C" void kernel_launch(void* const* d_in, const int* in_sizes, int n_in,
                              void* d_out, int out_size) {
    const float* hidden = (const float*)d_in[0];
    const float* cosp   = (const float*)d_in[1];
    const float* sinp   = (const float*)d_in[2];
    const int*   seg    = (const int*)d_in[3];
    const float* Wq = (const float*)d_in[5];
    const float* Wk = (const float*)d_in[6];
    const float* Wv = (const float*)d_in[7];
    const float* Wo = (const float*)d_in[8];
    const float* qw = (const float*)d_in[9];
    const float* kw = (const float*)d_in[10];
    float* out = (float*)d_out;

    float *qraw, *kraw;
    __half *hid, *wq, *wk, *wv, *wo, *qb, *kb, *vb, *ao;
    cudaGetSymbolAddress((void**)&qraw, g_qraw);
    cudaGetSymbolAddress((void**)&kraw, g_kraw);
    cudaGetSymbolAddress((void**)&hid, g_hid);
    cudaGetSymbolAddress((void**)&wq, g_wq);
    cudaGetSymbolAddress((void**)&wk, g_wk);
    cudaGetSymbolAddress((void**)&wv, g_wv);
    cudaGetSymbolAddress((void**)&wo, g_wo);
    cudaGetSymbolAddress((void**)&qb, g_qb);
    cudaGetSymbolAddress((void**)&kb, g_kb);
    cudaGetSymbolAddress((void**)&vb, g_vb);
    cudaGetSymbolAddress((void**)&ao, g_ao);

    cudaFuncSetAttribute(gemm_h1_kernel, cudaFuncAttributeMaxDynamicSharedMemorySize, G_SMEM);
    cudaFuncSetAttribute(attn_tc_kernel, cudaFuncAttributeMaxDynamicSharedMemorySize, AT_SMEM);

    // 1. convert all operands to fp16 (single launch, 23068672/1024 = 22528 blocks)
    cvt_all_kernel<<<CV_S4 / 1024, 256>>>(hidden, Wq, Wk, Wv, Wo,
                                          hid, wq, wk, wv, wo);

    // 2. merged Q/K/V projection (V written directly as fp16 [b,g,t,d])
    gemm_h1_kernel<<<dim3(20, 32), 256, G_SMEM>>>(hid, wq, wk, wv,
                                                  qraw, kraw, vb, 0, 2048, 1);

    // 3. rmsnorm + rope (warp-per-row)
    rope_norm_w_kernel<H_, 256><<<(B_*T_*H_) / 8, 256>>>(qraw, cosp, sinp, qw, qb);
    rope_norm_w_kernel<G_, 128><<<(B_*T_*G_) / 8, 256>>>(kraw, cosp, sinp, kw, kb);

    // 4. attention (gate fused, segment skip, 4 CTAs/SM)
    attn_tc_kernel<<<dim3(T_/64, B_*H_), 128, AT_SMEM>>>(qb, kb, vb, qraw, seg, ao);

    // 5. output projection
    gemm_h1_kernel<<<dim3(8, 32), 256, G_SMEM>>>(ao, wo, nullptr, nullptr,
                                                 out, nullptr, nullptr, 2048, 2048, 0);
}

// round 16
// speedup vs baseline: 9.4737x; 1.0816x over previous
#include <cuda_runtime.h>
#include <cuda_fp16.h>
#include <cstdint>

// Problem constants
#define B_  2
#define T_  2048
#define D_  2048
#define H_  16
#define G_  4
#define KH  128
#define EPS 1e-6f
static const float SCALE = 0.088388347648318447f; // 128^-0.5

// ---------------- scratch (device globals) -----------------------------------
__device__ float g_qraw[B_*T_*H_*2*KH];       // fp32 (gate kept here)
__device__ float g_kraw[B_*T_*G_*KH];
__device__ __half g_hid[B_*T_*D_];
__device__ __half g_wq[D_*H_*2*KH];
__device__ __half g_wk[D_*G_*KH];
__device__ __half g_wv[D_*G_*KH];
__device__ __half g_wo[H_*KH*D_];
__device__ __half g_qb[B_*H_*T_*KH];   // Q  [b,h,t,d]
__device__ __half g_kb[B_*G_*T_*KH];   // K  [b,g,t,d]
__device__ __half g_vb[B_*G_*T_*KH];   // V  [b,g,t,d]
__device__ __half g_ao[B_*T_*H_*KH];   // gated attn out

// ============================ helpers ========================================
__device__ __forceinline__ uint32_t smem_u32(const void* p) {
    return (uint32_t)__cvta_generic_to_shared((void*)p);
}
__device__ __forceinline__ void ldsm_x4(uint32_t* r, uint32_t addr) {
    asm volatile("ldmatrix.sync.aligned.m8n8.x4.shared.b16 {%0,%1,%2,%3}, [%4];"
        : "=r"(r[0]), "=r"(r[1]), "=r"(r[2]), "=r"(r[3]) : "r"(addr));
}
__device__ __forceinline__ void ldsm_x4_t(uint32_t* r, uint32_t addr) {
    asm volatile("ldmatrix.sync.aligned.m8n8.x4.trans.shared.b16 {%0,%1,%2,%3}, [%4];"
        : "=r"(r[0]), "=r"(r[1]), "=r"(r[2]), "=r"(r[3]) : "r"(addr));
}
__device__ __forceinline__ void mma2(float* d, const uint32_t* a, uint32_t b0, uint32_t b1) {
    asm volatile("mma.sync.aligned.m16n8k16.row.col.f32.f16.f16.f32 "
        "{%0,%1,%2,%3}, {%4,%5,%6,%7}, {%8,%9}, {%0,%1,%2,%3};"
        : "+f"(d[0]), "+f"(d[1]), "+f"(d[2]), "+f"(d[3])
        : "r"(a[0]), "r"(a[1]), "r"(a[2]), "r"(a[3]), "r"(b0), "r"(b1));
}
__device__ __forceinline__ void cpa16(uint32_t s, const void* g) {
    asm volatile("cp.async.cg.shared.global [%0], [%1], 16;" :: "r"(s), "l"(g));
}
__device__ __forceinline__ void cpa_commit() { asm volatile("cp.async.commit_group;"); }
template<int N> __device__ __forceinline__ void cpa_wait() {
    asm volatile("cp.async.wait_group %0;" :: "n"(N));
}
__device__ __forceinline__ float ex2f(float x) {
    float y; asm("ex2.approx.ftz.f32 %0, %1;" : "=f"(y) : "f"(x)); return y;
}
__device__ __forceinline__ uint32_t f22h(float a, float b) {
    __half2 t = __floats2half2_rn(a, b);
    return *reinterpret_cast<uint32_t*>(&t);
}

// ---------------- merged convert fp32 -> fp16 (all 5 operands) ---------------
// regions: hid 8388608, wq 8388608, wk 1048576, wv 1048576, wo 4194304
#define CV_S0 8388608u
#define CV_S1 16777216u
#define CV_S2 17825792u
#define CV_S3 18874368u
#define CV_S4 23068672u
__global__ __launch_bounds__(256)
void cvt_all_kernel(const float* __restrict__ hid, const float* __restrict__ wq,
                    const float* __restrict__ wk, const float* __restrict__ wv,
                    const float* __restrict__ wo,
                    __half* __restrict__ oh, __half* __restrict__ oq,
                    __half* __restrict__ ok, __half* __restrict__ ov,
                    __half* __restrict__ oo) {
    size_t i = ((size_t)blockIdx.x * 256 + threadIdx.x) * 4;
    const float* in; __half* out; size_t off;
    if (i < CV_S0)      { in = hid; out = oh; off = i; }
    else if (i < CV_S1) { in = wq;  out = oq; off = i - CV_S0; }
    else if (i < CV_S2) { in = wk;  out = ok; off = i - CV_S1; }
    else if (i < CV_S3) { in = wv;  out = ov; off = i - CV_S2; }
    else                { in = wo;  out = oo; off = i - CV_S3; }
    float4 v = *(const float4*)(in + off);
    *(uint32_t*)(out + off)     = f22h(v.x, v.y);
    *(uint32_t*)(out + off + 2) = f22h(v.z, v.w);
}

// ================= GEMM: C[M,N] = A @ B, single fp16, 1-term =================
// CTA 128x256, BK=64, 512 thr, 16 warps x (32x64), 4-stage cp.async,
// ONE barrier per chunk. 4 warps per SMSP for latency hiding.
#define GA_ST 144
#define GB_ST 528
#define G_A  0
#define G_B  18432
#define G_STAGE 52224
#define G_SMEM 208896

__global__ __launch_bounds__(512, 1)
void gemm_h1_kernel(const __half* __restrict__ A,
                    const __half* __restrict__ B0, const __half* __restrict__ Bk,
                    const __half* __restrict__ Bv,
                    float* __restrict__ Cq, float* __restrict__ Ck,
                    __half* __restrict__ Vo,
                    int N0, int Kd, int qkv) {
    extern __shared__ char sg[];
    uint32_t smb = smem_u32(sg);
    const int tid = threadIdx.x, wid = tid >> 5, lane = tid & 31;
    const int m0 = blockIdx.y * 128;
    const int x = blockIdx.x;

    const __half* bp;
    float* c = nullptr;
    int bst, n0, isV = 0;
    if (!qkv) { bp = B0; bst = N0; n0 = x * 256; c = Cq; }
    else if (x < 16) { bp = B0; bst = 4096; n0 = x * 256; c = Cq; }
    else if (x < 18) { bp = Bk; bst = 512; n0 = (x - 16) * 256; c = Ck; }
    else            { bp = Bv; bst = 512; n0 = (x - 18) * 256; isV = 1; }

    // 16 warps: 4 m-slots x 4 n-slots. warp tile 32x64.
    const int wm = (wid & 3) * 32, wn = (wid >> 2) * 64;

    float acc[2][8][4];
    #pragma unroll
    for (int i = 0; i < 2; i++)
        #pragma unroll
        for (int j = 0; j < 8; j++)
            #pragma unroll
            for (int e = 0; e < 4; e++) acc[i][j][e] = 0.0f;

    const int NC = Kd >> 6;   // 32

    #define G_ISSUE(ch) do { \
        int _sg_ = (ch) & 3; int _k0 = (ch) << 6; \
        uint32_t _st = smb + _sg_ * G_STAGE; \
        _Pragma("unroll") \
        for (int _j = 0; _j < 2; _j++) { \
            int _i = tid + 512 * _j; int _r = _i >> 3, _cc = _i & 7; \
            cpa16(_st + G_A + _r * GA_ST + _cc * 16, A + (size_t)(m0 + _r) * Kd + _k0 + _cc * 8); \
        } \
        _Pragma("unroll") \
        for (int _j = 0; _j < 4; _j++) { \
            int _i = tid + 512 * _j; int _r = _i >> 5, _cc = _i & 31; \
            cpa16(_st + G_B + _r * GB_ST + _cc * 16, bp + (size_t)(_k0 + _r) * bst + n0 + _cc * 8); \
        } \
        cpa_commit(); \
    } while (0)

    G_ISSUE(0);
    G_ISSUE(1);
    G_ISSUE(2);

    const int a_r = lane & 15;
    const int a_cb = (lane >> 4) * 16;
    const int b_k = (((lane >> 3) & 1) << 3) + (lane & 7);
    const int b_cb = ((lane >> 3) & 2) ? 16 : 0;

    for (int ch = 0; ch < NC; ch++) {
        // commits so far = 3 + ch; allow 2 pending -> chunk ch resident.
        cpa_wait<2>();
        __syncthreads();   // publishes stage ch + releases stage (ch-1)&3 for overwrite
        if (ch + 3 < NC) G_ISSUE(ch + 3); else cpa_commit();

        uint32_t st = smb + (ch & 3) * G_STAGE;
        uint32_t aB = st + G_A + (wm + a_r) * GA_ST + a_cb;
        uint32_t bB = st + G_B + b_k * GB_ST + wn * 2 + b_cb;

        #pragma unroll
        for (int kc = 0; kc < 4; kc++) {
            uint32_t ah[2][4];
            #pragma unroll
            for (int mi = 0; mi < 2; mi++)
                ldsm_x4(ah[mi], aB + mi * (16 * GA_ST) + kc * 32);
            #pragma unroll
            for (int bj = 0; bj < 4; bj++) {
                uint32_t bf[4];
                ldsm_x4_t(bf, bB + kc * (16 * GB_ST) + bj * 32);
                #pragma unroll
                for (int mi = 0; mi < 2; mi++) {
                    mma2(acc[mi][2*bj],   ah[mi], bf[0], bf[1]);
                    mma2(acc[mi][2*bj+1], ah[mi], bf[2], bf[3]);
                }
            }
        }
    }

    const int r0 = m0 + wm + (lane >> 2);
    const int c0 = n0 + wn + (lane & 3) * 2;
    if (!isV) {
        #pragma unroll
        for (int mi = 0; mi < 2; mi++) {
            #pragma unroll
            for (int nj = 0; nj < 8; nj++) {
                float2 lo2; lo2.x = acc[mi][nj][0]; lo2.y = acc[mi][nj][1];
                float2 hi2; hi2.x = acc[mi][nj][2]; hi2.y = acc[mi][nj][3];
                *(float2*)&c[(size_t)(r0 + mi * 16) * bst + c0 + nj * 8] = lo2;
                *(float2*)&c[(size_t)(r0 + mi * 16 + 8) * bst + c0 + nj * 8] = hi2;
            }
        }
    } else {
        #pragma unroll
        for (int mi = 0; mi < 2; mi++) {
            #pragma unroll
            for (int nj = 0; nj < 8; nj++) {
                int cg = c0 + nj * 8;
                int g = cg >> 7, d = cg & 127;
                #pragma unroll
                for (int half_ = 0; half_ < 2; half_++) {
                    int r = r0 + mi * 16 + half_ * 8;
                    int b = r >> 11, t = r & 2047;
                    uint32_t hv = f22h(acc[mi][nj][half_*2], acc[mi][nj][half_*2+1]);
                    size_t o = ((size_t)(b * G_ + g) * T_ + t) * KH + d;
                    *(uint32_t*)&Vo[o] = hv;
                }
            }
        }
    }
}

// -------- RMSNorm + RoPE, warp-per-row (shuffle-only, no smem) ---------------
template<int NH, int RST>
__global__ __launch_bounds__(256)
void rope_norm_w_kernel(const float* __restrict__ raw, const float* __restrict__ cosp,
                        const float* __restrict__ sinp, const float* __restrict__ w,
                        __half* __restrict__ outp) {
    const int idx = blockIdx.x * 8 + (threadIdx.x >> 5);
    const int lane = threadIdx.x & 31;
    const int bt = idx / NH, hh = idx % NH;
    const int b = bt >> 11, t = bt & 2047;
    const float* row = raw + (size_t)idx * RST;

    float4 a = *(const float4*)(row + lane * 4);
    float4 w4 = *(const float4*)(w + lane * 4);
    float ss = a.x*a.x + a.y*a.y + a.z*a.z + a.w*a.w;
    #pragma unroll
    for (int o = 16; o; o >>= 1) ss += __shfl_xor_sync(0xffffffffu, ss, o);
    float r = rsqrtf(ss * (1.0f / 128.0f) + EPS);
    float4 n;
    n.x = a.x * r * w4.x; n.y = a.y * r * w4.y;
    n.z = a.z * r * w4.z; n.w = a.w * r * w4.w;
    float4 p;
    p.x = __shfl_xor_sync(0xffffffffu, n.x, 16);
    p.y = __shfl_xor_sync(0xffffffffu, n.y, 16);
    p.z = __shfl_xor_sync(0xffffffffu, n.z, 16);
    p.w = __shfl_xor_sync(0xffffffffu, n.w, 16);
    float4 c4 = *(const float4*)(cosp + (size_t)bt * KH + lane * 4);
    float4 s4 = *(const float4*)(sinp + (size_t)bt * KH + lane * 4);
    float4 o4;
    if (lane < 16) {
        o4.x = n.x * c4.x - p.x * s4.x; o4.y = n.y * c4.y - p.y * s4.y;
        o4.z = n.z * c4.z - p.z * s4.z; o4.w = n.w * c4.w - p.w * s4.w;
    } else {
        o4.x = n.x * c4.x + p.x * s4.x; o4.y = n.y * c4.y + p.y * s4.y;
        o4.z = n.z * c4.z + p.z * s4.z; o4.w = n.w * c4.w + p.w * s4.w;
    }
    size_t o = ((size_t)(b * NH + hh) * T_ + t) * KH + lane * 4;
    uint2 hv;
    hv.x = f22h(o4.x, o4.y);
    hv.y = f22h(o4.z, o4.w);
    *(uint2*)&outp[o] = hv;
}

// ================= tensor-core flash attention (segment-skip) ================
#define AT_ST 272
#define AT_KV 17408
#define AT_KVSTG 17408
#define AT_SV  8704
#define AT_SEG 52224
#define AT_SMEM 52480

__global__ __launch_bounds__(128, 4)
void attn_tc_kernel(const __half* __restrict__ qv, const __half* __restrict__ kv,
                    const __half* __restrict__ vv,
                    const float* __restrict__ qraw, const int* __restrict__ seg,
                    __half* __restrict__ ao) {
    extern __shared__ char sa[];
    uint32_t smb = smem_u32(sa);
    const int tid = threadIdx.x, wid = tid >> 5, lane = tid & 31;
    const int qt = (int)(gridDim.x - 1 - blockIdx.x);
    const int q0 = qt * 64;
    const int bh_ = blockIdx.y;
    const int b = bh_ >> 4, h = bh_ & 15;
    const int g = h >> 2;
    const int wm = wid * 16;

    const __half* qb  = qv + ((size_t)(b * H_ + h) * T_ + q0) * KH;
    const __half* kb  = kv + (size_t)(b * G_ + g) * T_ * KH;
    const __half* vb  = vv + (size_t)(b * G_ + g) * T_ * KH;
    const int* segb = seg + (size_t)b * T_;

    const int sq_min = segb[q0];
    int lo = 0, hi = q0;
    while (lo < hi) { int mid = (lo + hi) >> 1; if (segb[mid] < sq_min) lo = mid + 1; else hi = mid; }
    const int t0 = lo >> 5;

    #pragma unroll
    for (int j = 0; j < 8; j++) {
        int i = tid + 128 * j; int r = i >> 4, cc = i & 15;
        cpa16(smb + r * AT_ST + cc * 16, qb + (size_t)r * KH + cc * 8);
    }

    const int nT = (q0 + 64) / 32;

    #define AT_ISSUE(t) do { \
        int _s = (t) & 1; int _s0 = (t) * 32; \
        uint32_t _bs = smb + AT_KV + _s * AT_KVSTG; \
        _Pragma("unroll") \
        for (int _j = 0; _j < 4; _j++) { \
            int _i = tid + 128 * _j; int _r = _i >> 4, _cc = _i & 15; \
            size_t _go = (size_t)(_s0 + _r) * KH + _cc * 8; \
            cpa16(_bs + _r * AT_ST + _cc * 16, kb + _go); \
            cpa16(_bs + AT_SV + _r * AT_ST + _cc * 16, vb + _go); \
        } \
        if (tid < 8) cpa16(smb + AT_SEG + _s * 128 + tid * 16, segb + _s0 + tid * 4); \
        cpa_commit(); \
    } while (0)

    AT_ISSUE(t0);

    const int qp0 = q0 + wm + (lane >> 2), qp1 = qp0 + 8;
    const int qs0 = segb[qp0];
    const int qs1 = segb[qp1];

    float rm0 = -1e30f, rm1 = -1e30f, rl0 = 0.0f, rl1 = 0.0f;
    float oacc[16][4];
    #pragma unroll
    for (int i = 0; i < 16; i++)
        #pragma unroll
        for (int e = 0; e < 4; e++) oacc[i][e] = 0.0f;

    const uint32_t aQ = smb + (wm + (lane & 15)) * AT_ST + (lane >> 4) * 16;
    const int vb_k = (((lane >> 3) & 1) << 3) + (lane & 7);
    const int vb_cb = ((lane >> 3) & 2) ? 16 : 0;
    const float SC = SCALE * 1.4426950408889634f;
    const float NEGINF = -__int_as_float(0x7f800000);

    for (int t = t0; t < nT; t++) {
        if (t + 1 < nT) { AT_ISSUE(t + 1); cpa_wait<1>(); }
        else cpa_wait<0>();
        __syncthreads();
        const int s0 = t * 32;
        uint32_t kst = smb + AT_KV + (t & 1) * AT_KVSTG;
        const int* kseg = (const int*)(sa + AT_SEG + (t & 1) * 128);

        float sacc[4][4];
        #pragma unroll
        for (int i = 0; i < 4; i++)
            #pragma unroll
            for (int e = 0; e < 4; e++) sacc[i][e] = 0.0f;

        #pragma unroll
        for (int kc = 0; kc < 8; kc++) {
            uint32_t aq[4];
            ldsm_x4(aq, aQ + kc * 32);
            #pragma unroll
            for (int ng = 0; ng < 2; ng++) {
                uint32_t kf[4];
                uint32_t ka = kst + (ng * 16 + (lane & 15)) * AT_ST + (lane >> 4) * 16 + kc * 32;
                ldsm_x4(kf, ka);
                mma2(sacc[2*ng],   aq, kf[0], kf[2]);
                mma2(sacc[2*ng+1], aq, kf[1], kf[3]);
            }
        }

        const int lc = (lane & 3) * 2;
        #pragma unroll
        for (int gi = 0; gi < 4; gi++) {
            int c0c = s0 + gi * 8 + lc, c1c = c0c + 1;
            int ks0 = kseg[gi * 8 + lc], ks1 = kseg[gi * 8 + lc + 1];
            float v;
            v = sacc[gi][0] * SC; sacc[gi][0] = (c0c <= qp0 && ks0 == qs0) ? v : NEGINF;
            v = sacc[gi][1] * SC; sacc[gi][1] = (c1c <= qp0 && ks1 == qs0) ? v : NEGINF;
            v = sacc[gi][2] * SC; sacc[gi][2] = (c0c <= qp1 && ks0 == qs1) ? v : NEGINF;
            v = sacc[gi][3] * SC; sacc[gi][3] = (c1c <= qp1 && ks1 == qs1) ? v : NEGINF;
        }

        float mx0 = NEGINF, mx1 = NEGINF;
        #pragma unroll
        for (int gi = 0; gi < 4; gi++) {
            mx0 = fmaxf(mx0, fmaxf(sacc[gi][0], sacc[gi][1]));
            mx1 = fmaxf(mx1, fmaxf(sacc[gi][2], sacc[gi][3]));
        }
        mx0 = fmaxf(mx0, __shfl_xor_sync(0xffffffffu, mx0, 1));
        mx0 = fmaxf(mx0, __shfl_xor_sync(0xffffffffu, mx0, 2));
        mx1 = fmaxf(mx1, __shfl_xor_sync(0xffffffffu, mx1, 1));
        mx1 = fmaxf(mx1, __shfl_xor_sync(0xffffffffu, mx1, 2));
        float nm0 = fmaxf(rm0, mx0), nm1 = fmaxf(rm1, mx1);
        float al0 = ex2f(rm0 - nm0), al1 = ex2f(rm1 - nm1);
        rm0 = nm0; rm1 = nm1;
        float sum0 = 0.0f, sum1 = 0.0f;
        #pragma unroll
        for (int gi = 0; gi < 4; gi++) {
            float p;
            p = ex2f(sacc[gi][0] - nm0); sum0 += p; sacc[gi][0] = p;
            p = ex2f(sacc[gi][1] - nm0); sum0 += p; sacc[gi][1] = p;
            p = ex2f(sacc[gi][2] - nm1); sum1 += p; sacc[gi][2] = p;
            p = ex2f(sacc[gi][3] - nm1); sum1 += p; sacc[gi][3] = p;
        }
        rl0 = rl0 * al0 + sum0;
        rl1 = rl1 * al1 + sum1;
        #pragma unroll
        for (int og = 0; og < 16; og++) {
            oacc[og][0] *= al0; oacc[og][1] *= al0;
            oacc[og][2] *= al1; oacc[og][3] *= al1;
        }

        #pragma unroll
        for (int kc2 = 0; kc2 < 2; kc2++) {
            uint32_t pa[4];
            pa[0] = f22h(sacc[2*kc2][0],   sacc[2*kc2][1]);
            pa[1] = f22h(sacc[2*kc2][2],   sacc[2*kc2][3]);
            pa[2] = f22h(sacc[2*kc2+1][0], sacc[2*kc2+1][1]);
            pa[3] = f22h(sacc[2*kc2+1][2], sacc[2*kc2+1][3]);
            uint32_t vbase = kst + AT_SV + (kc2 * 16 + vb_k) * AT_ST + vb_cb;
            #pragma unroll
            for (int nd = 0; nd < 8; nd++) {
                uint32_t vbf[4];
                ldsm_x4_t(vbf, vbase + nd * 32);
                mma2(oacc[2*nd],   pa, vbf[0], vbf[1]);
                mma2(oacc[2*nd+1], pa, vbf[2], vbf[3]);
            }
        }
        __syncthreads();
    }

    rl0 += __shfl_xor_sync(0xffffffffu, rl0, 1);
    rl0 += __shfl_xor_sync(0xffffffffu, rl0, 2);
    rl1 += __shfl_xor_sync(0xffffffffu, rl1, 1);
    rl1 += __shfl_xor_sync(0xffffffffu, rl1, 2);
    float inv0 = 1.0f / rl0, inv1 = 1.0f / rl1;
    const float L2E = 1.4426950408889634f;
    #pragma unroll
    for (int og = 0; og < 16; og++) {
        int d = og * 8 + (lane & 3) * 2;
        {
            float2 gt = *(const float2*)&qraw[((size_t)(b * T_ + qp0) * H_ + h) * 256 + 128 + d];
            float s0v = 1.0f / (1.0f + ex2f(-gt.x * L2E));
            float s1v = 1.0f / (1.0f + ex2f(-gt.y * L2E));
            uint32_t hv = f22h(oacc[og][0] * inv0 * s0v, oacc[og][1] * inv0 * s1v);
            size_t o = (size_t)(b * T_ + qp0) * (H_ * KH) + h * KH + d;
            *(uint32_t*)&ao[o] = hv;
        }
        {
            float2 gt = *(const float2*)&qraw[((size_t)(b * T_ + qp1) * H_ + h) * 256 + 128 + d];
            float s0v = 1.0f / (1.0f + ex2f(-gt.x * L2E));
            float s1v = 1.0f / (1.0f + ex2f(-gt.y * L2E));
            uint32_t hv = f22h(oacc[og][2] * inv1 * s0v, oacc[og][3] * inv1 * s1v);
            size_t o = (size_t)(b * T_ + qp1) * (H_ * KH) + h * KH + d;
            *(uint32_t*)&ao[o] = hv;
        }
    }
}

// ---------------- launch -----------------------------------------------------
extern "C" void kernel_launch(void* const* d_in, const int* in_sizes, int n_in,
                              void* d_out, int out_size) {
    const float* hidden = (const float*)d_in[0];
    const float* cosp   = (const float*)d_in[1];
    const float* sinp   = (const float*)d_in[2];
    const int*   seg    = (const int*)d_in[3];
    const float* Wq = (const float*)d_in[5];
    const float* Wk = (const float*)d_in[6];
    const float* Wv = (const float*)d_in[7];
    const float* Wo = (const float*)d_in[8];
    const float* qw = (const float*)d_in[9];
    const float* kw = (const float*)d_in[10];
    float* out = (float*)d_out;

    float *qraw, *kraw;
    __half *hid, *wq, *wk, *wv, *wo, *qb, *kb, *vb, *ao;
    cudaGetSymbolAddress((void**)&qraw, g_qraw);
    cudaGetSymbolAddress((void**)&kraw, g_kraw);
    cudaGetSymbolAddress((void**)&hid, g_hid);
    cudaGetSymbolAddress((void**)&wq, g_wq);
    cudaGetSymbolAddress((void**)&wk, g_wk);
    cudaGetSymbolAddress((void**)&wv, g_wv);
    cudaGetSymbolAddress((void**)&wo, g_wo);
    cudaGetSymbolAddress((void**)&qb, g_qb);
    cudaGetSymbolAddress((void**)&kb, g_kb);
    cudaGetSymbolAddress((void**)&vb, g_vb);
    cudaGetSymbolAddress((void**)&ao, g_ao);

    cudaFuncSetAttribute(gemm_h1_kernel, cudaFuncAttributeMaxDynamicSharedMemorySize, G_SMEM);
    cudaFuncSetAttribute(attn_tc_kernel, cudaFuncAttributeMaxDynamicSharedMemorySize, AT_SMEM);

    // 1. convert all operands to fp16 (single launch)
    cvt_all_kernel<<<CV_S4 / 1024, 256>>>(hidden, Wq, Wk, Wv, Wo,
                                          hid, wq, wk, wv, wo);

    // 2. merged Q/K/V projection (V written directly as fp16 [b,g,t,d])
    gemm_h1_kernel<<<dim3(20, 32), 512, G_SMEM>>>(hid, wq, wk, wv,
                                                  qraw, kraw, vb, 0, 2048, 1);

    // 3. rmsnorm + rope (warp-per-row)
    rope_norm_w_kernel<H_, 256><<<(B_*T_*H_) / 8, 256>>>(qraw, cosp, sinp, qw, qb);
    rope_norm_w_kernel<G_, 128><<<(B_*T_*G_) / 8, 256>>>(kraw, cosp, sinp, kw, kb);

    // 4. attention (gate fused, segment skip, 4 CTAs/SM)
    attn_tc_kernel<<<dim3(T_/64, B_*H_), 128, AT_SMEM>>>(qb, kb, vb, qraw, seg, ao);

    // 5. output projection
    gemm_h1_kernel<<<dim3(8, 32), 512, G_SMEM>>>(ao, wo, nullptr, nullptr,
                                                 out, nullptr, nullptr, 2048, 2048, 0);
}

// round 17
// speedup vs baseline: 9.9328x; 1.0485x over previous
#include <cuda_runtime.h>
#include <cuda_fp16.h>
#include <cstdint>

// Problem constants
#define B_  2
#define T_  2048
#define D_  2048
#define H_  16
#define G_  4
#define KH  128
#define EPS 1e-6f
static const float SCALE = 0.088388347648318447f; // 128^-0.5

// ---------------- scratch (device globals) -----------------------------------
__device__ float g_qraw[B_*T_*H_*2*KH];       // fp32 (gate kept here)
__device__ float g_kraw[B_*T_*G_*KH];
__device__ __half g_hid[B_*T_*D_];
__device__ __half g_wq[D_*H_*2*KH];
__device__ __half g_wk[D_*G_*KH];
__device__ __half g_wv[D_*G_*KH];
__device__ __half g_wo[H_*KH*D_];
__device__ __half g_qb[B_*H_*T_*KH];   // Q  [b,h,t,d]
__device__ __half g_kb[B_*G_*T_*KH];   // K  [b,g,t,d]
__device__ __half g_vb[B_*G_*T_*KH];   // V  [b,g,t,d]
__device__ __half g_ao[B_*T_*H_*KH];   // gated attn out

// ============================ helpers ========================================
__device__ __forceinline__ uint32_t smem_u32(const void* p) {
    return (uint32_t)__cvta_generic_to_shared((void*)p);
}
__device__ __forceinline__ void ldsm_x4(uint32_t* r, uint32_t addr) {
    asm volatile("ldmatrix.sync.aligned.m8n8.x4.shared.b16 {%0,%1,%2,%3}, [%4];"
        : "=r"(r[0]), "=r"(r[1]), "=r"(r[2]), "=r"(r[3]) : "r"(addr));
}
__device__ __forceinline__ void ldsm_x4_t(uint32_t* r, uint32_t addr) {
    asm volatile("ldmatrix.sync.aligned.m8n8.x4.trans.shared.b16 {%0,%1,%2,%3}, [%4];"
        : "=r"(r[0]), "=r"(r[1]), "=r"(r[2]), "=r"(r[3]) : "r"(addr));
}
__device__ __forceinline__ void mma2(float* d, const uint32_t* a, uint32_t b0, uint32_t b1) {
    asm volatile("mma.sync.aligned.m16n8k16.row.col.f32.f16.f16.f32 "
        "{%0,%1,%2,%3}, {%4,%5,%6,%7}, {%8,%9}, {%0,%1,%2,%3};"
        : "+f"(d[0]), "+f"(d[1]), "+f"(d[2]), "+f"(d[3])
        : "r"(a[0]), "r"(a[1]), "r"(a[2]), "r"(a[3]), "r"(b0), "r"(b1));
}
__device__ __forceinline__ void cpa16(uint32_t s, const void* g) {
    asm volatile("cp.async.cg.shared.global [%0], [%1], 16;" :: "r"(s), "l"(g));
}
__device__ __forceinline__ void cpa_commit() { asm volatile("cp.async.commit_group;"); }
template<int N> __device__ __forceinline__ void cpa_wait() {
    asm volatile("cp.async.wait_group %0;" :: "n"(N));
}
__device__ __forceinline__ float ex2f(float x) {
    float y; asm("ex2.approx.ftz.f32 %0, %1;" : "=f"(y) : "f"(x)); return y;
}
__device__ __forceinline__ uint32_t f22h(float a, float b) {
    __half2 t = __floats2half2_rn(a, b);
    return *reinterpret_cast<uint32_t*>(&t);
}

// ---------------- merged convert fp32 -> fp16 (all 5 operands) ---------------
// regions: hid 8388608, wq 8388608, wk 1048576, wv 1048576, wo 4194304
#define CV_S0 8388608u
#define CV_S1 16777216u
#define CV_S2 17825792u
#define CV_S3 18874368u
#define CV_S4 23068672u
__global__ __launch_bounds__(256)
void cvt_all_kernel(const float* __restrict__ hid, const float* __restrict__ wq,
                    const float* __restrict__ wk, const float* __restrict__ wv,
                    const float* __restrict__ wo,
                    __half* __restrict__ oh, __half* __restrict__ oq,
                    __half* __restrict__ ok, __half* __restrict__ ov,
                    __half* __restrict__ oo) {
    size_t i = ((size_t)blockIdx.x * 256 + threadIdx.x) * 4;
    const float* in; __half* out; size_t off;
    if (i < CV_S0)      { in = hid; out = oh; off = i; }
    else if (i < CV_S1) { in = wq;  out = oq; off = i - CV_S0; }
    else if (i < CV_S2) { in = wk;  out = ok; off = i - CV_S1; }
    else if (i < CV_S3) { in = wv;  out = ov; off = i - CV_S2; }
    else                { in = wo;  out = oo; off = i - CV_S3; }
    float4 v = *(const float4*)(in + off);
    *(uint32_t*)(out + off)     = f22h(v.x, v.y);
    *(uint32_t*)(out + off + 2) = f22h(v.z, v.w);
}

// ================= GEMM: C[M,N] = A @ B, single fp16, 1-term =================
// CTA 128x128, BK=64, 256 thr, 8 warps x (32x64), 3-stage cp.async,
// ONE barrier per chunk, 2 CTAs/SM (8 warps per SMSP total).
#define GA_ST 144
#define GB_ST 272
#define G_A  0
#define G_B  18432
#define G_STAGE 35840
#define G_SMEM 107520

__global__ __launch_bounds__(256, 2)
void gemm_h1_kernel(const __half* __restrict__ A,
                    const __half* __restrict__ B0, const __half* __restrict__ Bk,
                    const __half* __restrict__ Bv,
                    float* __restrict__ Cq, float* __restrict__ Ck,
                    __half* __restrict__ Vo,
                    int N0, int Kd, int qkv) {
    extern __shared__ char sg[];
    uint32_t smb = smem_u32(sg);
    const int tid = threadIdx.x, wid = tid >> 5, lane = tid & 31;
    const int m0 = blockIdx.y * 128;
    const int x = blockIdx.x;

    const __half* bp;
    float* c = nullptr;
    int bst, n0, isV = 0;
    if (!qkv) { bp = B0; bst = N0; n0 = x * 128; c = Cq; }
    else if (x < 32) { bp = B0; bst = 4096; n0 = x * 128; c = Cq; }
    else if (x < 36) { bp = Bk; bst = 512; n0 = (x - 32) * 128; c = Ck; }
    else            { bp = Bv; bst = 512; n0 = (x - 36) * 128; isV = 1; }

    // 8 warps: 4 m-slots x 2 n-slots. warp tile 32x64.
    const int wm = (wid & 3) * 32, wn = (wid >> 2) * 64;

    float acc[2][8][4];
    #pragma unroll
    for (int i = 0; i < 2; i++)
        #pragma unroll
        for (int j = 0; j < 8; j++)
            #pragma unroll
            for (int e = 0; e < 4; e++) acc[i][j][e] = 0.0f;

    const int NC = Kd >> 6;   // K/64

    #define G_ISSUE(ch) do { \
        int _sg_ = (ch) % 3; int _k0 = (ch) << 6; \
        uint32_t _st = smb + _sg_ * G_STAGE; \
        _Pragma("unroll") \
        for (int _j = 0; _j < 4; _j++) { \
            int _i = tid + 256 * _j; int _r = _i >> 3, _cc = _i & 7; \
            cpa16(_st + G_A + _r * GA_ST + _cc * 16, A + (size_t)(m0 + _r) * Kd + _k0 + _cc * 8); \
        } \
        _Pragma("unroll") \
        for (int _j = 0; _j < 4; _j++) { \
            int _i = tid + 256 * _j; int _r = _i >> 4, _cc = _i & 15; \
            cpa16(_st + G_B + _r * GB_ST + _cc * 16, bp + (size_t)(_k0 + _r) * bst + n0 + _cc * 8); \
        } \
        cpa_commit(); \
    } while (0)

    G_ISSUE(0);
    G_ISSUE(1);

    const int a_r = lane & 15;
    const int a_cb = (lane >> 4) * 16;
    const int b_k = (((lane >> 3) & 1) << 3) + (lane & 7);
    const int b_cb = ((lane >> 3) & 2) ? 16 : 0;

    for (int ch = 0; ch < NC; ch++) {
        // commits so far = 2 + ch; allow 1 pending -> chunk ch resident.
        cpa_wait<1>();
        __syncthreads();   // publishes stage ch + releases stage (ch+2)%3 for overwrite
        if (ch + 2 < NC) G_ISSUE(ch + 2); else cpa_commit();

        uint32_t st = smb + (ch % 3) * G_STAGE;
        uint32_t aB = st + G_A + (wm + a_r) * GA_ST + a_cb;
        uint32_t bB = st + G_B + b_k * GB_ST + wn * 2 + b_cb;

        #pragma unroll
        for (int kc = 0; kc < 4; kc++) {
            uint32_t ah[2][4];
            #pragma unroll
            for (int mi = 0; mi < 2; mi++)
                ldsm_x4(ah[mi], aB + mi * (16 * GA_ST) + kc * 32);
            #pragma unroll
            for (int bj = 0; bj < 4; bj++) {
                uint32_t bf[4];
                ldsm_x4_t(bf, bB + kc * (16 * GB_ST) + bj * 32);
                #pragma unroll
                for (int mi = 0; mi < 2; mi++) {
                    mma2(acc[mi][2*bj],   ah[mi], bf[0], bf[1]);
                    mma2(acc[mi][2*bj+1], ah[mi], bf[2], bf[3]);
                }
            }
        }
    }

    const int r0 = m0 + wm + (lane >> 2);
    const int c0 = n0 + wn + (lane & 3) * 2;
    if (!isV) {
        #pragma unroll
        for (int mi = 0; mi < 2; mi++) {
            #pragma unroll
            for (int nj = 0; nj < 8; nj++) {
                float2 lo2; lo2.x = acc[mi][nj][0]; lo2.y = acc[mi][nj][1];
                float2 hi2; hi2.x = acc[mi][nj][2]; hi2.y = acc[mi][nj][3];
                *(float2*)&c[(size_t)(r0 + mi * 16) * bst + c0 + nj * 8] = lo2;
                *(float2*)&c[(size_t)(r0 + mi * 16 + 8) * bst + c0 + nj * 8] = hi2;
            }
        }
    } else {
        #pragma unroll
        for (int mi = 0; mi < 2; mi++) {
            #pragma unroll
            for (int nj = 0; nj < 8; nj++) {
                int cg = c0 + nj * 8;
                int g = cg >> 7, d = cg & 127;
                #pragma unroll
                for (int half_ = 0; half_ < 2; half_++) {
                    int r = r0 + mi * 16 + half_ * 8;
                    int b = r >> 11, t = r & 2047;
                    uint32_t hv = f22h(acc[mi][nj][half_*2], acc[mi][nj][half_*2+1]);
                    size_t o = ((size_t)(b * G_ + g) * T_ + t) * KH + d;
                    *(uint32_t*)&Vo[o] = hv;
                }
            }
        }
    }
}

// -------- RMSNorm + RoPE, warp-per-row (shuffle-only, no smem) ---------------
template<int NH, int RST>
__global__ __launch_bounds__(256)
void rope_norm_w_kernel(const float* __restrict__ raw, const float* __restrict__ cosp,
                        const float* __restrict__ sinp, const float* __restrict__ w,
                        __half* __restrict__ outp) {
    const int idx = blockIdx.x * 8 + (threadIdx.x >> 5);
    const int lane = threadIdx.x & 31;
    const int bt = idx / NH, hh = idx % NH;
    const int b = bt >> 11, t = bt & 2047;
    const float* row = raw + (size_t)idx * RST;

    float4 a = *(const float4*)(row + lane * 4);
    float4 w4 = *(const float4*)(w + lane * 4);
    float ss = a.x*a.x + a.y*a.y + a.z*a.z + a.w*a.w;
    #pragma unroll
    for (int o = 16; o; o >>= 1) ss += __shfl_xor_sync(0xffffffffu, ss, o);
    float r = rsqrtf(ss * (1.0f / 128.0f) + EPS);
    float4 n;
    n.x = a.x * r * w4.x; n.y = a.y * r * w4.y;
    n.z = a.z * r * w4.z; n.w = a.w * r * w4.w;
    float4 p;
    p.x = __shfl_xor_sync(0xffffffffu, n.x, 16);
    p.y = __shfl_xor_sync(0xffffffffu, n.y, 16);
    p.z = __shfl_xor_sync(0xffffffffu, n.z, 16);
    p.w = __shfl_xor_sync(0xffffffffu, n.w, 16);
    float4 c4 = *(const float4*)(cosp + (size_t)bt * KH + lane * 4);
    float4 s4 = *(const float4*)(sinp + (size_t)bt * KH + lane * 4);
    float4 o4;
    if (lane < 16) {
        o4.x = n.x * c4.x - p.x * s4.x; o4.y = n.y * c4.y - p.y * s4.y;
        o4.z = n.z * c4.z - p.z * s4.z; o4.w = n.w * c4.w - p.w * s4.w;
    } else {
        o4.x = n.x * c4.x + p.x * s4.x; o4.y = n.y * c4.y + p.y * s4.y;
        o4.z = n.z * c4.z + p.z * s4.z; o4.w = n.w * c4.w + p.w * s4.w;
    }
    size_t o = ((size_t)(b * NH + hh) * T_ + t) * KH + lane * 4;
    uint2 hv;
    hv.x = f22h(o4.x, o4.y);
    hv.y = f22h(o4.z, o4.w);
    *(uint2*)&outp[o] = hv;
}

// ================= tensor-core flash attention (segment-skip) ================
#define AT_ST 272
#define AT_KV 17408
#define AT_KVSTG 17408
#define AT_SV  8704
#define AT_SEG 52224
#define AT_SMEM 52480

__global__ __launch_bounds__(128, 4)
void attn_tc_kernel(const __half* __restrict__ qv, const __half* __restrict__ kv,
                    const __half* __restrict__ vv,
                    const float* __restrict__ qraw, const int* __restrict__ seg,
                    __half* __restrict__ ao) {
    extern __shared__ char sa[];
    uint32_t smb = smem_u32(sa);
    const int tid = threadIdx.x, wid = tid >> 5, lane = tid & 31;
    const int qt = (int)(gridDim.x - 1 - blockIdx.x);
    const int q0 = qt * 64;
    const int bh_ = blockIdx.y;
    const int b = bh_ >> 4, h = bh_ & 15;
    const int g = h >> 2;
    const int wm = wid * 16;

    const __half* qb  = qv + ((size_t)(b * H_ + h) * T_ + q0) * KH;
    const __half* kb  = kv + (size_t)(b * G_ + g) * T_ * KH;
    const __half* vb  = vv + (size_t)(b * G_ + g) * T_ * KH;
    const int* segb = seg + (size_t)b * T_;

    const int sq_min = segb[q0];
    int lo = 0, hi = q0;
    while (lo < hi) { int mid = (lo + hi) >> 1; if (segb[mid] < sq_min) lo = mid + 1; else hi = mid; }
    const int t0 = lo >> 5;

    #pragma unroll
    for (int j = 0; j < 8; j++) {
        int i = tid + 128 * j; int r = i >> 4, cc = i & 15;
        cpa16(smb + r * AT_ST + cc * 16, qb + (size_t)r * KH + cc * 8);
    }

    const int nT = (q0 + 64) / 32;

    #define AT_ISSUE(t) do { \
        int _s = (t) & 1; int _s0 = (t) * 32; \
        uint32_t _bs = smb + AT_KV + _s * AT_KVSTG; \
        _Pragma("unroll") \
        for (int _j = 0; _j < 4; _j++) { \
            int _i = tid + 128 * _j; int _r = _i >> 4, _cc = _i & 15; \
            size_t _go = (size_t)(_s0 + _r) * KH + _cc * 8; \
            cpa16(_bs + _r * AT_ST + _cc * 16, kb + _go); \
            cpa16(_bs + AT_SV + _r * AT_ST + _cc * 16, vb + _go); \
        } \
        if (tid < 8) cpa16(smb + AT_SEG + _s * 128 + tid * 16, segb + _s0 + tid * 4); \
        cpa_commit(); \
    } while (0)

    AT_ISSUE(t0);

    const int qp0 = q0 + wm + (lane >> 2), qp1 = qp0 + 8;
    const int qs0 = segb[qp0];
    const int qs1 = segb[qp1];

    float rm0 = -1e30f, rm1 = -1e30f, rl0 = 0.0f, rl1 = 0.0f;
    float oacc[16][4];
    #pragma unroll
    for (int i = 0; i < 16; i++)
        #pragma unroll
        for (int e = 0; e < 4; e++) oacc[i][e] = 0.0f;

    const uint32_t aQ = smb + (wm + (lane & 15)) * AT_ST + (lane >> 4) * 16;
    const int vb_k = (((lane >> 3) & 1) << 3) + (lane & 7);
    const int vb_cb = ((lane >> 3) & 2) ? 16 : 0;
    const float SC = SCALE * 1.4426950408889634f;
    const float NEGINF = -__int_as_float(0x7f800000);

    for (int t = t0; t < nT; t++) {
        if (t + 1 < nT) { AT_ISSUE(t + 1); cpa_wait<1>(); }
        else cpa_wait<0>();
        __syncthreads();
        const int s0 = t * 32;
        uint32_t kst = smb + AT_KV + (t & 1) * AT_KVSTG;
        const int* kseg = (const int*)(sa + AT_SEG + (t & 1) * 128);

        float sacc[4][4];
        #pragma unroll
        for (int i = 0; i < 4; i++)
            #pragma unroll
            for (int e = 0; e < 4; e++) sacc[i][e] = 0.0f;

        #pragma unroll
        for (int kc = 0; kc < 8; kc++) {
            uint32_t aq[4];
            ldsm_x4(aq, aQ + kc * 32);
            #pragma unroll
            for (int ng = 0; ng < 2; ng++) {
                uint32_t kf[4];
                uint32_t ka = kst + (ng * 16 + (lane & 15)) * AT_ST + (lane >> 4) * 16 + kc * 32;
                ldsm_x4(kf, ka);
                mma2(sacc[2*ng],   aq, kf[0], kf[2]);
                mma2(sacc[2*ng+1], aq, kf[1], kf[3]);
            }
        }

        const int lc = (lane & 3) * 2;
        #pragma unroll
        for (int gi = 0; gi < 4; gi++) {
            int c0c = s0 + gi * 8 + lc, c1c = c0c + 1;
            int ks0 = kseg[gi * 8 + lc], ks1 = kseg[gi * 8 + lc + 1];
            float v;
            v = sacc[gi][0] * SC; sacc[gi][0] = (c0c <= qp0 && ks0 == qs0) ? v : NEGINF;
            v = sacc[gi][1] * SC; sacc[gi][1] = (c1c <= qp0 && ks1 == qs0) ? v : NEGINF;
            v = sacc[gi][2] * SC; sacc[gi][2] = (c0c <= qp1 && ks0 == qs1) ? v : NEGINF;
            v = sacc[gi][3] * SC; sacc[gi][3] = (c1c <= qp1 && ks1 == qs1) ? v : NEGINF;
        }

        float mx0 = NEGINF, mx1 = NEGINF;
        #pragma unroll
        for (int gi = 0; gi < 4; gi++) {
            mx0 = fmaxf(mx0, fmaxf(sacc[gi][0], sacc[gi][1]));
            mx1 = fmaxf(mx1, fmaxf(sacc[gi][2], sacc[gi][3]));
        }
        mx0 = fmaxf(mx0, __shfl_xor_sync(0xffffffffu, mx0, 1));
        mx0 = fmaxf(mx0, __shfl_xor_sync(0xffffffffu, mx0, 2));
        mx1 = fmaxf(mx1, __shfl_xor_sync(0xffffffffu, mx1, 1));
        mx1 = fmaxf(mx1, __shfl_xor_sync(0xffffffffu, mx1, 2));
        float nm0 = fmaxf(rm0, mx0), nm1 = fmaxf(rm1, mx1);
        float al0 = ex2f(rm0 - nm0), al1 = ex2f(rm1 - nm1);
        rm0 = nm0; rm1 = nm1;
        float sum0 = 0.0f, sum1 = 0.0f;
        #pragma unroll
        for (int gi = 0; gi < 4; gi++) {
            float p;
            p = ex2f(sacc[gi][0] - nm0); sum0 += p; sacc[gi][0] = p;
            p = ex2f(sacc[gi][1] - nm0); sum0 += p; sacc[gi][1] = p;
            p = ex2f(sacc[gi][2] - nm1); sum1 += p; sacc[gi][2] = p;
            p = ex2f(sacc[gi][3] - nm1); sum1 += p; sacc[gi][3] = p;
        }
        rl0 = rl0 * al0 + sum0;
        rl1 = rl1 * al1 + sum1;
        #pragma unroll
        for (int og = 0; og < 16; og++) {
            oacc[og][0] *= al0; oacc[og][1] *= al0;
            oacc[og][2] *= al1; oacc[og][3] *= al1;
        }

        #pragma unroll
        for (int kc2 = 0; kc2 < 2; kc2++) {
            uint32_t pa[4];
            pa[0] = f22h(sacc[2*kc2][0],   sacc[2*kc2][1]);
            pa[1] = f22h(sacc[2*kc2][2],   sacc[2*kc2][3]);
            pa[2] = f22h(sacc[2*kc2+1][0], sacc[2*kc2+1][1]);
            pa[3] = f22h(sacc[2*kc2+1][2], sacc[2*kc2+1][3]);
            uint32_t vbase = kst + AT_SV + (kc2 * 16 + vb_k) * AT_ST + vb_cb;
            #pragma unroll
            for (int nd = 0; nd < 8; nd++) {
                uint32_t vbf[4];
                ldsm_x4_t(vbf, vbase + nd * 32);
                mma2(oacc[2*nd],   pa, vbf[0], vbf[1]);
                mma2(oacc[2*nd+1], pa, vbf[2], vbf[3]);
            }
        }
        __syncthreads();
    }

    rl0 += __shfl_xor_sync(0xffffffffu, rl0, 1);
    rl0 += __shfl_xor_sync(0xffffffffu, rl0, 2);
    rl1 += __shfl_xor_sync(0xffffffffu, rl1, 1);
    rl1 += __shfl_xor_sync(0xffffffffu, rl1, 2);
    float inv0 = 1.0f / rl0, inv1 = 1.0f / rl1;
    const float L2E = 1.4426950408889634f;
    #pragma unroll
    for (int og = 0; og < 16; og++) {
        int d = og * 8 + (lane & 3) * 2;
        {
            float2 gt = *(const float2*)&qraw[((size_t)(b * T_ + qp0) * H_ + h) * 256 + 128 + d];
            float s0v = 1.0f / (1.0f + ex2f(-gt.x * L2E));
            float s1v = 1.0f / (1.0f + ex2f(-gt.y * L2E));
            uint32_t hv = f22h(oacc[og][0] * inv0 * s0v, oacc[og][1] * inv0 * s1v);
            size_t o = (size_t)(b * T_ + qp0) * (H_ * KH) + h * KH + d;
            *(uint32_t*)&ao[o] = hv;
        }
        {
            float2 gt = *(const float2*)&qraw[((size_t)(b * T_ + qp1) * H_ + h) * 256 + 128 + d];
            float s0v = 1.0f / (1.0f + ex2f(-gt.x * L2E));
            float s1v = 1.0f / (1.0f + ex2f(-gt.y * L2E));
            uint32_t hv = f22h(oacc[og][2] * inv1 * s0v, oacc[og][3] * inv1 * s1v);
            size_t o = (size_t)(b * T_ + qp1) * (H_ * KH) + h * KH + d;
            *(uint32_t*)&ao[o] = hv;
        }
    }
}

// ---------------- launch -----------------------------------------------------
extern "C" void kernel_launch(void* const* d_in, const int* in_sizes, int n_in,
                              void* d_out, int out_size) {
    const float* hidden = (const float*)d_in[0];
    const float* cosp   = (const float*)d_in[1];
    const float* sinp   = (const float*)d_in[2];
    const int*   seg    = (const int*)d_in[3];
    const float* Wq = (const float*)d_in[5];
    const float* Wk = (const float*)d_in[6];
    const float* Wv = (const float*)d_in[7];
    const float* Wo = (const float*)d_in[8];
    const float* qw = (const float*)d_in[9];
    const float* kw = (const float*)d_in[10];
    float* out = (float*)d_out;

    float *qraw, *kraw;
    __half *hid, *wq, *wk, *wv, *wo, *qb, *kb, *vb, *ao;
    cudaGetSymbolAddress((void**)&qraw, g_qraw);
    cudaGetSymbolAddress((void**)&kraw, g_kraw);
    cudaGetSymbolAddress((void**)&hid, g_hid);
    cudaGetSymbolAddress((void**)&wq, g_wq);
    cudaGetSymbolAddress((void**)&wk, g_wk);
    cudaGetSymbolAddress((void**)&wv, g_wv);
    cudaGetSymbolAddress((void**)&wo, g_wo);
    cudaGetSymbolAddress((void**)&qb, g_qb);
    cudaGetSymbolAddress((void**)&kb, g_kb);
    cudaGetSymbolAddress((void**)&vb, g_vb);
    cudaGetSymbolAddress((void**)&ao, g_ao);

    cudaFuncSetAttribute(gemm_h1_kernel, cudaFuncAttributeMaxDynamicSharedMemorySize, G_SMEM);
    cudaFuncSetAttribute(attn_tc_kernel, cudaFuncAttributeMaxDynamicSharedMemorySize, AT_SMEM);

    // 1. convert all operands to fp16 (single launch)
    cvt_all_kernel<<<CV_S4 / 1024, 256>>>(hidden, Wq, Wk, Wv, Wo,
                                          hid, wq, wk, wv, wo);

    // 2. merged Q/K/V projection (V written directly as fp16 [b,g,t,d])
    gemm_h1_kernel<<<dim3(40, 32), 256, G_SMEM>>>(hid, wq, wk, wv,
                                                  qraw, kraw, vb, 0, 2048, 1);

    // 3. rmsnorm + rope (warp-per-row)
    rope_norm_w_kernel<H_, 256><<<(B_*T_*H_) / 8, 256>>>(qraw, cosp, sinp, qw, qb);
    rope_norm_w_kernel<G_, 128><<<(B_*T_*G_) / 8, 256>>>(kraw, cosp, sinp, kw, kb);

    // 4. attention (gate fused, segment skip, 4 CTAs/SM)
    attn_tc_kernel<<<dim3(T_/64, B_*H_), 128, AT_SMEM>>>(qb, kb, vb, qraw, seg, ao);

    // 5. output projection
    gemm_h1_kernel<<<dim3(16, 32), 256, G_SMEM>>>(ao, wo, nullptr, nullptr,
                                                  out, nullptr, nullptr, 2048, 2048, 0);
}